// round 1
// baseline (speedup 1.0000x reference)
#include <cuda_runtime.h>
#include <cstdint>

#define DEVINL __device__ __forceinline__

constexpr int Bc = 4, Sc = 2048, Dc = 1024, Hc = 16, HDc = 64;
constexpr int Mc = Bc * Sc;           // 8192
constexpr int NQKV = 3 * Dc;          // 3072

// Scratch (allocation-free rule: __device__ globals)
__device__ float g_q[(size_t)Bc * Hc * Sc * HDc];    // (b*H+h, s, d)
__device__ float g_k[(size_t)Bc * Hc * Sc * HDc];
__device__ float g_v[(size_t)Bc * Hc * Sc * HDc];
__device__ float g_attn[(size_t)Mc * Dc];            // (b, s, h*64+d)

DEVINL uint32_t f2tf(float x) {
    uint32_t u; asm("cvt.rna.tf32.f32 %0, %1;" : "=r"(u) : "f"(x)); return u;
}
DEVINL void split_tf(float x, uint32_t& hi, uint32_t& lo) {
    asm("cvt.rna.tf32.f32 %0, %1;" : "=r"(hi) : "f"(x));
    float r = x - __uint_as_float(hi);
    asm("cvt.rna.tf32.f32 %0, %1;" : "=r"(lo) : "f"(r));
}
DEVINL void mma_tf32(float d[4], const uint32_t a[4], const uint32_t b[2], const float c[4]) {
    asm volatile(
        "mma.sync.aligned.m16n8k8.row.col.f32.tf32.tf32.f32 "
        "{%0,%1,%2,%3}, {%4,%5,%6,%7}, {%8,%9}, {%10,%11,%12,%13};\n"
        : "=f"(d[0]), "=f"(d[1]), "=f"(d[2]), "=f"(d[3])
        : "r"(a[0]), "r"(a[1]), "r"(a[2]), "r"(a[3]),
          "r"(b[0]), "r"(b[1]),
          "f"(c[0]), "f"(c[1]), "f"(c[2]), "f"(c[3]));
}
DEVINL void cp16(void* s, const void* g) {
    uint32_t sa = (uint32_t)__cvta_generic_to_shared(s);
    asm volatile("cp.async.cg.shared.global [%0], [%1], 16;\n" :: "r"(sa), "l"(g));
}
DEVINL void cp_commit() { asm volatile("cp.async.commit_group;\n"); }
template <int N> DEVINL void cp_wait() { asm volatile("cp.async.wait_group %0;\n" :: "n"(N)); }

// ---------------------------------------------------------------------------
// GEMM: C = A(Mx1024) * W(1024xN_) + bias, 3xTF32.
// EPI=0: scatter QKV into g_q/g_k/g_v (head-major). EPI=1: A := g_attn, write out.
// CTA tile 128x128, BK=32, 8 warps (4x2), warp tile 32x64.
// ---------------------------------------------------------------------------
constexpr int GEMM_LDA = 36;    // 32 + 4 pad (floats)
constexpr int GEMM_LDB = 132;   // 128 + 4 pad
constexpr int GEMM_SMEM = (2 * 128 * GEMM_LDA + 2 * 32 * GEMM_LDB) * 4;  // 70656 B

template <int N_, int EPI>
__global__ void __launch_bounds__(256, 1)
gemm_kernel(const float* __restrict__ Ain, const float* __restrict__ W,
            const float* __restrict__ bias, float* __restrict__ out)
{
    constexpr int K_ = 1024;
    constexpr int BK = 32;
    extern __shared__ float sm[];
    float* As = sm;
    float* Bs = sm + 2 * 128 * GEMM_LDA;

    const float* A = (EPI == 1) ? g_attn : Ain;

    const int tid = threadIdx.x;
    const int wid = tid >> 5, lid = tid & 31;
    const int wm = wid >> 1, wn = wid & 1;
    const int g = lid >> 2, tg = lid & 3;

    const int cm = blockIdx.y * 128;
    const int cn = blockIdx.x * 128;

    float acc[2][8][4];
#pragma unroll
    for (int i = 0; i < 2; i++)
#pragma unroll
        for (int j = 0; j < 8; j++)
#pragma unroll
            for (int e = 0; e < 4; e++) acc[i][j][e] = 0.f;

    auto load_tile = [&](int kt, int buf) {
#pragma unroll
        for (int it = 0; it < 4; it++) {
            int idx = tid + it * 256;             // A: 128x32 = 1024 float4
            int r = idx >> 3, c4 = idx & 7;
            cp16(As + buf * 128 * GEMM_LDA + r * GEMM_LDA + c4 * 4,
                 A + (size_t)(cm + r) * K_ + kt * BK + c4 * 4);
        }
#pragma unroll
        for (int it = 0; it < 4; it++) {
            int idx = tid + it * 256;             // B: 32x128 = 1024 float4
            int r = idx >> 5, c4 = idx & 31;
            cp16(Bs + buf * BK * GEMM_LDB + r * GEMM_LDB + c4 * 4,
                 W + (size_t)(kt * BK + r) * N_ + cn + c4 * 4);
        }
        cp_commit();
    };

    constexpr int NT = K_ / BK;
    load_tile(0, 0);
    for (int kt = 0; kt < NT; kt++) {
        if (kt + 1 < NT) { load_tile(kt + 1, (kt + 1) & 1); cp_wait<1>(); }
        else             { cp_wait<0>(); }
        __syncthreads();
        const float* Ab = As + (kt & 1) * 128 * GEMM_LDA;
        const float* Bb = Bs + (kt & 1) * BK * GEMM_LDB;
#pragma unroll
        for (int ks = 0; ks < 4; ks++) {
            uint32_t ah[2][4], al[2][4];
#pragma unroll
            for (int mi = 0; mi < 2; mi++) {
                int r = wm * 32 + mi * 16 + g;
                split_tf(Ab[r * GEMM_LDA + ks * 8 + tg],           ah[mi][0], al[mi][0]);
                split_tf(Ab[(r + 8) * GEMM_LDA + ks * 8 + tg],     ah[mi][1], al[mi][1]);
                split_tf(Ab[r * GEMM_LDA + ks * 8 + tg + 4],       ah[mi][2], al[mi][2]);
                split_tf(Ab[(r + 8) * GEMM_LDA + ks * 8 + tg + 4], ah[mi][3], al[mi][3]);
            }
            uint32_t bh[8][2], bl[8][2];
#pragma unroll
            for (int nj = 0; nj < 8; nj++) {
                int c = wn * 64 + nj * 8 + g;
                split_tf(Bb[(ks * 8 + tg) * GEMM_LDB + c],     bh[nj][0], bl[nj][0]);
                split_tf(Bb[(ks * 8 + tg + 4) * GEMM_LDB + c], bh[nj][1], bl[nj][1]);
            }
#pragma unroll
            for (int mi = 0; mi < 2; mi++)
#pragma unroll
                for (int nj = 0; nj < 8; nj++) {
                    mma_tf32(acc[mi][nj], al[mi], bh[nj], acc[mi][nj]);
                    mma_tf32(acc[mi][nj], ah[mi], bl[nj], acc[mi][nj]);
                    mma_tf32(acc[mi][nj], ah[mi], bh[nj], acc[mi][nj]);
                }
        }
        __syncthreads();
    }

    // Epilogue
#pragma unroll
    for (int mi = 0; mi < 2; mi++) {
#pragma unroll
        for (int nj = 0; nj < 8; nj++) {
            int col0 = cn + wn * 64 + nj * 8 + 2 * tg;     // even
            float2 v0 = make_float2(acc[mi][nj][0] + bias[col0],
                                    acc[mi][nj][1] + bias[col0 + 1]);
            float2 v1 = make_float2(acc[mi][nj][2] + bias[col0],
                                    acc[mi][nj][3] + bias[col0 + 1]);
            int row0 = cm + wm * 32 + mi * 16 + g;
            int row1 = row0 + 8;
            if (EPI == 1) {
                *(float2*)&out[(size_t)row0 * N_ + col0] = v0;
                *(float2*)&out[(size_t)row1 * N_ + col0] = v1;
            } else {
                int t = col0 >> 10;             // 0:q 1:k 2:v (uniform per nj)
                int r1 = col0 & 1023;
                int h = r1 >> 6, d = r1 & 63;   // d even
                float* dst = (t == 0) ? g_q : (t == 1) ? g_k : g_v;
                int b0 = row0 >> 11, s0 = row0 & 2047;
                int b1 = row1 >> 11, s1 = row1 & 2047;
                *(float2*)&dst[(((size_t)(b0 * Hc + h)) * Sc + s0) * HDc + d] = v0;
                *(float2*)&dst[(((size_t)(b1 * Hc + h)) * Sc + s1) * HDc + d] = v1;
            }
        }
    }
}

// ---------------------------------------------------------------------------
// Flash attention, causal, hd=64. One CTA per (head, 128-query block).
// 8 warps x 16 query rows. QK^T in 3xTF32, PV in 1xTF32. Online softmax.
// ---------------------------------------------------------------------------
constexpr int F_LDP = 132;  // P staging stride (floats)
constexpr int F_LDK = 68;   // K/V tile stride
constexpr int FLASH_SMEM = (128 * F_LDP + 2 * 128 * F_LDK) * 4;  // 137216 B

__global__ void __launch_bounds__(256, 1)
flash_kernel()
{
    extern __shared__ float sm[];
    float* Ps = sm;                      // 128 x 132 (also Q staging)
    float* Ks = Ps + 128 * F_LDP;        // 128 x 68
    float* Vs = Ks + 128 * F_LDK;        // 128 x 68

    const int tid = threadIdx.x, wid = tid >> 5, lid = tid & 31;
    const int g = lid >> 2, tg = lid & 3;
    const int qb = blockIdx.x;           // 0..15
    const int head = blockIdx.y;         // 0..63

    const float* Qg = g_q + (size_t)head * Sc * HDc + (size_t)qb * 128 * HDc;
    const float* Kg = g_k + (size_t)head * Sc * HDc;
    const float* Vg = g_v + (size_t)head * Sc * HDc;

    // Stage Q block into Ps, pull fragments into registers (hi/lo split)
#pragma unroll
    for (int it = 0; it < 8; it++) {
        int idx = tid + it * 256;        // 2048 float4
        int r = idx >> 4, c4 = idx & 15;
        cp16(Ps + r * F_LDK + c4 * 4, Qg + (size_t)r * HDc + c4 * 4);
    }
    cp_commit(); cp_wait<0>();
    __syncthreads();

    uint32_t qfh[8][4], qfl[8][4];
    {
        int r = wid * 16 + g;
#pragma unroll
        for (int ks = 0; ks < 8; ks++) {
            split_tf(Ps[r * F_LDK + ks * 8 + tg],           qfh[ks][0], qfl[ks][0]);
            split_tf(Ps[(r + 8) * F_LDK + ks * 8 + tg],     qfh[ks][1], qfl[ks][1]);
            split_tf(Ps[r * F_LDK + ks * 8 + tg + 4],       qfh[ks][2], qfl[ks][2]);
            split_tf(Ps[(r + 8) * F_LDK + ks * 8 + tg + 4], qfh[ks][3], qfl[ks][3]);
        }
    }
    __syncthreads();   // Ps now reusable as P

    float o[8][4];
#pragma unroll
    for (int j = 0; j < 8; j++)
#pragma unroll
        for (int e = 0; e < 4; e++) o[j][e] = 0.f;
    float m0 = -1e30f, m1 = -1e30f, l0 = 0.f, l1 = 0.f;

    const float scale = 0.125f;                     // 1/sqrt(64)
    const float LOG2E = 1.4426950408889634f;
    const int row0g = qb * 128 + wid * 16 + g;
    const int row1g = row0g + 8;

    for (int kb = 0; kb <= qb; kb++) {
        // Load K and V 128x64 tiles
#pragma unroll
        for (int it = 0; it < 8; it++) {
            int idx = tid + it * 256;
            int r = idx >> 4, c4 = idx & 15;
            cp16(Ks + r * F_LDK + c4 * 4, Kg + (size_t)(kb * 128 + r) * HDc + c4 * 4);
        }
#pragma unroll
        for (int it = 0; it < 8; it++) {
            int idx = tid + it * 256;
            int r = idx >> 4, c4 = idx & 15;
            cp16(Vs + r * F_LDK + c4 * 4, Vg + (size_t)(kb * 128 + r) * HDc + c4 * 4);
        }
        cp_commit(); cp_wait<0>();
        __syncthreads();

        // S = Q K^T (warp: 16 x 128), 3xTF32
        float sacc[16][4];
#pragma unroll
        for (int nj = 0; nj < 16; nj++)
#pragma unroll
            for (int e = 0; e < 4; e++) sacc[nj][e] = 0.f;
#pragma unroll
        for (int ks = 0; ks < 8; ks++) {
#pragma unroll
            for (int nj = 0; nj < 16; nj++) {
                uint32_t bh[2], bl[2];
                split_tf(Ks[(nj * 8 + g) * F_LDK + ks * 8 + tg],     bh[0], bl[0]);
                split_tf(Ks[(nj * 8 + g) * F_LDK + ks * 8 + tg + 4], bh[1], bl[1]);
                mma_tf32(sacc[nj], qfl[ks], bh, sacc[nj]);
                mma_tf32(sacc[nj], qfh[ks], bl, sacc[nj]);
                mma_tf32(sacc[nj], qfh[ks], bh, sacc[nj]);
            }
        }

        // scale + causal mask
#pragma unroll
        for (int nj = 0; nj < 16; nj++) {
#pragma unroll
            for (int e = 0; e < 4; e++) {
                int col = kb * 128 + nj * 8 + 2 * tg + (e & 1);
                int row = (e & 2) ? row1g : row0g;
                float v = sacc[nj][e] * scale;
                sacc[nj][e] = (col > row) ? -1e30f : v;
            }
        }

        // Row max
        float rmax0 = -1e30f, rmax1 = -1e30f;
#pragma unroll
        for (int nj = 0; nj < 16; nj++) {
            rmax0 = fmaxf(rmax0, fmaxf(sacc[nj][0], sacc[nj][1]));
            rmax1 = fmaxf(rmax1, fmaxf(sacc[nj][2], sacc[nj][3]));
        }
        rmax0 = fmaxf(rmax0, __shfl_xor_sync(0xffffffffu, rmax0, 1));
        rmax0 = fmaxf(rmax0, __shfl_xor_sync(0xffffffffu, rmax0, 2));
        rmax1 = fmaxf(rmax1, __shfl_xor_sync(0xffffffffu, rmax1, 1));
        rmax1 = fmaxf(rmax1, __shfl_xor_sync(0xffffffffu, rmax1, 2));

        float nm0 = fmaxf(m0, rmax0), nm1 = fmaxf(m1, rmax1);
        float alpha0 = exp2f((m0 - nm0) * LOG2E);
        float alpha1 = exp2f((m1 - nm1) * LOG2E);

        float rs0 = 0.f, rs1 = 0.f;
#pragma unroll
        for (int nj = 0; nj < 16; nj++) {
            float p0 = exp2f((sacc[nj][0] - nm0) * LOG2E);
            float p1 = exp2f((sacc[nj][1] - nm0) * LOG2E);
            float p2 = exp2f((sacc[nj][2] - nm1) * LOG2E);
            float p3 = exp2f((sacc[nj][3] - nm1) * LOG2E);
            sacc[nj][0] = p0; sacc[nj][1] = p1; sacc[nj][2] = p2; sacc[nj][3] = p3;
            rs0 += p0 + p1; rs1 += p2 + p3;
        }
        rs0 += __shfl_xor_sync(0xffffffffu, rs0, 1);
        rs0 += __shfl_xor_sync(0xffffffffu, rs0, 2);
        rs1 += __shfl_xor_sync(0xffffffffu, rs1, 1);
        rs1 += __shfl_xor_sync(0xffffffffu, rs1, 2);

        m0 = nm0; m1 = nm1;
        l0 = l0 * alpha0 + rs0;
        l1 = l1 * alpha1 + rs1;
#pragma unroll
        for (int j = 0; j < 8; j++) {
            o[j][0] *= alpha0; o[j][1] *= alpha0;
            o[j][2] *= alpha1; o[j][3] *= alpha1;
        }

        // Stage P (warp-private rows) to smem, C-layout -> A-layout via LDS
        {
            int pr = wid * 16 + g;
#pragma unroll
            for (int nj = 0; nj < 16; nj++) {
                Ps[pr * F_LDP + nj * 8 + 2 * tg]           = sacc[nj][0];
                Ps[pr * F_LDP + nj * 8 + 2 * tg + 1]       = sacc[nj][1];
                Ps[(pr + 8) * F_LDP + nj * 8 + 2 * tg]     = sacc[nj][2];
                Ps[(pr + 8) * F_LDP + nj * 8 + 2 * tg + 1] = sacc[nj][3];
            }
        }
        __syncwarp();

        // O += P V  (1xTF32)
#pragma unroll
        for (int ks = 0; ks < 16; ks++) {
            uint32_t af[4];
            int r = wid * 16 + g;
            af[0] = f2tf(Ps[r * F_LDP + ks * 8 + tg]);
            af[1] = f2tf(Ps[(r + 8) * F_LDP + ks * 8 + tg]);
            af[2] = f2tf(Ps[r * F_LDP + ks * 8 + tg + 4]);
            af[3] = f2tf(Ps[(r + 8) * F_LDP + ks * 8 + tg + 4]);
#pragma unroll
            for (int nj = 0; nj < 8; nj++) {
                uint32_t bf[2];
                bf[0] = f2tf(Vs[(ks * 8 + tg) * F_LDK + nj * 8 + g]);
                bf[1] = f2tf(Vs[(ks * 8 + tg + 4) * F_LDK + nj * 8 + g]);
                mma_tf32(o[nj], af, bf, o[nj]);
            }
        }
        __syncthreads();   // protect Ks/Vs for next k-block
    }

    // Write O / l  into g_attn[(b,s,h*64+d)]
    {
        int b = head >> 4, h = head & 15;
        int s0 = qb * 128 + wid * 16 + g;
        float inv0 = 1.f / l0, inv1 = 1.f / l1;
        size_t base0 = ((size_t)b * Sc + s0) * Dc + h * HDc;
        size_t base1 = ((size_t)b * Sc + s0 + 8) * Dc + h * HDc;
#pragma unroll
        for (int nj = 0; nj < 8; nj++) {
            int d0 = nj * 8 + 2 * tg;
            *(float2*)&g_attn[base0 + d0] = make_float2(o[nj][0] * inv0, o[nj][1] * inv0);
            *(float2*)&g_attn[base1 + d0] = make_float2(o[nj][2] * inv1, o[nj][3] * inv1);
        }
    }
}

// ---------------------------------------------------------------------------
extern "C" void kernel_launch(void* const* d_in, const int* in_sizes, int n_in,
                              void* d_out, int out_size)
{
    (void)in_sizes; (void)n_in; (void)out_size;
    const float* x      = (const float*)d_in[0];
    // d_in[1] is the causal mask; shape is known static (tril), not needed.
    const float* w_attn = (const float*)d_in[2];
    const float* b_attn = (const float*)d_in[3];
    const float* w_proj = (const float*)d_in[4];
    const float* b_proj = (const float*)d_in[5];
    float* out = (float*)d_out;

    cudaFuncSetAttribute(gemm_kernel<NQKV, 0>, cudaFuncAttributeMaxDynamicSharedMemorySize, GEMM_SMEM);
    cudaFuncSetAttribute(gemm_kernel<Dc, 1>,   cudaFuncAttributeMaxDynamicSharedMemorySize, GEMM_SMEM);
    cudaFuncSetAttribute(flash_kernel,         cudaFuncAttributeMaxDynamicSharedMemorySize, FLASH_SMEM);

    // 1) QKV = x @ w_attn + b_attn, scattered to head-major q/k/v
    gemm_kernel<NQKV, 0><<<dim3(NQKV / 128, Mc / 128), 256, GEMM_SMEM>>>(x, w_attn, b_attn, nullptr);
    // 2) causal flash attention per (head, q-block)
    flash_kernel<<<dim3(Sc / 128, Bc * Hc), 256, FLASH_SMEM>>>();
    // 3) out = attn @ w_proj + b_proj
    gemm_kernel<Dc, 1><<<dim3(Dc / 128, Mc / 128), 256, GEMM_SMEM>>>(nullptr, w_proj, b_proj, out);
}

// round 3
// speedup vs baseline: 1.4157x; 1.4157x over previous
#include <cuda_runtime.h>
#include <cstdint>

#define DEVINL __device__ __forceinline__

constexpr int Bc = 4, Sc = 2048, Dc = 1024, Hc = 16, HDc = 64;
constexpr int Mc = Bc * Sc;           // 8192
constexpr int NQKV = 3 * Dc;          // 3072

// Scratch (allocation-free rule: __device__ globals)
__device__ float g_q[(size_t)Bc * Hc * Sc * HDc];    // (b*H+h, s, d)
__device__ float g_k[(size_t)Bc * Hc * Sc * HDc];
__device__ float g_v[(size_t)Bc * Hc * Sc * HDc];
__device__ float g_attn[(size_t)Mc * Dc];            // (b, s, h*64+d)

// ---------------------------------------------------------------------------
// Helpers
// ---------------------------------------------------------------------------
DEVINL uint32_t f2tf(float x) {
    uint32_t u; asm("cvt.rna.tf32.f32 %0, %1;" : "=r"(u) : "f"(x)); return u;
}
// Pack (x0,x1) -> bf16x2 hi word + residual lo word. lower 16 bits = x0.
DEVINL void cvt_split2(float x0, float x1, uint32_t& h, uint32_t& l) {
    asm("cvt.rn.bf16x2.f32 %0, %1, %2;" : "=r"(h) : "f"(x1), "f"(x0));
    float r0 = x0 - __uint_as_float(h << 16);
    float r1 = x1 - __uint_as_float(h & 0xffff0000u);
    asm("cvt.rn.bf16x2.f32 %0, %1, %2;" : "=r"(l) : "f"(r1), "f"(r0));
}
DEVINL void mma_bf16(float d[4], const uint32_t a[4], const uint32_t b[2], const float c[4]) {
    asm volatile(
        "mma.sync.aligned.m16n8k16.row.col.f32.bf16.bf16.f32 "
        "{%0,%1,%2,%3}, {%4,%5,%6,%7}, {%8,%9}, {%10,%11,%12,%13};\n"
        : "=f"(d[0]), "=f"(d[1]), "=f"(d[2]), "=f"(d[3])
        : "r"(a[0]), "r"(a[1]), "r"(a[2]), "r"(a[3]),
          "r"(b[0]), "r"(b[1]),
          "f"(c[0]), "f"(c[1]), "f"(c[2]), "f"(c[3]));
}
DEVINL void mma_tf32(float d[4], const uint32_t a[4], const uint32_t b[2], const float c[4]) {
    asm volatile(
        "mma.sync.aligned.m16n8k8.row.col.f32.tf32.tf32.f32 "
        "{%0,%1,%2,%3}, {%4,%5,%6,%7}, {%8,%9}, {%10,%11,%12,%13};\n"
        : "=f"(d[0]), "=f"(d[1]), "=f"(d[2]), "=f"(d[3])
        : "r"(a[0]), "r"(a[1]), "r"(a[2]), "r"(a[3]),
          "r"(b[0]), "r"(b[1]),
          "f"(c[0]), "f"(c[1]), "f"(c[2]), "f"(c[3]));
}
DEVINL void cp16(void* s, const void* g) {
    uint32_t sa = (uint32_t)__cvta_generic_to_shared(s);
    asm volatile("cp.async.cg.shared.global [%0], [%1], 16;\n" :: "r"(sa), "l"(g));
}
DEVINL void cp_commit() { asm volatile("cp.async.commit_group;\n"); }
template <int N> DEVINL void cp_wait() { asm volatile("cp.async.wait_group %0;\n" :: "n"(N)); }

// ---------------------------------------------------------------------------
// bf16 3x-split GEMM (mma.sync m16n8k16): C = A(Mx1024) W(1024xN_) + bias.
// CTA 128x128, BK=64. 8 warps: wm=wid>>1 (m 32), wn=wid&1 (n 64).
// SMEM: A/B stored as bf16-pair words, stride 36 words (conflict-free frags).
// Register-pipelined single stage: LDG(kt+1) issued before mma(kt).
// EPI=0: scatter to g_q/g_k/g_v. EPI=1: A := g_attn, write out.
// ---------------------------------------------------------------------------
constexpr int G_LD = 36;                           // words per row
constexpr int G_ARR = 128 * G_LD;                  // words per array
constexpr int G_SMEM = 4 * G_ARR * 4;              // 73728 B

template <int N_, int EPI>
__global__ void __launch_bounds__(256, 1)
bf_gemm(const float* __restrict__ Ain, const float* __restrict__ W,
        const float* __restrict__ bias, float* __restrict__ out)
{
    extern __shared__ uint32_t sw[];
    uint32_t* Ah = sw;
    uint32_t* Al = Ah + G_ARR;
    uint32_t* Bh = Al + G_ARR;
    uint32_t* Bl = Bh + G_ARR;

    const float* A = (EPI == 1) ? g_attn : Ain;
    const int tid = threadIdx.x, wid = tid >> 5, lid = tid & 31;
    const int wm = wid >> 1, wn = wid & 1;
    const int g = lid >> 2, tg = lid & 3;
    const int cm = blockIdx.y * 128, cn = blockIdx.x * 128;

    // load coords
    const int am = tid >> 4, ak4 = tid & 15;       // A: rows am+16it, k4
    const int bkp = tid & 7, bn4 = tid >> 3;       // B: kpair bkp+8it, n4

    float acc[2][8][4];
#pragma unroll
    for (int i = 0; i < 2; i++)
#pragma unroll
        for (int j = 0; j < 8; j++)
#pragma unroll
            for (int e = 0; e < 4; e++) acc[i][j][e] = 0.f;

    float4 areg[8], breg[4][2];
    auto ldg_tile = [&](int kt) {
#pragma unroll
        for (int it = 0; it < 8; it++)
            areg[it] = *(const float4*)&A[(size_t)(cm + am + it * 16) * 1024 + kt * 64 + ak4 * 4];
#pragma unroll
        for (int it = 0; it < 4; it++)
#pragma unroll
            for (int j = 0; j < 2; j++)
                breg[it][j] = *(const float4*)&W[(size_t)(kt * 64 + 2 * (bkp + it * 8) + j) * N_ + cn + bn4 * 4];
    };
    auto sts_tile = [&]() {
#pragma unroll
        for (int it = 0; it < 8; it++) {
            uint32_t h0, h1, l0, l1;
            cvt_split2(areg[it].x, areg[it].y, h0, l0);
            cvt_split2(areg[it].z, areg[it].w, h1, l1);
            int w = (am + it * 16) * G_LD + ak4 * 2;
            *(uint2*)(Ah + w) = make_uint2(h0, h1);
            *(uint2*)(Al + w) = make_uint2(l0, l1);
        }
#pragma unroll
        for (int it = 0; it < 4; it++) {
            int kp = bkp + it * 8;
            const float* v0 = &breg[it][0].x;
            const float* v1 = &breg[it][1].x;
#pragma unroll
            for (int c = 0; c < 4; c++) {
                uint32_t h, l;
                cvt_split2(v0[c], v1[c], h, l);
                int w = (bn4 * 4 + c) * G_LD + kp;
                Bh[w] = h; Bl[w] = l;
            }
        }
    };

    ldg_tile(0);
    constexpr int NT = 16;
    for (int kt = 0; kt < NT; kt++) {
        __syncthreads();
        sts_tile();
        __syncthreads();
        if (kt + 1 < NT) ldg_tile(kt + 1);

#pragma unroll
        for (int ks = 0; ks < 4; ks++) {
            uint32_t ah[2][4], al[2][4];
#pragma unroll
            for (int mi = 0; mi < 2; mi++) {
                int r0 = (wm * 32 + mi * 16 + g) * G_LD + ks * 8;
                int r1 = r0 + 8 * G_LD;
                ah[mi][0] = Ah[r0 + tg];     ah[mi][1] = Ah[r1 + tg];
                ah[mi][2] = Ah[r0 + tg + 4]; ah[mi][3] = Ah[r1 + tg + 4];
                al[mi][0] = Al[r0 + tg];     al[mi][1] = Al[r1 + tg];
                al[mi][2] = Al[r0 + tg + 4]; al[mi][3] = Al[r1 + tg + 4];
            }
#pragma unroll
            for (int nj = 0; nj < 8; nj++) {
                int nb = (wn * 64 + nj * 8 + g) * G_LD + ks * 8;
                uint32_t bh[2] = {Bh[nb + tg], Bh[nb + tg + 4]};
                uint32_t bl[2] = {Bl[nb + tg], Bl[nb + tg + 4]};
#pragma unroll
                for (int mi = 0; mi < 2; mi++) {
                    mma_bf16(acc[mi][nj], al[mi], bh, acc[mi][nj]);
                    mma_bf16(acc[mi][nj], ah[mi], bl, acc[mi][nj]);
                    mma_bf16(acc[mi][nj], ah[mi], bh, acc[mi][nj]);
                }
            }
        }
    }

    // Epilogue
#pragma unroll
    for (int mi = 0; mi < 2; mi++) {
#pragma unroll
        for (int nj = 0; nj < 8; nj++) {
            int col0 = cn + wn * 64 + nj * 8 + 2 * tg;
            float2 v0 = make_float2(acc[mi][nj][0] + bias[col0],
                                    acc[mi][nj][1] + bias[col0 + 1]);
            float2 v1 = make_float2(acc[mi][nj][2] + bias[col0],
                                    acc[mi][nj][3] + bias[col0 + 1]);
            int row0 = cm + wm * 32 + mi * 16 + g;
            int row1 = row0 + 8;
            if (EPI == 1) {
                *(float2*)&out[(size_t)row0 * N_ + col0] = v0;
                *(float2*)&out[(size_t)row1 * N_ + col0] = v1;
            } else {
                int t = col0 >> 10;
                int r1 = col0 & 1023;
                int h = r1 >> 6, d = r1 & 63;
                float* dst = (t == 0) ? g_q : (t == 1) ? g_k : g_v;
                int b0 = row0 >> 11, s0 = row0 & 2047;
                int b1 = row1 >> 11, s1 = row1 & 2047;
                *(float2*)&dst[(((size_t)(b0 * Hc + h)) * Sc + s0) * HDc + d] = v0;
                *(float2*)&dst[(((size_t)(b1 * Hc + h)) * Sc + s1) * HDc + d] = v1;
            }
        }
    }
}

// ---------------------------------------------------------------------------
// Flash attention: causal, hd=64. QK^T in 3x-split bf16 (hoisted splits),
// PV in 1xTF32. 8 warps x 16 query rows, 128x128 tiles.
// SMEM: Ps fp32 128x132 | Ksh/Ksl bf16-words 128x36 | Vs fp32 128x68
// ---------------------------------------------------------------------------
constexpr int F_LDP = 132;
constexpr int F_LDQ = 68;     // Q staging stride (fp32, within Ps area)
constexpr int F_LDV = 68;
constexpr int F_PS_B  = 0;
constexpr int F_KSH_B = 128 * F_LDP * 4;                 // 67584
constexpr int F_KSL_B = F_KSH_B + 128 * G_LD * 4;        // +18432
constexpr int F_VS_B  = F_KSL_B + 128 * G_LD * 4;        // +18432
constexpr int FLASH_SMEM = F_VS_B + 128 * F_LDV * 4;     // 139264

__global__ void __launch_bounds__(256, 1)
flash_kernel()
{
    extern __shared__ char smc[];
    float*    Ps  = (float*)(smc + F_PS_B);
    uint32_t* Ksh = (uint32_t*)(smc + F_KSH_B);
    uint32_t* Ksl = (uint32_t*)(smc + F_KSL_B);
    float*    Vs  = (float*)(smc + F_VS_B);

    const int tid = threadIdx.x, wid = tid >> 5, lid = tid & 31;
    const int g = lid >> 2, tg = lid & 3;
    const int qb = blockIdx.x;
    const int head = blockIdx.y;

    const float* Qg = g_q + (size_t)head * Sc * HDc + (size_t)qb * 128 * HDc;
    const float* Kg = g_k + (size_t)head * Sc * HDc;
    const float* Vg = g_v + (size_t)head * Sc * HDc;

    // Stage Q (fp32) into Ps area, split to bf16 fragments once.
#pragma unroll
    for (int it = 0; it < 8; it++) {
        int idx = tid + it * 256;
        int r = idx >> 4, c4 = idx & 15;
        cp16(Ps + r * F_LDQ + c4 * 4, Qg + (size_t)r * HDc + c4 * 4);
    }
    cp_commit(); cp_wait<0>();
    __syncthreads();

    uint32_t qh[4][4], ql[4][4];
    {
        int r = wid * 16 + g;
#pragma unroll
        for (int ks = 0; ks < 4; ks++) {
            int k0 = ks * 16 + 2 * tg;
            cvt_split2(Ps[r * F_LDQ + k0],           Ps[r * F_LDQ + k0 + 1],           qh[ks][0], ql[ks][0]);
            cvt_split2(Ps[(r + 8) * F_LDQ + k0],     Ps[(r + 8) * F_LDQ + k0 + 1],     qh[ks][1], ql[ks][1]);
            cvt_split2(Ps[r * F_LDQ + k0 + 8],       Ps[r * F_LDQ + k0 + 9],           qh[ks][2], ql[ks][2]);
            cvt_split2(Ps[(r + 8) * F_LDQ + k0 + 8], Ps[(r + 8) * F_LDQ + k0 + 9],     qh[ks][3], ql[ks][3]);
        }
    }
    __syncthreads();   // Ps now reusable as P

    float o[8][4];
#pragma unroll
    for (int j = 0; j < 8; j++)
#pragma unroll
        for (int e = 0; e < 4; e++) o[j][e] = 0.f;
    float m0 = -1e30f, m1 = -1e30f, l0 = 0.f, l1 = 0.f;

    const float scale = 0.125f;
    const float LOG2E = 1.4426950408889634f;
    const int row0g = qb * 128 + wid * 16 + g;
    const int row1g = row0g + 8;

    const int kr = tid >> 4, kd4 = tid & 15;   // K load coords

    for (int kb = 0; kb <= qb; kb++) {
        // V via cp.async (fp32), K via LDG + split + STS (bf16 hi/lo)
#pragma unroll
        for (int it = 0; it < 8; it++) {
            int idx = tid + it * 256;
            int r = idx >> 4, c4 = idx & 15;
            cp16(Vs + r * F_LDV + c4 * 4, Vg + (size_t)(kb * 128 + r) * HDc + c4 * 4);
        }
        cp_commit();
#pragma unroll
        for (int it = 0; it < 8; it++) {
            float4 kv = *(const float4*)&Kg[(size_t)(kb * 128 + kr + it * 16) * HDc + kd4 * 4];
            uint32_t h0, h1, l0w, l1w;
            cvt_split2(kv.x, kv.y, h0, l0w);
            cvt_split2(kv.z, kv.w, h1, l1w);
            int w = (kr + it * 16) * G_LD + kd4 * 2;
            *(uint2*)(Ksh + w) = make_uint2(h0, h1);
            *(uint2*)(Ksl + w) = make_uint2(l0w, l1w);
        }
        cp_wait<0>();
        __syncthreads();

        // S = Q K^T : bf16 3x, k16 steps
        float sacc[16][4];
#pragma unroll
        for (int nj = 0; nj < 16; nj++)
#pragma unroll
            for (int e = 0; e < 4; e++) sacc[nj][e] = 0.f;
#pragma unroll
        for (int ks = 0; ks < 4; ks++) {
#pragma unroll
            for (int nj = 0; nj < 16; nj++) {
                int nb = (nj * 8 + g) * G_LD + ks * 8;
                uint32_t bh[2] = {Ksh[nb + tg], Ksh[nb + tg + 4]};
                uint32_t bl[2] = {Ksl[nb + tg], Ksl[nb + tg + 4]};
                mma_bf16(sacc[nj], ql[ks], bh, sacc[nj]);
                mma_bf16(sacc[nj], qh[ks], bl, sacc[nj]);
                mma_bf16(sacc[nj], qh[ks], bh, sacc[nj]);
            }
        }

        // scale + causal mask
#pragma unroll
        for (int nj = 0; nj < 16; nj++) {
#pragma unroll
            for (int e = 0; e < 4; e++) {
                int col = kb * 128 + nj * 8 + 2 * tg + (e & 1);
                int row = (e & 2) ? row1g : row0g;
                float v = sacc[nj][e] * scale;
                sacc[nj][e] = (col > row) ? -1e30f : v;
            }
        }

        float rmax0 = -1e30f, rmax1 = -1e30f;
#pragma unroll
        for (int nj = 0; nj < 16; nj++) {
            rmax0 = fmaxf(rmax0, fmaxf(sacc[nj][0], sacc[nj][1]));
            rmax1 = fmaxf(rmax1, fmaxf(sacc[nj][2], sacc[nj][3]));
        }
        rmax0 = fmaxf(rmax0, __shfl_xor_sync(0xffffffffu, rmax0, 1));
        rmax0 = fmaxf(rmax0, __shfl_xor_sync(0xffffffffu, rmax0, 2));
        rmax1 = fmaxf(rmax1, __shfl_xor_sync(0xffffffffu, rmax1, 1));
        rmax1 = fmaxf(rmax1, __shfl_xor_sync(0xffffffffu, rmax1, 2));

        float nm0 = fmaxf(m0, rmax0), nm1 = fmaxf(m1, rmax1);
        float alpha0 = exp2f((m0 - nm0) * LOG2E);
        float alpha1 = exp2f((m1 - nm1) * LOG2E);

        float rs0 = 0.f, rs1 = 0.f;
#pragma unroll
        for (int nj = 0; nj < 16; nj++) {
            float p0 = exp2f((sacc[nj][0] - nm0) * LOG2E);
            float p1 = exp2f((sacc[nj][1] - nm0) * LOG2E);
            float p2 = exp2f((sacc[nj][2] - nm1) * LOG2E);
            float p3 = exp2f((sacc[nj][3] - nm1) * LOG2E);
            sacc[nj][0] = p0; sacc[nj][1] = p1; sacc[nj][2] = p2; sacc[nj][3] = p3;
            rs0 += p0 + p1; rs1 += p2 + p3;
        }
        rs0 += __shfl_xor_sync(0xffffffffu, rs0, 1);
        rs0 += __shfl_xor_sync(0xffffffffu, rs0, 2);
        rs1 += __shfl_xor_sync(0xffffffffu, rs1, 1);
        rs1 += __shfl_xor_sync(0xffffffffu, rs1, 2);

        m0 = nm0; m1 = nm1;
        l0 = l0 * alpha0 + rs0;
        l1 = l1 * alpha1 + rs1;
#pragma unroll
        for (int j = 0; j < 8; j++) {
            o[j][0] *= alpha0; o[j][1] *= alpha0;
            o[j][2] *= alpha1; o[j][3] *= alpha1;
        }

        // Stage P to smem (C-layout -> A-layout)
        {
            int pr = wid * 16 + g;
#pragma unroll
            for (int nj = 0; nj < 16; nj++) {
                Ps[pr * F_LDP + nj * 8 + 2 * tg]           = sacc[nj][0];
                Ps[pr * F_LDP + nj * 8 + 2 * tg + 1]       = sacc[nj][1];
                Ps[(pr + 8) * F_LDP + nj * 8 + 2 * tg]     = sacc[nj][2];
                Ps[(pr + 8) * F_LDP + nj * 8 + 2 * tg + 1] = sacc[nj][3];
            }
        }
        __syncwarp();

        // O += P V  (1xTF32)
#pragma unroll
        for (int ks = 0; ks < 16; ks++) {
            uint32_t af[4];
            int r = wid * 16 + g;
            af[0] = f2tf(Ps[r * F_LDP + ks * 8 + tg]);
            af[1] = f2tf(Ps[(r + 8) * F_LDP + ks * 8 + tg]);
            af[2] = f2tf(Ps[r * F_LDP + ks * 8 + tg + 4]);
            af[3] = f2tf(Ps[(r + 8) * F_LDP + ks * 8 + tg + 4]);
#pragma unroll
            for (int nj = 0; nj < 8; nj++) {
                uint32_t bf[2];
                bf[0] = f2tf(Vs[(ks * 8 + tg) * F_LDV + nj * 8 + g]);
                bf[1] = f2tf(Vs[(ks * 8 + tg + 4) * F_LDV + nj * 8 + g]);
                mma_tf32(o[nj], af, bf, o[nj]);
            }
        }
        __syncthreads();
    }

    // Write O / l into g_attn[(b,s,h*64+d)]
    {
        int b = head >> 4, h = head & 15;
        int s0 = qb * 128 + wid * 16 + g;
        float inv0 = 1.f / l0, inv1 = 1.f / l1;
        size_t base0 = ((size_t)b * Sc + s0) * Dc + h * HDc;
        size_t base1 = ((size_t)b * Sc + s0 + 8) * Dc + h * HDc;
#pragma unroll
        for (int nj = 0; nj < 8; nj++) {
            int d0 = nj * 8 + 2 * tg;
            *(float2*)&g_attn[base0 + d0] = make_float2(o[nj][0] * inv0, o[nj][1] * inv0);
            *(float2*)&g_attn[base1 + d0] = make_float2(o[nj][2] * inv1, o[nj][3] * inv1);
        }
    }
}

// ---------------------------------------------------------------------------
extern "C" void kernel_launch(void* const* d_in, const int* in_sizes, int n_in,
                              void* d_out, int out_size)
{
    (void)in_sizes; (void)n_in; (void)out_size;
    const float* x      = (const float*)d_in[0];
    const float* w_attn = (const float*)d_in[2];
    const float* b_attn = (const float*)d_in[3];
    const float* w_proj = (const float*)d_in[4];
    const float* b_proj = (const float*)d_in[5];
    float* out = (float*)d_out;

    cudaFuncSetAttribute(bf_gemm<NQKV, 0>, cudaFuncAttributeMaxDynamicSharedMemorySize, G_SMEM);
    cudaFuncSetAttribute(bf_gemm<Dc, 1>,   cudaFuncAttributeMaxDynamicSharedMemorySize, G_SMEM);
    cudaFuncSetAttribute(flash_kernel,     cudaFuncAttributeMaxDynamicSharedMemorySize, FLASH_SMEM);

    // 1) QKV = x @ w_attn + b_attn (bf16 3x-split mma.sync), scatter head-major
    bf_gemm<NQKV, 0><<<dim3(NQKV / 128, Mc / 128), 256, G_SMEM>>>(x, w_attn, b_attn, nullptr);
    // 2) causal flash attention
    flash_kernel<<<dim3(Sc / 128, Bc * Hc), 256, FLASH_SMEM>>>();
    // 3) out = attn @ w_proj + b_proj
    bf_gemm<Dc, 1><<<dim3(Dc / 128, Mc / 128), 256, G_SMEM>>>(nullptr, w_proj, b_proj, out);
}

// round 4
// speedup vs baseline: 1.5924x; 1.1248x over previous
#include <cuda_runtime.h>
#include <cstdint>

#define DEVINL __device__ __forceinline__

constexpr int Bc = 4, Sc = 2048, Dc = 1024, Hc = 16, HDc = 64;
constexpr int Mc = Bc * Sc;           // 8192
constexpr int NQKV = 3 * Dc;          // 3072

// Scratch (allocation-free rule: __device__ globals)
__device__ float g_q[(size_t)Bc * Hc * Sc * HDc];    // (b*H+h, s, d)
__device__ float g_k[(size_t)Bc * Hc * Sc * HDc];
__device__ float g_v[(size_t)Bc * Hc * Sc * HDc];
__device__ float g_attn[(size_t)Mc * Dc];            // (b, s, h*64+d)

// ---------------------------------------------------------------------------
// Helpers
// ---------------------------------------------------------------------------
DEVINL uint32_t f2tf(float x) {
    uint32_t u; asm("cvt.rna.tf32.f32 %0, %1;" : "=r"(u) : "f"(x)); return u;
}
// Pack (x0,x1) -> bf16x2 hi word + residual lo word. lower 16 bits = x0.
DEVINL void cvt_split2(float x0, float x1, uint32_t& h, uint32_t& l) {
    asm("cvt.rn.bf16x2.f32 %0, %1, %2;" : "=r"(h) : "f"(x1), "f"(x0));
    float r0 = x0 - __uint_as_float(h << 16);
    float r1 = x1 - __uint_as_float(h & 0xffff0000u);
    asm("cvt.rn.bf16x2.f32 %0, %1, %2;" : "=r"(l) : "f"(r1), "f"(r0));
}
DEVINL void mma_bf16(float d[4], const uint32_t a[4], const uint32_t b[2], const float c[4]) {
    asm volatile(
        "mma.sync.aligned.m16n8k16.row.col.f32.bf16.bf16.f32 "
        "{%0,%1,%2,%3}, {%4,%5,%6,%7}, {%8,%9}, {%10,%11,%12,%13};\n"
        : "=f"(d[0]), "=f"(d[1]), "=f"(d[2]), "=f"(d[3])
        : "r"(a[0]), "r"(a[1]), "r"(a[2]), "r"(a[3]),
          "r"(b[0]), "r"(b[1]),
          "f"(c[0]), "f"(c[1]), "f"(c[2]), "f"(c[3]));
}
DEVINL void mma_tf32(float d[4], const uint32_t a[4], const uint32_t b[2], const float c[4]) {
    asm volatile(
        "mma.sync.aligned.m16n8k8.row.col.f32.tf32.tf32.f32 "
        "{%0,%1,%2,%3}, {%4,%5,%6,%7}, {%8,%9}, {%10,%11,%12,%13};\n"
        : "=f"(d[0]), "=f"(d[1]), "=f"(d[2]), "=f"(d[3])
        : "r"(a[0]), "r"(a[1]), "r"(a[2]), "r"(a[3]),
          "r"(b[0]), "r"(b[1]),
          "f"(c[0]), "f"(c[1]), "f"(c[2]), "f"(c[3]));
}
DEVINL void ldsm_x4(uint32_t addr, uint32_t& r0, uint32_t& r1, uint32_t& r2, uint32_t& r3) {
    asm volatile("ldmatrix.sync.aligned.m8n8.x4.shared.b16 {%0,%1,%2,%3}, [%4];"
                 : "=r"(r0), "=r"(r1), "=r"(r2), "=r"(r3) : "r"(addr));
}
DEVINL void cp16(void* s, const void* g) {
    uint32_t sa = (uint32_t)__cvta_generic_to_shared(s);
    asm volatile("cp.async.cg.shared.global [%0], [%1], 16;\n" :: "r"(sa), "l"(g));
}
DEVINL void cp_commit() { asm volatile("cp.async.commit_group;\n"); }
template <int N> DEVINL void cp_wait() { asm volatile("cp.async.wait_group %0;\n" :: "n"(N)); }

// ---------------------------------------------------------------------------
// bf16 3x-split GEMM (m16n8k16 + ldmatrix): C = A(Mx1024) W(1024xN_) + bias.
// CTA 128x128, BK=64, double-buffered SMEM (1 sync/tile).
// 8 warps as 2(m)x4(n): warp tile 64x32 -> mi 0..3, nj 0..3.
// SMEM arrays (bf16-pair words, stride 36): Ah | Al | Bh | Bl  x2 stages.
// EPI=0: scatter to g_q/g_k/g_v. EPI=1: A := g_attn, write out.
// ---------------------------------------------------------------------------
constexpr int G_LD = 36;                     // words per row (32 + 4 pad)
constexpr int G_ARR = 128 * G_LD;            // 4608 words per array
constexpr int G_STG_W = 4 * G_ARR;           // words per stage
constexpr int G_STG_B = G_STG_W * 4;         // 73728 B
constexpr int G_SMEM = 2 * G_STG_B;          // 147456 B

template <int N_, int EPI>
__global__ void __launch_bounds__(256, 1)
bf_gemm(const float* __restrict__ Ain, const float* __restrict__ W,
        const float* __restrict__ bias, float* __restrict__ out)
{
    extern __shared__ uint32_t sw[];
    const float* A = (EPI == 1) ? g_attn : Ain;
    const int tid = threadIdx.x, wid = tid >> 5, lid = tid & 31;
    const int wm = wid >> 2, wn = wid & 3;
    const int g = lid >> 2, tg = lid & 3;
    const int cm = blockIdx.y * 128, cn = blockIdx.x * 128;
    const uint32_t smb = (uint32_t)__cvta_generic_to_shared(sw);

    // global load coords
    const int am = tid >> 4, ak4 = tid & 15;       // A: rows am+16it, k4
    const int bkp = tid & 7, bn4 = tid >> 3;       // B: kpair bkp+8it, n4

    // ldmatrix fragment base addresses (bytes)
    const uint32_t a_fb = smb + 4u * ((wm * 64 + (lid & 15)) * G_LD + (lid >> 4) * 4);
    const uint32_t b_fb = smb + 4u * ((wn * 32 + ((lid >> 4) & 1) * 8 + (lid & 7)) * G_LD
                                      + ((lid >> 3) & 1) * 4) + 2u * G_ARR * 4;

    float acc[4][4][4];
#pragma unroll
    for (int i = 0; i < 4; i++)
#pragma unroll
        for (int j = 0; j < 4; j++)
#pragma unroll
            for (int e = 0; e < 4; e++) acc[i][j][e] = 0.f;

    float4 areg[8], breg[4][2];
    auto ldg_tile = [&](int kt) {
#pragma unroll
        for (int it = 0; it < 8; it++)
            areg[it] = *(const float4*)&A[(size_t)(cm + am + it * 16) * 1024 + kt * 64 + ak4 * 4];
#pragma unroll
        for (int it = 0; it < 4; it++)
#pragma unroll
            for (int j = 0; j < 2; j++)
                breg[it][j] = *(const float4*)&W[(size_t)(kt * 64 + 2 * (bkp + it * 8) + j) * N_ + cn + bn4 * 4];
    };
    auto sts_tile = [&](int buf) {
        uint32_t* Ah = sw + buf * G_STG_W;
        uint32_t* Al = Ah + G_ARR;
        uint32_t* Bh = Ah + 2 * G_ARR;
        uint32_t* Bl = Ah + 3 * G_ARR;
#pragma unroll
        for (int it = 0; it < 8; it++) {
            uint32_t h0, h1, l0, l1;
            cvt_split2(areg[it].x, areg[it].y, h0, l0);
            cvt_split2(areg[it].z, areg[it].w, h1, l1);
            int w = (am + it * 16) * G_LD + ak4 * 2;
            *(uint2*)(Ah + w) = make_uint2(h0, h1);
            *(uint2*)(Al + w) = make_uint2(l0, l1);
        }
#pragma unroll
        for (int it = 0; it < 4; it++) {
            int kp = bkp + it * 8;
            const float* v0 = &breg[it][0].x;
            const float* v1 = &breg[it][1].x;
#pragma unroll
            for (int c = 0; c < 4; c++) {
                uint32_t h, l;
                cvt_split2(v0[c], v1[c], h, l);
                int w = (bn4 * 4 + c) * G_LD + kp;
                Bh[w] = h; Bl[w] = l;
            }
        }
    };

    ldg_tile(0);
    sts_tile(0);
    __syncthreads();

    constexpr int NT = 16;
    for (int kt = 0; kt < NT; kt++) {
        const int buf = kt & 1;
        if (kt + 1 < NT) ldg_tile(kt + 1);

        const uint32_t ab = a_fb + buf * G_STG_B;
        const uint32_t bb = b_fb + buf * G_STG_B;
#pragma unroll
        for (int ks = 0; ks < 4; ks++) {
            uint32_t ah[4][4], al[4][4];
#pragma unroll
            for (int mi = 0; mi < 4; mi++) {
                uint32_t ad = ab + 4u * (mi * 16 * G_LD + ks * 8);
                ldsm_x4(ad, ah[mi][0], ah[mi][1], ah[mi][2], ah[mi][3]);
                ldsm_x4(ad + G_ARR * 4, al[mi][0], al[mi][1], al[mi][2], al[mi][3]);
            }
            uint32_t bh[4][2], bl[4][2];
#pragma unroll
            for (int p = 0; p < 2; p++) {
                uint32_t bd = bb + 4u * (p * 16 * G_LD + ks * 8);
                ldsm_x4(bd, bh[2 * p][0], bh[2 * p][1], bh[2 * p + 1][0], bh[2 * p + 1][1]);
                ldsm_x4(bd + G_ARR * 4, bl[2 * p][0], bl[2 * p][1], bl[2 * p + 1][0], bl[2 * p + 1][1]);
            }
#pragma unroll
            for (int mi = 0; mi < 4; mi++)
#pragma unroll
                for (int nj = 0; nj < 4; nj++) {
                    mma_bf16(acc[mi][nj], al[mi], bh[nj], acc[mi][nj]);
                    mma_bf16(acc[mi][nj], ah[mi], bl[nj], acc[mi][nj]);
                    mma_bf16(acc[mi][nj], ah[mi], bh[nj], acc[mi][nj]);
                }
        }
        if (kt + 1 < NT) sts_tile(buf ^ 1);
        __syncthreads();
    }

    // Epilogue
#pragma unroll
    for (int mi = 0; mi < 4; mi++) {
#pragma unroll
        for (int nj = 0; nj < 4; nj++) {
            int col0 = cn + wn * 32 + nj * 8 + 2 * tg;
            float2 v0 = make_float2(acc[mi][nj][0] + bias[col0],
                                    acc[mi][nj][1] + bias[col0 + 1]);
            float2 v1 = make_float2(acc[mi][nj][2] + bias[col0],
                                    acc[mi][nj][3] + bias[col0 + 1]);
            int row0 = cm + wm * 64 + mi * 16 + g;
            int row1 = row0 + 8;
            if (EPI == 1) {
                *(float2*)&out[(size_t)row0 * N_ + col0] = v0;
                *(float2*)&out[(size_t)row1 * N_ + col0] = v1;
            } else {
                int t = col0 >> 10;
                int r1 = col0 & 1023;
                int h = r1 >> 6, d = r1 & 63;
                float* dst = (t == 0) ? g_q : (t == 1) ? g_k : g_v;
                int b0 = row0 >> 11, s0 = row0 & 2047;
                int b1 = row1 >> 11, s1 = row1 & 2047;
                *(float2*)&dst[(((size_t)(b0 * Hc + h)) * Sc + s0) * HDc + d] = v0;
                *(float2*)&dst[(((size_t)(b1 * Hc + h)) * Sc + s1) * HDc + d] = v1;
            }
        }
    }
}

// ---------------------------------------------------------------------------
// Flash attention: causal, hd=64. QK^T bf16 3x-split (ldmatrix), PV 1xTF32
// with pre-converted P/V (tf32 stored in SMEM). 8 warps x 16 query rows.
// SMEM: Ps/Pu 128x132 | Ksh,Ksl 128x36 (bf16 words) | Vu 128x72 (tf32 words)
// ---------------------------------------------------------------------------
constexpr int F_LDP = 132;
constexpr int F_LDQ = 68;                                // Q staging stride
constexpr int F_LDV = 72;                                // V stride (conflict-free)
constexpr int F_KSH_B = 128 * F_LDP * 4;                 // 67584
constexpr int F_KSL_B = F_KSH_B + 128 * G_LD * 4;        // +18432
constexpr int F_VS_B  = F_KSL_B + 128 * G_LD * 4;        // +18432
constexpr int FLASH_SMEM = F_VS_B + 128 * F_LDV * 4;     // 141312

__global__ void __launch_bounds__(256, 1)
flash_kernel()
{
    extern __shared__ char smc[];
    float*    Ps  = (float*)smc;                 // Q staging (fp32) then P (tf32 bits)
    uint32_t* Pu  = (uint32_t*)smc;
    uint32_t* Ksh = (uint32_t*)(smc + F_KSH_B);
    uint32_t* Ksl = (uint32_t*)(smc + F_KSL_B);
    uint32_t* Vu  = (uint32_t*)(smc + F_VS_B);
    const uint32_t smb = (uint32_t)__cvta_generic_to_shared(smc);

    const int tid = threadIdx.x, wid = tid >> 5, lid = tid & 31;
    const int g = lid >> 2, tg = lid & 3;
    const int qb = blockIdx.x;
    const int head = blockIdx.y;

    const float* Qg = g_q + (size_t)head * Sc * HDc + (size_t)qb * 128 * HDc;
    const float* Kg = g_k + (size_t)head * Sc * HDc;
    const float* Vg = g_v + (size_t)head * Sc * HDc;

    // Stage Q (fp32), split to bf16 hi/lo fragments once.
#pragma unroll
    for (int it = 0; it < 8; it++) {
        int idx = tid + it * 256;
        int r = idx >> 4, c4 = idx & 15;
        cp16(Ps + r * F_LDQ + c4 * 4, Qg + (size_t)r * HDc + c4 * 4);
    }
    cp_commit(); cp_wait<0>();
    __syncthreads();

    uint32_t qh[4][4], ql[4][4];
    {
        int r = wid * 16 + g;
#pragma unroll
        for (int ks = 0; ks < 4; ks++) {
            int k0 = ks * 16 + 2 * tg;
            cvt_split2(Ps[r * F_LDQ + k0],           Ps[r * F_LDQ + k0 + 1],       qh[ks][0], ql[ks][0]);
            cvt_split2(Ps[(r + 8) * F_LDQ + k0],     Ps[(r + 8) * F_LDQ + k0 + 1], qh[ks][1], ql[ks][1]);
            cvt_split2(Ps[r * F_LDQ + k0 + 8],       Ps[r * F_LDQ + k0 + 9],       qh[ks][2], ql[ks][2]);
            cvt_split2(Ps[(r + 8) * F_LDQ + k0 + 8], Ps[(r + 8) * F_LDQ + k0 + 9], qh[ks][3], ql[ks][3]);
        }
    }
    __syncthreads();   // Ps now reusable as P

    // K fragment ldmatrix base (B-operand pattern)
    const uint32_t k_fb = smb + F_KSH_B
        + 4u * ((((lid >> 4) & 1) * 8 + (lid & 7)) * G_LD + ((lid >> 3) & 1) * 4);

    float o[8][4];
#pragma unroll
    for (int j = 0; j < 8; j++)
#pragma unroll
        for (int e = 0; e < 4; e++) o[j][e] = 0.f;
    float m0 = -1e30f, m1 = -1e30f, l0 = 0.f, l1 = 0.f;

    const float scale = 0.125f;
    const float LOG2E = 1.4426950408889634f;
    const int row0g = qb * 128 + wid * 16 + g;
    const int row1g = row0g + 8;

    const int kr = tid >> 4, kd4 = tid & 15;   // K/V load coords (2 rows/warp, 16 col4)

    for (int kb = 0; kb <= qb; kb++) {
        // Batched LDG for K and V (MLP), then convert + STS.
        float4 kvr[8], vvr[8];
#pragma unroll
        for (int it = 0; it < 8; it++)
            kvr[it] = *(const float4*)&Kg[(size_t)(kb * 128 + kr + it * 16) * HDc + kd4 * 4];
#pragma unroll
        for (int it = 0; it < 8; it++)
            vvr[it] = *(const float4*)&Vg[(size_t)(kb * 128 + kr + it * 16) * HDc + kd4 * 4];
#pragma unroll
        for (int it = 0; it < 8; it++) {
            uint32_t h0, h1, lw0, lw1;
            cvt_split2(kvr[it].x, kvr[it].y, h0, lw0);
            cvt_split2(kvr[it].z, kvr[it].w, h1, lw1);
            int w = (kr + it * 16) * G_LD + kd4 * 2;
            *(uint2*)(Ksh + w) = make_uint2(h0, h1);
            *(uint2*)(Ksl + w) = make_uint2(lw0, lw1);
        }
#pragma unroll
        for (int it = 0; it < 8; it++) {
            int w = (kr + it * 16) * F_LDV + kd4 * 4;
            *(uint4*)(Vu + w) = make_uint4(f2tf(vvr[it].x), f2tf(vvr[it].y),
                                           f2tf(vvr[it].z), f2tf(vvr[it].w));
        }
        __syncthreads();

        // S = Q K^T : bf16 3x via ldmatrix
        float sacc[16][4];
#pragma unroll
        for (int nj = 0; nj < 16; nj++)
#pragma unroll
            for (int e = 0; e < 4; e++) sacc[nj][e] = 0.f;
#pragma unroll
        for (int ks = 0; ks < 4; ks++) {
#pragma unroll
            for (int p = 0; p < 8; p++) {
                uint32_t kd = k_fb + 4u * (p * 16 * G_LD + ks * 8);
                uint32_t bh0[2], bh1[2], bl0[2], bl1[2];
                ldsm_x4(kd, bh0[0], bh0[1], bh1[0], bh1[1]);
                ldsm_x4(kd + (F_KSL_B - F_KSH_B), bl0[0], bl0[1], bl1[0], bl1[1]);
                int nj0 = 2 * p, nj1 = 2 * p + 1;
                mma_bf16(sacc[nj0], ql[ks], bh0, sacc[nj0]);
                mma_bf16(sacc[nj0], qh[ks], bl0, sacc[nj0]);
                mma_bf16(sacc[nj0], qh[ks], bh0, sacc[nj0]);
                mma_bf16(sacc[nj1], ql[ks], bh1, sacc[nj1]);
                mma_bf16(sacc[nj1], qh[ks], bl1, sacc[nj1]);
                mma_bf16(sacc[nj1], qh[ks], bh1, sacc[nj1]);
            }
        }

        // scale + causal mask
#pragma unroll
        for (int nj = 0; nj < 16; nj++) {
#pragma unroll
            for (int e = 0; e < 4; e++) {
                int col = kb * 128 + nj * 8 + 2 * tg + (e & 1);
                int row = (e & 2) ? row1g : row0g;
                float v = sacc[nj][e] * scale;
                sacc[nj][e] = (col > row) ? -1e30f : v;
            }
        }

        float rmax0 = -1e30f, rmax1 = -1e30f;
#pragma unroll
        for (int nj = 0; nj < 16; nj++) {
            rmax0 = fmaxf(rmax0, fmaxf(sacc[nj][0], sacc[nj][1]));
            rmax1 = fmaxf(rmax1, fmaxf(sacc[nj][2], sacc[nj][3]));
        }
        rmax0 = fmaxf(rmax0, __shfl_xor_sync(0xffffffffu, rmax0, 1));
        rmax0 = fmaxf(rmax0, __shfl_xor_sync(0xffffffffu, rmax0, 2));
        rmax1 = fmaxf(rmax1, __shfl_xor_sync(0xffffffffu, rmax1, 1));
        rmax1 = fmaxf(rmax1, __shfl_xor_sync(0xffffffffu, rmax1, 2));

        float nm0 = fmaxf(m0, rmax0), nm1 = fmaxf(m1, rmax1);
        float alpha0 = exp2f((m0 - nm0) * LOG2E);
        float alpha1 = exp2f((m1 - nm1) * LOG2E);

        float rs0 = 0.f, rs1 = 0.f;
#pragma unroll
        for (int nj = 0; nj < 16; nj++) {
            float p0 = exp2f((sacc[nj][0] - nm0) * LOG2E);
            float p1 = exp2f((sacc[nj][1] - nm0) * LOG2E);
            float p2 = exp2f((sacc[nj][2] - nm1) * LOG2E);
            float p3 = exp2f((sacc[nj][3] - nm1) * LOG2E);
            sacc[nj][0] = p0; sacc[nj][1] = p1; sacc[nj][2] = p2; sacc[nj][3] = p3;
            rs0 += p0 + p1; rs1 += p2 + p3;
        }
        rs0 += __shfl_xor_sync(0xffffffffu, rs0, 1);
        rs0 += __shfl_xor_sync(0xffffffffu, rs0, 2);
        rs1 += __shfl_xor_sync(0xffffffffu, rs1, 1);
        rs1 += __shfl_xor_sync(0xffffffffu, rs1, 2);

        m0 = nm0; m1 = nm1;
        l0 = l0 * alpha0 + rs0;
        l1 = l1 * alpha1 + rs1;
#pragma unroll
        for (int j = 0; j < 8; j++) {
            o[j][0] *= alpha0; o[j][1] *= alpha0;
            o[j][2] *= alpha1; o[j][3] *= alpha1;
        }

        // Stage P as tf32 bits (C-layout -> A-layout)
        {
            int pr = wid * 16 + g;
#pragma unroll
            for (int nj = 0; nj < 16; nj++) {
                int wbase = pr * F_LDP + nj * 8 + 2 * tg;
                *(uint2*)(Pu + wbase)               = make_uint2(f2tf(sacc[nj][0]), f2tf(sacc[nj][1]));
                *(uint2*)(Pu + wbase + 8 * F_LDP)   = make_uint2(f2tf(sacc[nj][2]), f2tf(sacc[nj][3]));
            }
        }
        __syncwarp();

        // O += P V  (1xTF32, pre-converted operands)
#pragma unroll
        for (int ks = 0; ks < 16; ks++) {
            uint32_t af[4];
            int r = wid * 16 + g;
            af[0] = Pu[r * F_LDP + ks * 8 + tg];
            af[1] = Pu[(r + 8) * F_LDP + ks * 8 + tg];
            af[2] = Pu[r * F_LDP + ks * 8 + tg + 4];
            af[3] = Pu[(r + 8) * F_LDP + ks * 8 + tg + 4];
#pragma unroll
            for (int nj = 0; nj < 8; nj++) {
                uint32_t bf[2];
                bf[0] = Vu[(ks * 8 + tg) * F_LDV + nj * 8 + g];
                bf[1] = Vu[(ks * 8 + tg + 4) * F_LDV + nj * 8 + g];
                mma_tf32(o[nj], af, bf, o[nj]);
            }
        }
        __syncthreads();   // protect K/V/P for next k-block
    }

    // Write O / l into g_attn[(b,s,h*64+d)]
    {
        int b = head >> 4, h = head & 15;
        int s0 = qb * 128 + wid * 16 + g;
        float inv0 = 1.f / l0, inv1 = 1.f / l1;
        size_t base0 = ((size_t)b * Sc + s0) * Dc + h * HDc;
        size_t base1 = ((size_t)b * Sc + s0 + 8) * Dc + h * HDc;
#pragma unroll
        for (int nj = 0; nj < 8; nj++) {
            int d0 = nj * 8 + 2 * tg;
            *(float2*)&g_attn[base0 + d0] = make_float2(o[nj][0] * inv0, o[nj][1] * inv0);
            *(float2*)&g_attn[base1 + d0] = make_float2(o[nj][2] * inv1, o[nj][3] * inv1);
        }
    }
}

// ---------------------------------------------------------------------------
extern "C" void kernel_launch(void* const* d_in, const int* in_sizes, int n_in,
                              void* d_out, int out_size)
{
    (void)in_sizes; (void)n_in; (void)out_size;
    const float* x      = (const float*)d_in[0];
    const float* w_attn = (const float*)d_in[2];
    const float* b_attn = (const float*)d_in[3];
    const float* w_proj = (const float*)d_in[4];
    const float* b_proj = (const float*)d_in[5];
    float* out = (float*)d_out;

    cudaFuncSetAttribute(bf_gemm<NQKV, 0>, cudaFuncAttributeMaxDynamicSharedMemorySize, G_SMEM);
    cudaFuncSetAttribute(bf_gemm<Dc, 1>,   cudaFuncAttributeMaxDynamicSharedMemorySize, G_SMEM);
    cudaFuncSetAttribute(flash_kernel,     cudaFuncAttributeMaxDynamicSharedMemorySize, FLASH_SMEM);

    // 1) QKV = x @ w_attn + b_attn (bf16 3x-split, ldmatrix, double-buffered)
    bf_gemm<NQKV, 0><<<dim3(NQKV / 128, Mc / 128), 256, G_SMEM>>>(x, w_attn, b_attn, nullptr);
    // 2) causal flash attention
    flash_kernel<<<dim3(Sc / 128, Bc * Hc), 256, FLASH_SMEM>>>();
    // 3) out = attn @ w_proj + b_proj
    bf_gemm<Dc, 1><<<dim3(Dc / 128, Mc / 128), 256, G_SMEM>>>(nullptr, w_proj, b_proj, out);
}

// round 6
// speedup vs baseline: 1.7111x; 1.0745x over previous
#include <cuda_runtime.h>
#include <cstdint>

#define DEVINL __device__ __forceinline__

constexpr int Bc = 4, Sc = 2048, Dc = 1024, Hc = 16, HDc = 64;
constexpr int Mc = Bc * Sc;           // 8192
constexpr int NQKV = 3 * Dc;          // 3072

// ---------------------------------------------------------------------------
// Scratch (__device__ globals). All bf16 data stored as packed bf16x2 words.
// ---------------------------------------------------------------------------
__device__ uint32_t g_xh[(size_t)Mc * 512], g_xl[(size_t)Mc * 512];      // x      [8192][512]
__device__ uint32_t g_wth[(size_t)NQKV * 512], g_wtl[(size_t)NQKV * 512];// wA^T   [3072][512]
__device__ uint32_t g_wph[(size_t)Dc * 512], g_wpl[(size_t)Dc * 512];    // wP^T   [1024][512]
__device__ uint32_t g_qh[(size_t)64 * Sc * 32], g_ql[(size_t)64 * Sc * 32]; // q   [64][2048][32]
__device__ uint32_t g_kh[(size_t)64 * Sc * 32], g_kl[(size_t)64 * Sc * 32]; // k
__device__ uint32_t g_vt[(size_t)64 * Sc * 64];                             // v tf32 [64][2048][64]
__device__ uint32_t g_ah[(size_t)Mc * 512], g_al[(size_t)Mc * 512];      // attn  [8192][512]

// ---------------------------------------------------------------------------
// Helpers
// ---------------------------------------------------------------------------
DEVINL uint32_t f2tf(float x) {
    uint32_t u; asm("cvt.rna.tf32.f32 %0, %1;" : "=r"(u) : "f"(x)); return u;
}
// Pack (x0,x1) -> bf16x2 hi word + residual lo word. lower 16 bits = x0.
DEVINL void cvt_split2(float x0, float x1, uint32_t& h, uint32_t& l) {
    asm("cvt.rn.bf16x2.f32 %0, %1, %2;" : "=r"(h) : "f"(x1), "f"(x0));
    float r0 = x0 - __uint_as_float(h << 16);
    float r1 = x1 - __uint_as_float(h & 0xffff0000u);
    asm("cvt.rn.bf16x2.f32 %0, %1, %2;" : "=r"(l) : "f"(r1), "f"(r0));
}
DEVINL void mma_bf16(float d[4], const uint32_t a[4], const uint32_t b[2], const float c[4]) {
    asm volatile(
        "mma.sync.aligned.m16n8k16.row.col.f32.bf16.bf16.f32 "
        "{%0,%1,%2,%3}, {%4,%5,%6,%7}, {%8,%9}, {%10,%11,%12,%13};\n"
        : "=f"(d[0]), "=f"(d[1]), "=f"(d[2]), "=f"(d[3])
        : "r"(a[0]), "r"(a[1]), "r"(a[2]), "r"(a[3]),
          "r"(b[0]), "r"(b[1]),
          "f"(c[0]), "f"(c[1]), "f"(c[2]), "f"(c[3]));
}
DEVINL void mma_tf32(float d[4], const uint32_t a[4], const uint32_t b[2], const float c[4]) {
    asm volatile(
        "mma.sync.aligned.m16n8k8.row.col.f32.tf32.tf32.f32 "
        "{%0,%1,%2,%3}, {%4,%5,%6,%7}, {%8,%9}, {%10,%11,%12,%13};\n"
        : "=f"(d[0]), "=f"(d[1]), "=f"(d[2]), "=f"(d[3])
        : "r"(a[0]), "r"(a[1]), "r"(a[2]), "r"(a[3]),
          "r"(b[0]), "r"(b[1]),
          "f"(c[0]), "f"(c[1]), "f"(c[2]), "f"(c[3]));
}
DEVINL void ldsm_x4(uint32_t addr, uint32_t& r0, uint32_t& r1, uint32_t& r2, uint32_t& r3) {
    asm volatile("ldmatrix.sync.aligned.m8n8.x4.shared.b16 {%0,%1,%2,%3}, [%4];"
                 : "=r"(r0), "=r"(r1), "=r"(r2), "=r"(r3) : "r"(addr));
}
DEVINL void cp16(void* s, const void* g) {
    uint32_t sa = (uint32_t)__cvta_generic_to_shared(s);
    asm volatile("cp.async.cg.shared.global [%0], [%1], 16;\n" :: "r"(sa), "l"(g));
}
DEVINL void cp_commit() { asm volatile("cp.async.commit_group;\n"); }
template <int N> DEVINL void cp_wait() { asm volatile("cp.async.wait_group %0;\n" :: "n"(N)); }

// ---------------------------------------------------------------------------
// Pre-pass 1: split x (fp32 row-major [8192][1024]) -> g_xh/g_xl
// ---------------------------------------------------------------------------
__global__ void conv_x(const float* __restrict__ x)
{
    size_t idx = (size_t)blockIdx.x * 1024 + threadIdx.x;   // word index, 4M total
    float2 v = ((const float2*)x)[idx];
    uint32_t h, l;
    cvt_split2(v.x, v.y, h, l);
    g_xh[idx] = h; g_xl[idx] = l;
}

// ---------------------------------------------------------------------------
// Pre-pass 2: transpose + split W (fp32 [1024][N]) -> [N][512 words] hi/lo.
// which=0 -> g_wth/g_wtl (N=3072), which=1 -> g_wph/g_wpl (N=1024).
// Tile 64(k) x 32(n), block (32,8).
// ---------------------------------------------------------------------------
__global__ void conv_wT(const float* __restrict__ W, int N, int which)
{
    __shared__ float ts[64][33];
    uint32_t* Wh = which ? g_wph : g_wth;
    uint32_t* Wl = which ? g_wpl : g_wtl;
    const int k0 = blockIdx.x * 64, n0 = blockIdx.y * 32;
    const int tx = threadIdx.x, ty = threadIdx.y;
#pragma unroll
    for (int i = 0; i < 8; i++)
        ts[ty + i * 8][tx] = W[(size_t)(k0 + ty + i * 8) * N + n0 + tx];
    __syncthreads();
#pragma unroll
    for (int i = 0; i < 4; i++) {
        int n = ty + i * 8;
        uint32_t h, l;
        cvt_split2(ts[2 * tx][n], ts[2 * tx + 1][n], h, l);
        size_t w = (size_t)(n0 + n) * 512 + (k0 >> 1) + tx;
        Wh[w] = h; Wl[w] = l;
    }
}

// ---------------------------------------------------------------------------
// bf16 3x-split GEMM, all-bf16 cp.async pipeline.
// C = A(Mx1024) W^T_rowmajor + bias. CTA 128x128, BK=32, 4-stage cp.async.
// 8 warps 2(m)x4(n): warp tile 64x32.
// SMEM stage: Ah|Al|Bh|Bl, each 128 rows x 16 words, stride 20 (conflict-free).
// EPI=0: A=g_xh/xl, B=g_wth/wtl, scatter epilogue -> q/k bf16 hi/lo, v tf32.
// EPI=1: A=g_ah/al, B=g_wph/wpl, out fp32 + bias.
// ---------------------------------------------------------------------------
constexpr int P_LD = 20;                       // words/row (16 + 4 pad)
constexpr int P_ARR_W = 128 * P_LD;            // 2560 words
constexpr int P_ARR_B = P_ARR_W * 4;           // 10240 B
constexpr int P_STG_W = 4 * P_ARR_W;           // 10240 words
constexpr int P_STG_B = P_STG_W * 4;           // 40960 B
constexpr int G_SMEM = 4 * P_STG_B;            // 163840 B

template <int EPI>
__global__ void __launch_bounds__(256, 1)
bf_gemm(const float* __restrict__ bias, float* __restrict__ out)
{
    extern __shared__ uint32_t sw[];
    const uint32_t* Agh = EPI ? g_ah : g_xh;
    const uint32_t* Agl = EPI ? g_al : g_xl;
    const uint32_t* Bgh = EPI ? g_wph : g_wth;
    const uint32_t* Bgl = EPI ? g_wpl : g_wtl;

    const int tid = threadIdx.x, wid = tid >> 5, lid = tid & 31;
    const int wm = wid >> 2, wn = wid & 3;
    const int g = lid >> 2, tg = lid & 3;
    const int cm = blockIdx.y * 128, cn = blockIdx.x * 128;
    const uint32_t smb = (uint32_t)__cvta_generic_to_shared(sw);

    // ldmatrix fragment bases (bytes, within stage)
    const uint32_t a_fb = smb + 4u * ((wm * 64 + (lid & 15)) * P_LD + (lid >> 4) * 4);
    const uint32_t b_fb = smb + 4u * ((wn * 32 + ((lid >> 4) & 1) * 8 + (lid & 7)) * P_LD
                                      + ((lid >> 3) & 1) * 4) + 2u * P_ARR_B;

    // cp.async coords: 512 chunks per array, 2 per thread
    const int row = tid >> 1;                 // 0..127
    const int ch0 = (tid & 1) * 2;            // chunks {0,1} or {2,3}

    auto load_stage = [&](int kt, int s) {
#pragma unroll
        for (int i = 0; i < 2; i++) {
            int c = ch0 + i;
            uint32_t dst = (uint32_t)(s * P_STG_W + row * P_LD + c * 4);
            size_t asrc = (size_t)(cm + row) * 512 + kt * 16 + c * 4;   // FIX: kt*16
            size_t bsrc = (size_t)(cn + row) * 512 + kt * 16 + c * 4;   // FIX: kt*16
            cp16(sw + dst,               Agh + asrc);
            cp16(sw + dst + P_ARR_W,     Agl + asrc);
            cp16(sw + dst + 2 * P_ARR_W, Bgh + bsrc);
            cp16(sw + dst + 3 * P_ARR_W, Bgl + bsrc);
        }
    };

    float acc[4][4][4];
#pragma unroll
    for (int i = 0; i < 4; i++)
#pragma unroll
        for (int j = 0; j < 4; j++)
#pragma unroll
            for (int e = 0; e < 4; e++) acc[i][j][e] = 0.f;

    constexpr int NT = 32;                     // K=1024 / 32
    load_stage(0, 0); cp_commit();
    load_stage(1, 1); cp_commit();
    load_stage(2, 2); cp_commit();

    for (int kt = 0; kt < NT; kt++) {
        cp_wait<2>();
        __syncthreads();
        if (kt + 3 < NT) load_stage(kt + 3, (kt + 3) & 3);
        cp_commit();

        const uint32_t sb = (uint32_t)((kt & 3) * P_STG_B);
#pragma unroll
        for (int ks = 0; ks < 2; ks++) {
            uint32_t ah[4][4], al[4][4];
#pragma unroll
            for (int mi = 0; mi < 4; mi++) {
                uint32_t ad = a_fb + sb + 4u * (mi * 16 * P_LD + ks * 8);
                ldsm_x4(ad,           ah[mi][0], ah[mi][1], ah[mi][2], ah[mi][3]);
                ldsm_x4(ad + P_ARR_B, al[mi][0], al[mi][1], al[mi][2], al[mi][3]);
            }
            uint32_t bh[4][2], bl[4][2];
#pragma unroll
            for (int p = 0; p < 2; p++) {
                uint32_t bd = b_fb + sb + 4u * (p * 16 * P_LD + ks * 8);
                ldsm_x4(bd,           bh[2 * p][0], bh[2 * p][1], bh[2 * p + 1][0], bh[2 * p + 1][1]);
                ldsm_x4(bd + P_ARR_B, bl[2 * p][0], bl[2 * p][1], bl[2 * p + 1][0], bl[2 * p + 1][1]);
            }
#pragma unroll
            for (int mi = 0; mi < 4; mi++)
#pragma unroll
                for (int nj = 0; nj < 4; nj++) {
                    mma_bf16(acc[mi][nj], al[mi], bh[nj], acc[mi][nj]);
                    mma_bf16(acc[mi][nj], ah[mi], bl[nj], acc[mi][nj]);
                    mma_bf16(acc[mi][nj], ah[mi], bh[nj], acc[mi][nj]);
                }
        }
    }

    // Epilogue
#pragma unroll
    for (int mi = 0; mi < 4; mi++) {
#pragma unroll
        for (int nj = 0; nj < 4; nj++) {
            int col0 = cn + wn * 32 + nj * 8 + 2 * tg;       // even
            float2 v0 = make_float2(acc[mi][nj][0] + bias[col0],
                                    acc[mi][nj][1] + bias[col0 + 1]);
            float2 v1 = make_float2(acc[mi][nj][2] + bias[col0],
                                    acc[mi][nj][3] + bias[col0 + 1]);
            int row0 = cm + wm * 64 + mi * 16 + g;
            int row1 = row0 + 8;
            if (EPI == 1) {
                *(float2*)&out[(size_t)row0 * 1024 + col0] = v0;
                *(float2*)&out[(size_t)row1 * 1024 + col0] = v1;
            } else {
                int t = col0 >> 10;                // 0:q 1:k 2:v
                int r1 = col0 & 1023;
                int h = r1 >> 6, d = r1 & 63;      // d even
                int b0 = row0 >> 11, s0 = row0 & 2047;
                int b1 = row1 >> 11, s1 = row1 & 2047;
                size_t hw0 = ((size_t)(b0 * Hc + h) * Sc + s0) * 32 + (d >> 1);
                size_t hw1 = ((size_t)(b1 * Hc + h) * Sc + s1) * 32 + (d >> 1);
                if (t == 2) {
                    size_t vw0 = ((size_t)(b0 * Hc + h) * Sc + s0) * 64 + d;
                    size_t vw1 = ((size_t)(b1 * Hc + h) * Sc + s1) * 64 + d;
                    *(uint2*)&g_vt[vw0] = make_uint2(f2tf(v0.x), f2tf(v0.y));
                    *(uint2*)&g_vt[vw1] = make_uint2(f2tf(v1.x), f2tf(v1.y));
                } else {
                    uint32_t* Dh = (t == 0) ? g_qh : g_kh;
                    uint32_t* Dl = (t == 0) ? g_ql : g_kl;
                    uint32_t h0, l0, h1, l1;
                    cvt_split2(v0.x, v0.y, h0, l0);
                    cvt_split2(v1.x, v1.y, h1, l1);
                    Dh[hw0] = h0; Dl[hw0] = l0;
                    Dh[hw1] = h1; Dl[hw1] = l1;
                }
            }
        }
    }
}

// ---------------------------------------------------------------------------
// Flash attention: causal, hd=64. All operands pre-converted.
// QK^T bf16 3x-split (ldmatrix), PV 1xTF32. Double-buffered K/V via cp.async.
// SMEM: P 128x132 fp32 (Q staged there first) | K hi/lo 128x36 x2 stages |
//       V tf32 128x72 x2 stages.  Total 215040 B.
// ---------------------------------------------------------------------------
constexpr int F_LDP = 132;
constexpr int F_LDK = 36;
constexpr int F_LDV = 72;
constexpr int F_P_W   = 128 * F_LDP;              // 16896 words
constexpr int F_K_B   = F_P_W * 4;                // 67584: K stages base
constexpr int F_KSTG  = 2 * 128 * F_LDK * 4;      // 36864 B per stage (hi+lo)
constexpr int F_V_B   = F_K_B + 2 * F_KSTG;       // 141312
constexpr int F_VSTG  = 128 * F_LDV * 4;          // 36864
constexpr int FLASH_SMEM = F_V_B + 2 * F_VSTG;    // 215040

__global__ void __launch_bounds__(256, 1)
flash_kernel()
{
    extern __shared__ uint32_t smw[];
    uint32_t* Pu = smw;                       // P (tf32 words); Q staged here first
    const uint32_t smb = (uint32_t)__cvta_generic_to_shared(smw);

    const int tid = threadIdx.x, wid = tid >> 5, lid = tid & 31;
    const int g = lid >> 2, tg = lid & 3;
    const int qb = blockIdx.x;
    const int head = blockIdx.y;

    const uint32_t* Qh = g_qh + (size_t)head * Sc * 32 + (size_t)qb * 128 * 32;
    const uint32_t* Ql = g_ql + (size_t)head * Sc * 32 + (size_t)qb * 128 * 32;
    const uint32_t* Kh = g_kh + (size_t)head * Sc * 32;
    const uint32_t* Kl = g_kl + (size_t)head * Sc * 32;
    const uint32_t* Vt = g_vt + (size_t)head * Sc * 64;

    // Stage Q hi/lo (stride 36 words): Qh at word 0, Ql at word 4608.
#pragma unroll
    for (int i = 0; i < 4; i++) {
        int idx = tid + i * 256;               // 1024
        int r = idx >> 3, c = idx & 7;
        uint32_t dst = r * F_LDK + c * 4;
        cp16(smw + dst,        Qh + (size_t)r * 32 + c * 4);
        cp16(smw + dst + 4608, Ql + (size_t)r * 32 + c * 4);
    }
    cp_commit();

    auto load_tile = [&](int kb, int s) {
        const size_t kbase = (size_t)kb * 128;
#pragma unroll
        for (int i = 0; i < 4; i++) {          // K hi/lo: 1024 chunks each
            int idx = tid + i * 256;
            int r = idx >> 3, c = idx & 7;
            uint32_t dst = (F_K_B >> 2) + (uint32_t)s * (F_KSTG >> 2) + r * F_LDK + c * 4;
            size_t src = (kbase + r) * 32 + c * 4;
            cp16(smw + dst,                    Kh + src);
            cp16(smw + dst + 128 * F_LDK,      Kl + src);
        }
#pragma unroll
        for (int i = 0; i < 8; i++) {          // V: 2048 chunks
            int idx = tid + i * 256;
            int r = idx >> 4, c = idx & 15;
            uint32_t dst = (F_V_B >> 2) + (uint32_t)s * (F_VSTG >> 2) + r * F_LDV + c * 4;
            cp16(smw + dst, Vt + (kbase + r) * 64 + c * 4);
        }
    };
    load_tile(0, 0); cp_commit();

    // Extract Q fragments (A-operand) once.
    cp_wait<1>();                              // Q group done
    __syncthreads();
    uint32_t qh[4][4], ql[4][4];
    {
        uint32_t q_fb = smb + 4u * ((wid * 16 + (lid & 15)) * F_LDK + (lid >> 4) * 4);
#pragma unroll
        for (int ks = 0; ks < 4; ks++) {
            ldsm_x4(q_fb + 4u * (ks * 8),         qh[ks][0], qh[ks][1], qh[ks][2], qh[ks][3]);
            ldsm_x4(q_fb + 4u * (ks * 8) + 18432, ql[ks][0], ql[ks][1], ql[ks][2], ql[ks][3]);
        }
    }
    __syncthreads();                           // P region now reusable

    float o[8][4];
#pragma unroll
    for (int j = 0; j < 8; j++)
#pragma unroll
        for (int e = 0; e < 4; e++) o[j][e] = 0.f;
    float m0 = -1e30f, m1 = -1e30f, l0 = 0.f, l1 = 0.f;

    const float scale = 0.125f;
    const float LOG2E = 1.4426950408889634f;
    const int row0g = qb * 128 + wid * 16 + g;
    const int row1g = row0g + 8;

    const uint32_t k_fb0 = smb + F_K_B
        + 4u * ((((lid >> 4) & 1) * 8 + (lid & 7)) * F_LDK + ((lid >> 3) & 1) * 4);

    for (int kb = 0; kb <= qb; kb++) {
        if (kb + 1 <= qb) load_tile(kb + 1, (kb + 1) & 1);
        cp_commit();
        cp_wait<1>();                          // tile kb ready
        __syncthreads();

        const uint32_t kfb = k_fb0 + (uint32_t)(kb & 1) * F_KSTG;
        const uint32_t vbase = (F_V_B >> 2) + (uint32_t)(kb & 1) * (F_VSTG >> 2);

        // S = Q K^T : bf16 3x via ldmatrix
        float sacc[16][4];
#pragma unroll
        for (int nj = 0; nj < 16; nj++)
#pragma unroll
            for (int e = 0; e < 4; e++) sacc[nj][e] = 0.f;
#pragma unroll
        for (int ks = 0; ks < 4; ks++) {
#pragma unroll
            for (int p = 0; p < 8; p++) {
                uint32_t kd = kfb + 4u * (p * 16 * F_LDK + ks * 8);
                uint32_t bh0[2], bh1[2], bl0[2], bl1[2];
                ldsm_x4(kd,                   bh0[0], bh0[1], bh1[0], bh1[1]);
                ldsm_x4(kd + 128 * F_LDK * 4, bl0[0], bl0[1], bl1[0], bl1[1]);
                int nj0 = 2 * p, nj1 = 2 * p + 1;
                mma_bf16(sacc[nj0], ql[ks], bh0, sacc[nj0]);
                mma_bf16(sacc[nj0], qh[ks], bl0, sacc[nj0]);
                mma_bf16(sacc[nj0], qh[ks], bh0, sacc[nj0]);
                mma_bf16(sacc[nj1], ql[ks], bh1, sacc[nj1]);
                mma_bf16(sacc[nj1], qh[ks], bl1, sacc[nj1]);
                mma_bf16(sacc[nj1], qh[ks], bh1, sacc[nj1]);
            }
        }

        // scale + causal mask
#pragma unroll
        for (int nj = 0; nj < 16; nj++) {
#pragma unroll
            for (int e = 0; e < 4; e++) {
                int col = kb * 128 + nj * 8 + 2 * tg + (e & 1);
                int row = (e & 2) ? row1g : row0g;
                float v = sacc[nj][e] * scale;
                sacc[nj][e] = (col > row) ? -1e30f : v;
            }
        }

        float rmax0 = -1e30f, rmax1 = -1e30f;
#pragma unroll
        for (int nj = 0; nj < 16; nj++) {
            rmax0 = fmaxf(rmax0, fmaxf(sacc[nj][0], sacc[nj][1]));
            rmax1 = fmaxf(rmax1, fmaxf(sacc[nj][2], sacc[nj][3]));
        }
        rmax0 = fmaxf(rmax0, __shfl_xor_sync(0xffffffffu, rmax0, 1));
        rmax0 = fmaxf(rmax0, __shfl_xor_sync(0xffffffffu, rmax0, 2));
        rmax1 = fmaxf(rmax1, __shfl_xor_sync(0xffffffffu, rmax1, 1));
        rmax1 = fmaxf(rmax1, __shfl_xor_sync(0xffffffffu, rmax1, 2));

        float nm0 = fmaxf(m0, rmax0), nm1 = fmaxf(m1, rmax1);
        float alpha0 = exp2f((m0 - nm0) * LOG2E);
        float alpha1 = exp2f((m1 - nm1) * LOG2E);

        float rs0 = 0.f, rs1 = 0.f;
#pragma unroll
        for (int nj = 0; nj < 16; nj++) {
            float p0 = exp2f((sacc[nj][0] - nm0) * LOG2E);
            float p1 = exp2f((sacc[nj][1] - nm0) * LOG2E);
            float p2 = exp2f((sacc[nj][2] - nm1) * LOG2E);
            float p3 = exp2f((sacc[nj][3] - nm1) * LOG2E);
            sacc[nj][0] = p0; sacc[nj][1] = p1; sacc[nj][2] = p2; sacc[nj][3] = p3;
            rs0 += p0 + p1; rs1 += p2 + p3;
        }
        rs0 += __shfl_xor_sync(0xffffffffu, rs0, 1);
        rs0 += __shfl_xor_sync(0xffffffffu, rs0, 2);
        rs1 += __shfl_xor_sync(0xffffffffu, rs1, 1);
        rs1 += __shfl_xor_sync(0xffffffffu, rs1, 2);

        m0 = nm0; m1 = nm1;
        l0 = l0 * alpha0 + rs0;
        l1 = l1 * alpha1 + rs1;
#pragma unroll
        for (int j = 0; j < 8; j++) {
            o[j][0] *= alpha0; o[j][1] *= alpha0;
            o[j][2] *= alpha1; o[j][3] *= alpha1;
        }

        // Stage P as tf32 bits
        {
            int pr = wid * 16 + g;
#pragma unroll
            for (int nj = 0; nj < 16; nj++) {
                int wbase = pr * F_LDP + nj * 8 + 2 * tg;
                *(uint2*)(Pu + wbase)             = make_uint2(f2tf(sacc[nj][0]), f2tf(sacc[nj][1]));
                *(uint2*)(Pu + wbase + 8 * F_LDP) = make_uint2(f2tf(sacc[nj][2]), f2tf(sacc[nj][3]));
            }
        }
        __syncwarp();

        // O += P V  (1xTF32)
#pragma unroll
        for (int ks = 0; ks < 16; ks++) {
            uint32_t af[4];
            int r = wid * 16 + g;
            af[0] = Pu[r * F_LDP + ks * 8 + tg];
            af[1] = Pu[(r + 8) * F_LDP + ks * 8 + tg];
            af[2] = Pu[r * F_LDP + ks * 8 + tg + 4];
            af[3] = Pu[(r + 8) * F_LDP + ks * 8 + tg + 4];
#pragma unroll
            for (int nj = 0; nj < 8; nj++) {
                uint32_t bf[2];
                bf[0] = smw[vbase + (ks * 8 + tg) * F_LDV + nj * 8 + g];
                bf[1] = smw[vbase + (ks * 8 + tg + 4) * F_LDV + nj * 8 + g];
                mma_tf32(o[nj], af, bf, o[nj]);
            }
        }
        __syncthreads();   // all warps done with P and stage kb before overwrite
    }

    // Epilogue: write attn as bf16 hi/lo into g_ah/g_al [8192][512 words]
    {
        int b = head >> 4, h = head & 15;
        int s0 = qb * 128 + wid * 16 + g;
        float inv0 = 1.f / l0, inv1 = 1.f / l1;
        size_t base0 = ((size_t)b * Sc + s0) * 512 + h * 32;
        size_t base1 = ((size_t)b * Sc + s0 + 8) * 512 + h * 32;
#pragma unroll
        for (int nj = 0; nj < 8; nj++) {
            int dw = nj * 4 + tg;              // word index within head (d0/2)
            uint32_t h0, l0w, h1, l1w;
            cvt_split2(o[nj][0] * inv0, o[nj][1] * inv0, h0, l0w);
            cvt_split2(o[nj][2] * inv1, o[nj][3] * inv1, h1, l1w);
            g_ah[base0 + dw] = h0; g_al[base0 + dw] = l0w;
            g_ah[base1 + dw] = h1; g_al[base1 + dw] = l1w;
        }
    }
}

// ---------------------------------------------------------------------------
extern "C" void kernel_launch(void* const* d_in, const int* in_sizes, int n_in,
                              void* d_out, int out_size)
{
    (void)in_sizes; (void)n_in; (void)out_size;
    const float* x      = (const float*)d_in[0];
    const float* w_attn = (const float*)d_in[2];
    const float* b_attn = (const float*)d_in[3];
    const float* w_proj = (const float*)d_in[4];
    const float* b_proj = (const float*)d_in[5];
    float* out = (float*)d_out;

    cudaFuncSetAttribute(bf_gemm<0>,   cudaFuncAttributeMaxDynamicSharedMemorySize, G_SMEM);
    cudaFuncSetAttribute(bf_gemm<1>,   cudaFuncAttributeMaxDynamicSharedMemorySize, G_SMEM);
    cudaFuncSetAttribute(flash_kernel, cudaFuncAttributeMaxDynamicSharedMemorySize, FLASH_SMEM);

    // Pre-pass: split/transpose inputs to bf16 hi/lo
    conv_x<<<(Mc * 512) / 1024, 1024>>>(x);
    conv_wT<<<dim3(16, NQKV / 32), dim3(32, 8)>>>(w_attn, NQKV, 0);
    conv_wT<<<dim3(16, Dc / 32),   dim3(32, 8)>>>(w_proj, Dc, 1);

    // 1) QKV GEMM -> q/k bf16 hi/lo + v tf32 (head-major)
    bf_gemm<0><<<dim3(NQKV / 128, Mc / 128), 256, G_SMEM>>>(b_attn, nullptr);
    // 2) causal flash attention -> attn bf16 hi/lo
    flash_kernel<<<dim3(Sc / 128, Bc * Hc), 256, FLASH_SMEM>>>();
    // 3) proj GEMM -> out fp32
    bf_gemm<1><<<dim3(Dc / 128, Mc / 128), 256, G_SMEM>>>(b_proj, out);
}

// round 7
// speedup vs baseline: 2.6622x; 1.5559x over previous
#include <cuda_runtime.h>
#include <cstdint>

#define DEVINL __device__ __forceinline__

constexpr int Bc = 4, Sc = 2048, Dc = 1024, Hc = 16;
constexpr int Mc = Bc * Sc;           // 8192
constexpr int NQKV = 3 * Dc;          // 3072

// ---------------------------------------------------------------------------
// Scratch (__device__ globals). All fp16 data stored as packed f16x2 words.
// ---------------------------------------------------------------------------
__device__ uint32_t g_xh[(size_t)Mc * 512], g_xl[(size_t)Mc * 512];      // x split [8192][512]
__device__ uint32_t g_wth[(size_t)NQKV * 512];                           // wA^T hi [3072][512]
__device__ uint32_t g_wph[(size_t)Dc * 512];                             // wP^T hi [1024][512]
__device__ uint32_t g_qh[(size_t)64 * Sc * 32], g_ql[(size_t)64 * Sc * 32]; // q split [64][2048][32]
__device__ uint32_t g_kh[(size_t)64 * Sc * 32];                             // k hi
__device__ uint32_t g_vh[(size_t)64 * Sc * 32];                             // v hi
__device__ uint32_t g_ah[(size_t)Mc * 512], g_al[(size_t)Mc * 512];      // attn split [8192][512]

// ---------------------------------------------------------------------------
// Helpers
// ---------------------------------------------------------------------------
DEVINL uint32_t pack_h2(float x0, float x1) {
    uint32_t h;
    asm("cvt.rn.f16x2.f32 %0, %1, %2;" : "=r"(h) : "f"(x1), "f"(x0));
    return h;
}
DEVINL void split_h2(float x0, float x1, uint32_t& h, uint32_t& l) {
    h = pack_h2(x0, x1);
    float b0, b1;
    asm("{\n\t.reg .f16 lo, hi;\n\tmov.b32 {lo, hi}, %2;\n\t"
        "cvt.f32.f16 %0, lo;\n\tcvt.f32.f16 %1, hi;\n\t}"
        : "=f"(b0), "=f"(b1) : "r"(h));
    l = pack_h2(x0 - b0, x1 - b1);
}
DEVINL void mma_f16(float d[4], const uint32_t a[4], const uint32_t b[2], const float c[4]) {
    asm volatile(
        "mma.sync.aligned.m16n8k16.row.col.f32.f16.f16.f32 "
        "{%0,%1,%2,%3}, {%4,%5,%6,%7}, {%8,%9}, {%10,%11,%12,%13};\n"
        : "=f"(d[0]), "=f"(d[1]), "=f"(d[2]), "=f"(d[3])
        : "r"(a[0]), "r"(a[1]), "r"(a[2]), "r"(a[3]),
          "r"(b[0]), "r"(b[1]),
          "f"(c[0]), "f"(c[1]), "f"(c[2]), "f"(c[3]));
}
DEVINL void ldsm_x4(uint32_t addr, uint32_t& r0, uint32_t& r1, uint32_t& r2, uint32_t& r3) {
    asm volatile("ldmatrix.sync.aligned.m8n8.x4.shared.b16 {%0,%1,%2,%3}, [%4];"
                 : "=r"(r0), "=r"(r1), "=r"(r2), "=r"(r3) : "r"(addr));
}
DEVINL void ldsm_x4_t(uint32_t addr, uint32_t& r0, uint32_t& r1, uint32_t& r2, uint32_t& r3) {
    asm volatile("ldmatrix.sync.aligned.m8n8.x4.trans.shared.b16 {%0,%1,%2,%3}, [%4];"
                 : "=r"(r0), "=r"(r1), "=r"(r2), "=r"(r3) : "r"(addr));
}
DEVINL void cp16(void* s, const void* g) {
    uint32_t sa = (uint32_t)__cvta_generic_to_shared(s);
    asm volatile("cp.async.cg.shared.global [%0], [%1], 16;\n" :: "r"(sa), "l"(g));
}
DEVINL void cp_commit() { asm volatile("cp.async.commit_group;\n"); }
template <int N> DEVINL void cp_wait() { asm volatile("cp.async.wait_group %0;\n" :: "n"(N)); }

// ---------------------------------------------------------------------------
// Pre-pass 1: split x (fp32 [8192][1024]) -> g_xh/g_xl (f16x2 words)
// ---------------------------------------------------------------------------
__global__ void conv_x(const float* __restrict__ x)
{
    size_t idx = (size_t)blockIdx.x * 1024 + threadIdx.x;   // 4M words
    float2 v = ((const float2*)x)[idx];
    uint32_t h, l;
    split_h2(v.x, v.y, h, l);
    g_xh[idx] = h; g_xl[idx] = l;
}

// ---------------------------------------------------------------------------
// Pre-pass 2: transpose + round W (fp32 [1024][N]) -> [N][512 words] hi only.
// which=0 -> g_wth (N=3072), which=1 -> g_wph (N=1024).
// ---------------------------------------------------------------------------
__global__ void conv_wT(const float* __restrict__ W, int N, int which)
{
    __shared__ float ts[64][33];
    uint32_t* Wh = which ? g_wph : g_wth;
    const int k0 = blockIdx.x * 64, n0 = blockIdx.y * 32;
    const int tx = threadIdx.x, ty = threadIdx.y;
#pragma unroll
    for (int i = 0; i < 8; i++)
        ts[ty + i * 8][tx] = W[(size_t)(k0 + ty + i * 8) * N + n0 + tx];
    __syncthreads();
#pragma unroll
    for (int i = 0; i < 4; i++) {
        int n = ty + i * 8;
        Wh[(size_t)(n0 + n) * 512 + (k0 >> 1) + tx] = pack_h2(ts[2 * tx][n], ts[2 * tx + 1][n]);
    }
}

// ---------------------------------------------------------------------------
// fp16 2-term GEMM: C = A(Mx1024) W^T + bias.  A = (Ah + Al), B = Bh.
// CTA 128x128, BK=32, 3-stage cp.async, 2 CTAs/SM.
// 8 warps 2(m)x4(n): warp tile 64x32.
// SMEM stage: Ah | Al | Bh, each 128 rows x 16 words, stride 20.
// EPI=0: A=x, B=wA -> scatter q/k split, v hi (head-major).
// EPI=1: A=attn, B=wP -> out fp32 + bias.
// ---------------------------------------------------------------------------
constexpr int P_LD = 20;                       // words/row (16 + 4 pad)
constexpr int P_ARR_W = 128 * P_LD;            // 2560 words
constexpr int P_ARR_B = P_ARR_W * 4;           // 10240 B
constexpr int P_STG_W = 3 * P_ARR_W;           // 7680 words
constexpr int P_STG_B = P_STG_W * 4;           // 30720 B
constexpr int G_SMEM = 3 * P_STG_B;            // 92160 B

template <int EPI>
__global__ void __launch_bounds__(256, 2)
h_gemm(const float* __restrict__ bias, float* __restrict__ out)
{
    extern __shared__ uint32_t sw[];
    const uint32_t* Agh = EPI ? g_ah : g_xh;
    const uint32_t* Agl = EPI ? g_al : g_xl;
    const uint32_t* Bgh = EPI ? g_wph : g_wth;

    const int tid = threadIdx.x, wid = tid >> 5, lid = tid & 31;
    const int wm = wid >> 2, wn = wid & 3;
    const int g = lid >> 2, tg = lid & 3;
    const int cm = blockIdx.y * 128, cn = blockIdx.x * 128;
    const uint32_t smb = (uint32_t)__cvta_generic_to_shared(sw);

    // ldmatrix fragment bases (bytes, within stage)
    const uint32_t a_fb = smb + 4u * ((wm * 64 + (lid & 15)) * P_LD + (lid >> 4) * 4);
    const uint32_t b_fb = smb + 4u * ((wn * 32 + ((lid >> 4) & 1) * 8 + (lid & 7)) * P_LD
                                      + ((lid >> 3) & 1) * 4) + 2u * P_ARR_B;

    const int row = tid >> 1;                 // 0..127
    const int ch0 = (tid & 1) * 2;

    auto load_stage = [&](int kt, int s) {
#pragma unroll
        for (int i = 0; i < 2; i++) {
            int c = ch0 + i;
            uint32_t dst = (uint32_t)(s * P_STG_W + row * P_LD + c * 4);
            size_t asrc = (size_t)(cm + row) * 512 + kt * 16 + c * 4;
            size_t bsrc = (size_t)(cn + row) * 512 + kt * 16 + c * 4;
            cp16(sw + dst,               Agh + asrc);
            cp16(sw + dst + P_ARR_W,     Agl + asrc);
            cp16(sw + dst + 2 * P_ARR_W, Bgh + bsrc);
        }
    };

    float acc[4][4][4];
#pragma unroll
    for (int i = 0; i < 4; i++)
#pragma unroll
        for (int j = 0; j < 4; j++)
#pragma unroll
            for (int e = 0; e < 4; e++) acc[i][j][e] = 0.f;

    constexpr int NT = 32;                     // K=1024 / 32
    load_stage(0, 0); cp_commit();
    load_stage(1, 1); cp_commit();

    for (int kt = 0; kt < NT; kt++) {
        cp_wait<1>();
        __syncthreads();
        if (kt + 2 < NT) load_stage(kt + 2, (kt + 2) % 3);
        cp_commit();

        const uint32_t sb = (uint32_t)((kt % 3) * P_STG_B);
#pragma unroll
        for (int ks = 0; ks < 2; ks++) {
            uint32_t ah[4][4], al[4][4];
#pragma unroll
            for (int mi = 0; mi < 4; mi++) {
                uint32_t ad = a_fb + sb + 4u * (mi * 16 * P_LD + ks * 8);
                ldsm_x4(ad,           ah[mi][0], ah[mi][1], ah[mi][2], ah[mi][3]);
                ldsm_x4(ad + P_ARR_B, al[mi][0], al[mi][1], al[mi][2], al[mi][3]);
            }
#pragma unroll
            for (int p = 0; p < 2; p++) {
                uint32_t b0[2], b1[2];
                ldsm_x4(b_fb + sb + 4u * (p * 16 * P_LD + ks * 8), b0[0], b0[1], b1[0], b1[1]);
#pragma unroll
                for (int mi = 0; mi < 4; mi++) {
                    mma_f16(acc[mi][2 * p],     al[mi], b0, acc[mi][2 * p]);
                    mma_f16(acc[mi][2 * p],     ah[mi], b0, acc[mi][2 * p]);
                    mma_f16(acc[mi][2 * p + 1], al[mi], b1, acc[mi][2 * p + 1]);
                    mma_f16(acc[mi][2 * p + 1], ah[mi], b1, acc[mi][2 * p + 1]);
                }
            }
        }
    }

    // Epilogue
#pragma unroll
    for (int mi = 0; mi < 4; mi++) {
#pragma unroll
        for (int nj = 0; nj < 4; nj++) {
            int col0 = cn + wn * 32 + nj * 8 + 2 * tg;       // even
            float2 v0 = make_float2(acc[mi][nj][0] + bias[col0],
                                    acc[mi][nj][1] + bias[col0 + 1]);
            float2 v1 = make_float2(acc[mi][nj][2] + bias[col0],
                                    acc[mi][nj][3] + bias[col0 + 1]);
            int row0 = cm + wm * 64 + mi * 16 + g;
            int row1 = row0 + 8;
            if (EPI == 1) {
                *(float2*)&out[(size_t)row0 * 1024 + col0] = v0;
                *(float2*)&out[(size_t)row1 * 1024 + col0] = v1;
            } else {
                int t = col0 >> 10;                // 0:q 1:k 2:v
                int r1 = col0 & 1023;
                int h = r1 >> 6, d = r1 & 63;      // d even
                int b0 = row0 >> 11, s0 = row0 & 2047;
                int b1 = row1 >> 11, s1 = row1 & 2047;
                size_t w0 = ((size_t)(b0 * Hc + h) * Sc + s0) * 32 + (d >> 1);
                size_t w1 = ((size_t)(b1 * Hc + h) * Sc + s1) * 32 + (d >> 1);
                if (t == 2) {
                    g_vh[w0] = pack_h2(v0.x, v0.y);
                    g_vh[w1] = pack_h2(v1.x, v1.y);
                } else if (t == 1) {
                    g_kh[w0] = pack_h2(v0.x, v0.y);
                    g_kh[w1] = pack_h2(v1.x, v1.y);
                } else {
                    uint32_t h0, l0, h1, l1;
                    split_h2(v0.x, v0.y, h0, l0);
                    split_h2(v1.x, v1.y, h1, l1);
                    g_qh[w0] = h0; g_ql[w0] = l0;
                    g_qh[w1] = h1; g_ql[w1] = l1;
                }
            }
        }
    }
}

// ---------------------------------------------------------------------------
// Flash attention: causal, hd=64, k-blocks of 64, fp16 throughout.
// QK^T: Q split 2-term x K hi. PV: P packed in registers (no smem staging),
// V hi via ldmatrix.trans. 3-stage cp.async K/V tiles. 2 CTAs/SM.
// SMEM: K stages 3 x 64x36w | V stages 3 x 64x36w = 55296 B.
// Q staged at start: hi in V0+V1 area, lo in K0+K1 area.
// ---------------------------------------------------------------------------
constexpr int F_LD = 36;                       // words per 64-half row
constexpr int F_TW = 64 * F_LD;                // 2304 words per stage
constexpr int F_VB0 = 3 * F_TW;                // V area word offset (6912)
constexpr int FLASH_SMEM = 6 * F_TW * 4;       // 55296 B

__global__ void __launch_bounds__(256, 2)
flash_kernel()
{
    extern __shared__ uint32_t smw[];
    const uint32_t smb = (uint32_t)__cvta_generic_to_shared(smw);

    const int tid = threadIdx.x, wid = tid >> 5, lid = tid & 31;
    const int g = lid >> 2, tg = lid & 3;
    const int qb = blockIdx.x;                 // 0..15 (128-q blocks)
    const int head = blockIdx.y;               // 0..63

    const uint32_t* Qh = g_qh + (size_t)head * Sc * 32 + (size_t)qb * 128 * 32;
    const uint32_t* Ql = g_ql + (size_t)head * Sc * 32 + (size_t)qb * 128 * 32;
    const uint32_t* Kh = g_kh + (size_t)head * Sc * 32;
    const uint32_t* Vh = g_vh + (size_t)head * Sc * 32;

    // Stage Q: hi -> V area (128 rows x 36w), lo -> K area.
#pragma unroll
    for (int i = 0; i < 4; i++) {
        int idx = tid + i * 256;               // 0..1023
        int r = idx >> 3, c = idx & 7;
        cp16(smw + F_VB0 + r * F_LD + c * 4, Qh + (size_t)r * 32 + c * 4);
        cp16(smw + r * F_LD + c * 4,         Ql + (size_t)r * 32 + c * 4);
    }
    cp_commit();
    cp_wait<0>();
    __syncthreads();

    uint32_t qh[4][4], ql[4][4];
    {
        uint32_t qo = 4u * ((wid * 16 + (lid & 15)) * F_LD + (lid >> 4) * 4);
#pragma unroll
        for (int ks = 0; ks < 4; ks++) {
            ldsm_x4(smb + 4u * F_VB0 + qo + 4u * (ks * 8), qh[ks][0], qh[ks][1], qh[ks][2], qh[ks][3]);
            ldsm_x4(smb + qo + 4u * (ks * 8),              ql[ks][0], ql[ks][1], ql[ks][2], ql[ks][3]);
        }
    }
    __syncthreads();                           // K/V areas now reusable

    auto load_tile = [&](int kb, int s) {
        size_t kbase = (size_t)kb * 64;
#pragma unroll
        for (int i = 0; i < 2; i++) {
            int idx = tid + i * 256;           // 0..511
            int r = idx >> 3, c = idx & 7;
            uint32_t dk = (uint32_t)(s * F_TW + r * F_LD + c * 4);
            cp16(smw + dk,         Kh + (kbase + r) * 32 + c * 4);
            cp16(smw + F_VB0 + dk, Vh + (kbase + r) * 32 + c * 4);
        }
    };

    const int nkb = 2 * qb + 2;                // 64-wide k-blocks
    load_tile(0, 0); cp_commit();
    load_tile(1, 1); cp_commit();

    float o[8][4];
#pragma unroll
    for (int j = 0; j < 8; j++)
#pragma unroll
        for (int e = 0; e < 4; e++) o[j][e] = 0.f;
    float m0 = -1e30f, m1 = -1e30f, l0 = 0.f, l1 = 0.f;

    const float scale = 0.125f;
    const float LOG2E = 1.4426950408889634f;
    const int row0g = qb * 128 + wid * 16 + g;
    const int row1g = row0g + 8;

    const uint32_t k_fb = smb + 4u * ((((lid >> 4) & 1) * 8 + (lid & 7)) * F_LD
                                      + ((lid >> 3) & 1) * 4);
    const uint32_t v_fb = smb + 4u * F_VB0
                        + 4u * ((((lid >> 3) & 1) * 8 + (lid & 7)) * F_LD)
                        + (uint32_t)(lid >> 4) * 16;

    for (int kb = 0; kb < nkb; kb++) {
        cp_wait<1>();
        __syncthreads();
        if (kb + 2 < nkb) load_tile(kb + 2, (kb + 2) % 3);
        cp_commit();

        const uint32_t stb = (uint32_t)((kb % 3) * F_TW * 4);

        // S = Q K^T (16 q-rows x 64 k-cols per warp), fp16 2-term
        float sacc[8][4];
#pragma unroll
        for (int nj = 0; nj < 8; nj++)
#pragma unroll
            for (int e = 0; e < 4; e++) sacc[nj][e] = 0.f;
#pragma unroll
        for (int ks = 0; ks < 4; ks++) {
            uint32_t kd = k_fb + stb + 4u * (ks * 8);
#pragma unroll
            for (int p = 0; p < 4; p++) {
                uint32_t b0[2], b1[2];
                ldsm_x4(kd + 4u * (p * 16 * F_LD), b0[0], b0[1], b1[0], b1[1]);
                mma_f16(sacc[2 * p],     ql[ks], b0, sacc[2 * p]);
                mma_f16(sacc[2 * p],     qh[ks], b0, sacc[2 * p]);
                mma_f16(sacc[2 * p + 1], ql[ks], b1, sacc[2 * p + 1]);
                mma_f16(sacc[2 * p + 1], qh[ks], b1, sacc[2 * p + 1]);
            }
        }

        // scale + causal mask
#pragma unroll
        for (int nj = 0; nj < 8; nj++) {
#pragma unroll
            for (int e = 0; e < 4; e++) {
                int col = kb * 64 + nj * 8 + 2 * tg + (e & 1);
                int row = (e & 2) ? row1g : row0g;
                float v = sacc[nj][e] * scale;
                sacc[nj][e] = (col > row) ? -1e30f : v;
            }
        }

        // online softmax (two row groups per thread)
        float rmax0 = -1e30f, rmax1 = -1e30f;
#pragma unroll
        for (int nj = 0; nj < 8; nj++) {
            rmax0 = fmaxf(rmax0, fmaxf(sacc[nj][0], sacc[nj][1]));
            rmax1 = fmaxf(rmax1, fmaxf(sacc[nj][2], sacc[nj][3]));
        }
        rmax0 = fmaxf(rmax0, __shfl_xor_sync(0xffffffffu, rmax0, 1));
        rmax0 = fmaxf(rmax0, __shfl_xor_sync(0xffffffffu, rmax0, 2));
        rmax1 = fmaxf(rmax1, __shfl_xor_sync(0xffffffffu, rmax1, 1));
        rmax1 = fmaxf(rmax1, __shfl_xor_sync(0xffffffffu, rmax1, 2));

        float nm0 = fmaxf(m0, rmax0), nm1 = fmaxf(m1, rmax1);
        float alpha0 = exp2f((m0 - nm0) * LOG2E);
        float alpha1 = exp2f((m1 - nm1) * LOG2E);

        float rs0 = 0.f, rs1 = 0.f;
#pragma unroll
        for (int nj = 0; nj < 8; nj++) {
            float p0 = exp2f((sacc[nj][0] - nm0) * LOG2E);
            float p1 = exp2f((sacc[nj][1] - nm0) * LOG2E);
            float p2 = exp2f((sacc[nj][2] - nm1) * LOG2E);
            float p3 = exp2f((sacc[nj][3] - nm1) * LOG2E);
            sacc[nj][0] = p0; sacc[nj][1] = p1; sacc[nj][2] = p2; sacc[nj][3] = p3;
            rs0 += p0 + p1; rs1 += p2 + p3;
        }
        rs0 += __shfl_xor_sync(0xffffffffu, rs0, 1);
        rs0 += __shfl_xor_sync(0xffffffffu, rs0, 2);
        rs1 += __shfl_xor_sync(0xffffffffu, rs1, 1);
        rs1 += __shfl_xor_sync(0xffffffffu, rs1, 2);

        m0 = nm0; m1 = nm1;
        l0 = l0 * alpha0 + rs0;
        l1 = l1 * alpha1 + rs1;
#pragma unroll
        for (int j = 0; j < 8; j++) {
            o[j][0] *= alpha0; o[j][1] *= alpha0;
            o[j][2] *= alpha1; o[j][3] *= alpha1;
        }

        // O += P V : P C-frag packs directly into fp16 A-frag (no smem).
#pragma unroll
        for (int ks = 0; ks < 4; ks++) {
            uint32_t pa[4];
            pa[0] = pack_h2(sacc[2 * ks][0],     sacc[2 * ks][1]);
            pa[1] = pack_h2(sacc[2 * ks][2],     sacc[2 * ks][3]);
            pa[2] = pack_h2(sacc[2 * ks + 1][0], sacc[2 * ks + 1][1]);
            pa[3] = pack_h2(sacc[2 * ks + 1][2], sacc[2 * ks + 1][3]);
            uint32_t vd = v_fb + stb + 4u * (ks * 16 * F_LD);
#pragma unroll
            for (int p = 0; p < 4; p++) {
                uint32_t b0[2], b1[2];
                ldsm_x4_t(vd + (uint32_t)p * 32, b0[0], b0[1], b1[0], b1[1]);
                mma_f16(o[2 * p],     pa, b0, o[2 * p]);
                mma_f16(o[2 * p + 1], pa, b1, o[2 * p + 1]);
            }
        }
    }

    // Epilogue: write attn as fp16 hi/lo into g_ah/g_al [8192][512 words]
    {
        int b = head >> 4, h = head & 15;
        int s0 = qb * 128 + wid * 16 + g;
        float inv0 = 1.f / l0, inv1 = 1.f / l1;
        size_t base0 = ((size_t)b * Sc + s0) * 512 + h * 32;
        size_t base1 = ((size_t)b * Sc + s0 + 8) * 512 + h * 32;
#pragma unroll
        for (int nj = 0; nj < 8; nj++) {
            int dw = nj * 4 + tg;
            uint32_t h0, l0w, h1, l1w;
            split_h2(o[nj][0] * inv0, o[nj][1] * inv0, h0, l0w);
            split_h2(o[nj][2] * inv1, o[nj][3] * inv1, h1, l1w);
            g_ah[base0 + dw] = h0; g_al[base0 + dw] = l0w;
            g_ah[base1 + dw] = h1; g_al[base1 + dw] = l1w;
        }
    }
}

// ---------------------------------------------------------------------------
extern "C" void kernel_launch(void* const* d_in, const int* in_sizes, int n_in,
                              void* d_out, int out_size)
{
    (void)in_sizes; (void)n_in; (void)out_size;
    const float* x      = (const float*)d_in[0];
    const float* w_attn = (const float*)d_in[2];
    const float* b_attn = (const float*)d_in[3];
    const float* w_proj = (const float*)d_in[4];
    const float* b_proj = (const float*)d_in[5];
    float* out = (float*)d_out;

    cudaFuncSetAttribute(h_gemm<0>,    cudaFuncAttributeMaxDynamicSharedMemorySize, G_SMEM);
    cudaFuncSetAttribute(h_gemm<1>,    cudaFuncAttributeMaxDynamicSharedMemorySize, G_SMEM);
    cudaFuncSetAttribute(flash_kernel, cudaFuncAttributeMaxDynamicSharedMemorySize, FLASH_SMEM);

    // Pre-pass: split/transpose inputs to fp16
    conv_x<<<(Mc * 512) / 1024, 1024>>>(x);
    conv_wT<<<dim3(16, NQKV / 32), dim3(32, 8)>>>(w_attn, NQKV, 0);
    conv_wT<<<dim3(16, Dc / 32),   dim3(32, 8)>>>(w_proj, Dc, 1);

    // 1) QKV GEMM -> q split, k hi, v hi (head-major)
    h_gemm<0><<<dim3(NQKV / 128, Mc / 128), 256, G_SMEM>>>(b_attn, nullptr);
    // 2) causal flash attention -> attn split
    flash_kernel<<<dim3(Sc / 128, Bc * Hc), 256, FLASH_SMEM>>>();
    // 3) proj GEMM -> out fp32
    h_gemm<1><<<dim3(Dc / 128, Mc / 128), 256, G_SMEM>>>(b_proj, out);
}

// round 8
// speedup vs baseline: 2.7205x; 1.0219x over previous
#include <cuda_runtime.h>
#include <cstdint>

#define DEVINL __device__ __forceinline__

constexpr int Bc = 4, Sc = 2048, Dc = 1024, Hc = 16;
constexpr int Mc = Bc * Sc;           // 8192
constexpr int NQKV = 3 * Dc;          // 3072

// ---------------------------------------------------------------------------
// Scratch (__device__ globals). All fp16 data stored as packed f16x2 words.
// ---------------------------------------------------------------------------
__device__ uint32_t g_xh[(size_t)Mc * 512], g_xl[(size_t)Mc * 512];      // x split [8192][512]
__device__ uint32_t g_wth[(size_t)NQKV * 512];                           // wA^T hi [3072][512]
__device__ uint32_t g_wph[(size_t)Dc * 512];                             // wP^T hi [1024][512]
__device__ uint32_t g_qh[(size_t)64 * Sc * 32], g_ql[(size_t)64 * Sc * 32]; // q split [64][2048][32]
__device__ uint32_t g_kh[(size_t)64 * Sc * 32];                             // k hi
__device__ uint32_t g_vh[(size_t)64 * Sc * 32];                             // v hi
__device__ uint32_t g_ah[(size_t)Mc * 512], g_al[(size_t)Mc * 512];      // attn split [8192][512]

// ---------------------------------------------------------------------------
// Helpers
// ---------------------------------------------------------------------------
DEVINL uint32_t pack_h2(float x0, float x1) {
    uint32_t h;
    asm("cvt.rn.f16x2.f32 %0, %1, %2;" : "=r"(h) : "f"(x1), "f"(x0));
    return h;
}
DEVINL void split_h2(float x0, float x1, uint32_t& h, uint32_t& l) {
    h = pack_h2(x0, x1);
    float b0, b1;
    asm("{\n\t.reg .f16 lo, hi;\n\tmov.b32 {lo, hi}, %2;\n\t"
        "cvt.f32.f16 %0, lo;\n\tcvt.f32.f16 %1, hi;\n\t}"
        : "=f"(b0), "=f"(b1) : "r"(h));
    l = pack_h2(x0 - b0, x1 - b1);
}
DEVINL void mma_f16(float d[4], const uint32_t a[4], const uint32_t b[2], const float c[4]) {
    asm volatile(
        "mma.sync.aligned.m16n8k16.row.col.f32.f16.f16.f32 "
        "{%0,%1,%2,%3}, {%4,%5,%6,%7}, {%8,%9}, {%10,%11,%12,%13};\n"
        : "=f"(d[0]), "=f"(d[1]), "=f"(d[2]), "=f"(d[3])
        : "r"(a[0]), "r"(a[1]), "r"(a[2]), "r"(a[3]),
          "r"(b[0]), "r"(b[1]),
          "f"(c[0]), "f"(c[1]), "f"(c[2]), "f"(c[3]));
}
DEVINL void ldsm_x4(uint32_t addr, uint32_t& r0, uint32_t& r1, uint32_t& r2, uint32_t& r3) {
    asm volatile("ldmatrix.sync.aligned.m8n8.x4.shared.b16 {%0,%1,%2,%3}, [%4];"
                 : "=r"(r0), "=r"(r1), "=r"(r2), "=r"(r3) : "r"(addr));
}
DEVINL void ldsm_x4_t(uint32_t addr, uint32_t& r0, uint32_t& r1, uint32_t& r2, uint32_t& r3) {
    asm volatile("ldmatrix.sync.aligned.m8n8.x4.trans.shared.b16 {%0,%1,%2,%3}, [%4];"
                 : "=r"(r0), "=r"(r1), "=r"(r2), "=r"(r3) : "r"(addr));
}
DEVINL void cp16(void* s, const void* g) {
    uint32_t sa = (uint32_t)__cvta_generic_to_shared(s);
    asm volatile("cp.async.cg.shared.global [%0], [%1], 16;\n" :: "r"(sa), "l"(g));
}
DEVINL void cp_commit() { asm volatile("cp.async.commit_group;\n"); }
template <int N> DEVINL void cp_wait() { asm volatile("cp.async.wait_group %0;\n" :: "n"(N)); }

// ---------------------------------------------------------------------------
// Pre-pass 1: split x (fp32 [8192][1024]) -> g_xh/g_xl (f16x2 words)
// ---------------------------------------------------------------------------
__global__ void conv_x(const float* __restrict__ x)
{
    size_t idx = (size_t)blockIdx.x * 1024 + threadIdx.x;   // 4M words
    float2 v = ((const float2*)x)[idx];
    uint32_t h, l;
    split_h2(v.x, v.y, h, l);
    g_xh[idx] = h; g_xl[idx] = l;
}

// ---------------------------------------------------------------------------
// Pre-pass 2: transpose + round W (fp32 [1024][N]) -> [N][512 words] hi only.
// ---------------------------------------------------------------------------
__global__ void conv_wT(const float* __restrict__ W, int N, int which)
{
    __shared__ float ts[64][33];
    uint32_t* Wh = which ? g_wph : g_wth;
    const int k0 = blockIdx.x * 64, n0 = blockIdx.y * 32;
    const int tx = threadIdx.x, ty = threadIdx.y;
#pragma unroll
    for (int i = 0; i < 8; i++)
        ts[ty + i * 8][tx] = W[(size_t)(k0 + ty + i * 8) * N + n0 + tx];
    __syncthreads();
#pragma unroll
    for (int i = 0; i < 4; i++) {
        int n = ty + i * 8;
        Wh[(size_t)(n0 + n) * 512 + (k0 >> 1) + tx] = pack_h2(ts[2 * tx][n], ts[2 * tx + 1][n]);
    }
}

// ---------------------------------------------------------------------------
// fp16 2-term GEMM: C = A(Mx1024) W^T + bias.  A = (Ah + Al), B = Bh.
// CTA 128x128, BK=32, 3-stage cp.async, 2 CTAs/SM.
// Mainloop: per ks, 2 passes (all al-mmas, then all ah-mmas) -> RAW dist 16.
// ---------------------------------------------------------------------------
constexpr int P_LD = 20;                       // words/row (16 + 4 pad)
constexpr int P_ARR_W = 128 * P_LD;            // 2560 words
constexpr int P_ARR_B = P_ARR_W * 4;           // 10240 B
constexpr int P_STG_W = 3 * P_ARR_W;           // 7680 words
constexpr int P_STG_B = P_STG_W * 4;           // 30720 B
constexpr int G_SMEM = 3 * P_STG_B;            // 92160 B

template <int EPI>
__global__ void __launch_bounds__(256, 2)
h_gemm(const float* __restrict__ bias, float* __restrict__ out)
{
    extern __shared__ uint32_t sw[];
    const uint32_t* Agh = EPI ? g_ah : g_xh;
    const uint32_t* Agl = EPI ? g_al : g_xl;
    const uint32_t* Bgh = EPI ? g_wph : g_wth;

    const int tid = threadIdx.x, wid = tid >> 5, lid = tid & 31;
    const int wm = wid >> 2, wn = wid & 3;
    const int g = lid >> 2, tg = lid & 3;
    const int cm = blockIdx.y * 128, cn = blockIdx.x * 128;
    const uint32_t smb = (uint32_t)__cvta_generic_to_shared(sw);

    const uint32_t a_fb = smb + 4u * ((wm * 64 + (lid & 15)) * P_LD + (lid >> 4) * 4);
    const uint32_t b_fb = smb + 4u * ((wn * 32 + ((lid >> 4) & 1) * 8 + (lid & 7)) * P_LD
                                      + ((lid >> 3) & 1) * 4) + 2u * P_ARR_B;

    const int row = tid >> 1;
    const int ch0 = (tid & 1) * 2;

    auto load_stage = [&](int kt, int s) {
#pragma unroll
        for (int i = 0; i < 2; i++) {
            int c = ch0 + i;
            uint32_t dst = (uint32_t)(s * P_STG_W + row * P_LD + c * 4);
            size_t asrc = (size_t)(cm + row) * 512 + kt * 16 + c * 4;
            size_t bsrc = (size_t)(cn + row) * 512 + kt * 16 + c * 4;
            cp16(sw + dst,               Agh + asrc);
            cp16(sw + dst + P_ARR_W,     Agl + asrc);
            cp16(sw + dst + 2 * P_ARR_W, Bgh + bsrc);
        }
    };

    float acc[4][4][4];
#pragma unroll
    for (int i = 0; i < 4; i++)
#pragma unroll
        for (int j = 0; j < 4; j++)
#pragma unroll
            for (int e = 0; e < 4; e++) acc[i][j][e] = 0.f;

    constexpr int NT = 32;                     // K=1024 / 32
    load_stage(0, 0); cp_commit();
    load_stage(1, 1); cp_commit();

    for (int kt = 0; kt < NT; kt++) {
        cp_wait<1>();
        __syncthreads();
        if (kt + 2 < NT) load_stage(kt + 2, (kt + 2) % 3);
        cp_commit();

        const uint32_t sb = (uint32_t)((kt % 3) * P_STG_B);
#pragma unroll
        for (int ks = 0; ks < 2; ks++) {
            uint32_t ah[4][4], al[4][4], b[4][2];
#pragma unroll
            for (int mi = 0; mi < 4; mi++) {
                uint32_t ad = a_fb + sb + 4u * (mi * 16 * P_LD + ks * 8);
                ldsm_x4(ad,           ah[mi][0], ah[mi][1], ah[mi][2], ah[mi][3]);
                ldsm_x4(ad + P_ARR_B, al[mi][0], al[mi][1], al[mi][2], al[mi][3]);
            }
#pragma unroll
            for (int p = 0; p < 2; p++)
                ldsm_x4(b_fb + sb + 4u * (p * 16 * P_LD + ks * 8),
                        b[2 * p][0], b[2 * p][1], b[2 * p + 1][0], b[2 * p + 1][1]);
            // pass 1: all al terms (independent accumulators)
#pragma unroll
            for (int mi = 0; mi < 4; mi++)
#pragma unroll
                for (int nj = 0; nj < 4; nj++)
                    mma_f16(acc[mi][nj], al[mi], b[nj], acc[mi][nj]);
            // pass 2: all ah terms
#pragma unroll
            for (int mi = 0; mi < 4; mi++)
#pragma unroll
                for (int nj = 0; nj < 4; nj++)
                    mma_f16(acc[mi][nj], ah[mi], b[nj], acc[mi][nj]);
        }
    }

    // Epilogue
#pragma unroll
    for (int mi = 0; mi < 4; mi++) {
#pragma unroll
        for (int nj = 0; nj < 4; nj++) {
            int col0 = cn + wn * 32 + nj * 8 + 2 * tg;       // even
            float2 v0 = make_float2(acc[mi][nj][0] + bias[col0],
                                    acc[mi][nj][1] + bias[col0 + 1]);
            float2 v1 = make_float2(acc[mi][nj][2] + bias[col0],
                                    acc[mi][nj][3] + bias[col0 + 1]);
            int row0 = cm + wm * 64 + mi * 16 + g;
            int row1 = row0 + 8;
            if (EPI == 1) {
                *(float2*)&out[(size_t)row0 * 1024 + col0] = v0;
                *(float2*)&out[(size_t)row1 * 1024 + col0] = v1;
            } else {
                int t = col0 >> 10;                // 0:q 1:k 2:v
                int r1 = col0 & 1023;
                int h = r1 >> 6, d = r1 & 63;      // d even
                int b0 = row0 >> 11, s0 = row0 & 2047;
                int b1 = row1 >> 11, s1 = row1 & 2047;
                size_t w0 = ((size_t)(b0 * Hc + h) * Sc + s0) * 32 + (d >> 1);
                size_t w1 = ((size_t)(b1 * Hc + h) * Sc + s1) * 32 + (d >> 1);
                if (t == 2) {
                    g_vh[w0] = pack_h2(v0.x, v0.y);
                    g_vh[w1] = pack_h2(v1.x, v1.y);
                } else if (t == 1) {
                    g_kh[w0] = pack_h2(v0.x, v0.y);
                    g_kh[w1] = pack_h2(v1.x, v1.y);
                } else {
                    uint32_t h0, l0, h1, l1;
                    split_h2(v0.x, v0.y, h0, l0);
                    split_h2(v1.x, v1.y, h1, l1);
                    g_qh[w0] = h0; g_ql[w0] = l0;
                    g_qh[w1] = h1; g_ql[w1] = l1;
                }
            }
        }
    }
}

// ---------------------------------------------------------------------------
// Flash attention: causal, hd=64, k-blocks of 64, fp16 throughout.
// QK^T: ql pass then qh pass (RAW dist 4, grouped by 2 p-steps).
// Heaviest q-blocks launch first (qb = 15 - blockIdx.x).
// ---------------------------------------------------------------------------
constexpr int F_LD = 36;                       // words per 64-half row
constexpr int F_TW = 64 * F_LD;                // 2304 words per stage
constexpr int F_VB0 = 3 * F_TW;                // V area word offset
constexpr int FLASH_SMEM = 6 * F_TW * 4;       // 55296 B

__global__ void __launch_bounds__(256, 2)
flash_kernel()
{
    extern __shared__ uint32_t smw[];
    const uint32_t smb = (uint32_t)__cvta_generic_to_shared(smw);

    const int tid = threadIdx.x, wid = tid >> 5, lid = tid & 31;
    const int g = lid >> 2, tg = lid & 3;
    const int qb = (int)gridDim.x - 1 - (int)blockIdx.x;   // heavy blocks first
    const int head = blockIdx.y;

    const uint32_t* Qh = g_qh + (size_t)head * Sc * 32 + (size_t)qb * 128 * 32;
    const uint32_t* Ql = g_ql + (size_t)head * Sc * 32 + (size_t)qb * 128 * 32;
    const uint32_t* Kh = g_kh + (size_t)head * Sc * 32;
    const uint32_t* Vh = g_vh + (size_t)head * Sc * 32;

    // Stage Q: hi -> V area (128 rows x 36w), lo -> K area.
#pragma unroll
    for (int i = 0; i < 4; i++) {
        int idx = tid + i * 256;
        int r = idx >> 3, c = idx & 7;
        cp16(smw + F_VB0 + r * F_LD + c * 4, Qh + (size_t)r * 32 + c * 4);
        cp16(smw + r * F_LD + c * 4,         Ql + (size_t)r * 32 + c * 4);
    }
    cp_commit();
    cp_wait<0>();
    __syncthreads();

    uint32_t qh[4][4], ql[4][4];
    {
        uint32_t qo = 4u * ((wid * 16 + (lid & 15)) * F_LD + (lid >> 4) * 4);
#pragma unroll
        for (int ks = 0; ks < 4; ks++) {
            ldsm_x4(smb + 4u * F_VB0 + qo + 4u * (ks * 8), qh[ks][0], qh[ks][1], qh[ks][2], qh[ks][3]);
            ldsm_x4(smb + qo + 4u * (ks * 8),              ql[ks][0], ql[ks][1], ql[ks][2], ql[ks][3]);
        }
    }
    __syncthreads();                           // K/V areas now reusable

    auto load_tile = [&](int kb, int s) {
        size_t kbase = (size_t)kb * 64;
#pragma unroll
        for (int i = 0; i < 2; i++) {
            int idx = tid + i * 256;
            int r = idx >> 3, c = idx & 7;
            uint32_t dk = (uint32_t)(s * F_TW + r * F_LD + c * 4);
            cp16(smw + dk,         Kh + (kbase + r) * 32 + c * 4);
            cp16(smw + F_VB0 + dk, Vh + (kbase + r) * 32 + c * 4);
        }
    };

    const int nkb = 2 * qb + 2;                // 64-wide k-blocks
    load_tile(0, 0); cp_commit();
    load_tile(1, 1); cp_commit();

    float o[8][4];
#pragma unroll
    for (int j = 0; j < 8; j++)
#pragma unroll
        for (int e = 0; e < 4; e++) o[j][e] = 0.f;
    float m0 = -1e30f, m1 = -1e30f, l0 = 0.f, l1 = 0.f;

    const float scale = 0.125f;
    const float LOG2E = 1.4426950408889634f;
    const int row0g = qb * 128 + wid * 16 + g;
    const int row1g = row0g + 8;

    const uint32_t k_fb = smb + 4u * ((((lid >> 4) & 1) * 8 + (lid & 7)) * F_LD
                                      + ((lid >> 3) & 1) * 4);
    const uint32_t v_fb = smb + 4u * F_VB0
                        + 4u * ((((lid >> 3) & 1) * 8 + (lid & 7)) * F_LD)
                        + (uint32_t)(lid >> 4) * 16;

    for (int kb = 0; kb < nkb; kb++) {
        cp_wait<1>();
        __syncthreads();
        if (kb + 2 < nkb) load_tile(kb + 2, (kb + 2) % 3);
        cp_commit();

        const uint32_t stb = (uint32_t)((kb % 3) * F_TW * 4);

        // S = Q K^T (16 q-rows x 64 k-cols per warp), fp16 2-term,
        // grouped by 2 p-steps: ql pass (4 mmas) then qh pass (4 mmas).
        float sacc[8][4];
#pragma unroll
        for (int nj = 0; nj < 8; nj++)
#pragma unroll
            for (int e = 0; e < 4; e++) sacc[nj][e] = 0.f;
#pragma unroll
        for (int ks = 0; ks < 4; ks++) {
            uint32_t kd = k_fb + stb + 4u * (ks * 8);
#pragma unroll
            for (int pg = 0; pg < 2; pg++) {
                uint32_t b[4][2];
#pragma unroll
                for (int p = 0; p < 2; p++)
                    ldsm_x4(kd + 4u * ((pg * 2 + p) * 16 * F_LD),
                            b[2 * p][0], b[2 * p][1], b[2 * p + 1][0], b[2 * p + 1][1]);
#pragma unroll
                for (int j = 0; j < 4; j++)
                    mma_f16(sacc[pg * 4 + j], ql[ks], b[j], sacc[pg * 4 + j]);
#pragma unroll
                for (int j = 0; j < 4; j++)
                    mma_f16(sacc[pg * 4 + j], qh[ks], b[j], sacc[pg * 4 + j]);
            }
        }

        // scale + causal mask
#pragma unroll
        for (int nj = 0; nj < 8; nj++) {
#pragma unroll
            for (int e = 0; e < 4; e++) {
                int col = kb * 64 + nj * 8 + 2 * tg + (e & 1);
                int row = (e & 2) ? row1g : row0g;
                float v = sacc[nj][e] * scale;
                sacc[nj][e] = (col > row) ? -1e30f : v;
            }
        }

        // online softmax
        float rmax0 = -1e30f, rmax1 = -1e30f;
#pragma unroll
        for (int nj = 0; nj < 8; nj++) {
            rmax0 = fmaxf(rmax0, fmaxf(sacc[nj][0], sacc[nj][1]));
            rmax1 = fmaxf(rmax1, fmaxf(sacc[nj][2], sacc[nj][3]));
        }
        rmax0 = fmaxf(rmax0, __shfl_xor_sync(0xffffffffu, rmax0, 1));
        rmax0 = fmaxf(rmax0, __shfl_xor_sync(0xffffffffu, rmax0, 2));
        rmax1 = fmaxf(rmax1, __shfl_xor_sync(0xffffffffu, rmax1, 1));
        rmax1 = fmaxf(rmax1, __shfl_xor_sync(0xffffffffu, rmax1, 2));

        float nm0 = fmaxf(m0, rmax0), nm1 = fmaxf(m1, rmax1);
        float alpha0 = exp2f((m0 - nm0) * LOG2E);
        float alpha1 = exp2f((m1 - nm1) * LOG2E);

        float rs0 = 0.f, rs1 = 0.f;
#pragma unroll
        for (int nj = 0; nj < 8; nj++) {
            float p0 = exp2f((sacc[nj][0] - nm0) * LOG2E);
            float p1 = exp2f((sacc[nj][1] - nm0) * LOG2E);
            float p2 = exp2f((sacc[nj][2] - nm1) * LOG2E);
            float p3 = exp2f((sacc[nj][3] - nm1) * LOG2E);
            sacc[nj][0] = p0; sacc[nj][1] = p1; sacc[nj][2] = p2; sacc[nj][3] = p3;
            rs0 += p0 + p1; rs1 += p2 + p3;
        }
        rs0 += __shfl_xor_sync(0xffffffffu, rs0, 1);
        rs0 += __shfl_xor_sync(0xffffffffu, rs0, 2);
        rs1 += __shfl_xor_sync(0xffffffffu, rs1, 1);
        rs1 += __shfl_xor_sync(0xffffffffu, rs1, 2);

        m0 = nm0; m1 = nm1;
        l0 = l0 * alpha0 + rs0;
        l1 = l1 * alpha1 + rs1;
#pragma unroll
        for (int j = 0; j < 8; j++) {
            o[j][0] *= alpha0; o[j][1] *= alpha0;
            o[j][2] *= alpha1; o[j][3] *= alpha1;
        }

        // O += P V : P C-frag packs directly into fp16 A-frag (no smem).
#pragma unroll
        for (int ks = 0; ks < 4; ks++) {
            uint32_t pa[4];
            pa[0] = pack_h2(sacc[2 * ks][0],     sacc[2 * ks][1]);
            pa[1] = pack_h2(sacc[2 * ks][2],     sacc[2 * ks][3]);
            pa[2] = pack_h2(sacc[2 * ks + 1][0], sacc[2 * ks + 1][1]);
            pa[3] = pack_h2(sacc[2 * ks + 1][2], sacc[2 * ks + 1][3]);
            uint32_t vd = v_fb + stb + 4u * (ks * 16 * F_LD);
#pragma unroll
            for (int p = 0; p < 4; p++) {
                uint32_t b0[2], b1[2];
                ldsm_x4_t(vd + (uint32_t)p * 32, b0[0], b0[1], b1[0], b1[1]);
                mma_f16(o[2 * p],     pa, b0, o[2 * p]);
                mma_f16(o[2 * p + 1], pa, b1, o[2 * p + 1]);
            }
        }
    }

    // Epilogue: write attn as fp16 hi/lo into g_ah/g_al [8192][512 words]
    {
        int b = head >> 4, h = head & 15;
        int s0 = qb * 128 + wid * 16 + g;
        float inv0 = 1.f / l0, inv1 = 1.f / l1;
        size_t base0 = ((size_t)b * Sc + s0) * 512 + h * 32;
        size_t base1 = ((size_t)b * Sc + s0 + 8) * 512 + h * 32;
#pragma unroll
        for (int nj = 0; nj < 8; nj++) {
            int dw = nj * 4 + tg;
            uint32_t h0, l0w, h1, l1w;
            split_h2(o[nj][0] * inv0, o[nj][1] * inv0, h0, l0w);
            split_h2(o[nj][2] * inv1, o[nj][3] * inv1, h1, l1w);
            g_ah[base0 + dw] = h0; g_al[base0 + dw] = l0w;
            g_ah[base1 + dw] = h1; g_al[base1 + dw] = l1w;
        }
    }
}

// ---------------------------------------------------------------------------
extern "C" void kernel_launch(void* const* d_in, const int* in_sizes, int n_in,
                              void* d_out, int out_size)
{
    (void)in_sizes; (void)n_in; (void)out_size;
    const float* x      = (const float*)d_in[0];
    const float* w_attn = (const float*)d_in[2];
    const float* b_attn = (const float*)d_in[3];
    const float* w_proj = (const float*)d_in[4];
    const float* b_proj = (const float*)d_in[5];
    float* out = (float*)d_out;

    cudaFuncSetAttribute(h_gemm<0>,    cudaFuncAttributeMaxDynamicSharedMemorySize, G_SMEM);
    cudaFuncSetAttribute(h_gemm<1>,    cudaFuncAttributeMaxDynamicSharedMemorySize, G_SMEM);
    cudaFuncSetAttribute(flash_kernel, cudaFuncAttributeMaxDynamicSharedMemorySize, FLASH_SMEM);

    // Pre-pass: split/transpose inputs to fp16
    conv_x<<<(Mc * 512) / 1024, 1024>>>(x);
    conv_wT<<<dim3(16, NQKV / 32), dim3(32, 8)>>>(w_attn, NQKV, 0);
    conv_wT<<<dim3(16, Dc / 32),   dim3(32, 8)>>>(w_proj, Dc, 1);

    // 1) QKV GEMM -> q split, k hi, v hi (head-major)
    h_gemm<0><<<dim3(NQKV / 128, Mc / 128), 256, G_SMEM>>>(b_attn, nullptr);
    // 2) causal flash attention -> attn split
    flash_kernel<<<dim3(Sc / 128, Bc * Hc), 256, FLASH_SMEM>>>();
    // 3) proj GEMM -> out fp32
    h_gemm<1><<<dim3(Dc / 128, Mc / 128), 256, G_SMEM>>>(b_proj, out);
}

// round 9
// speedup vs baseline: 3.3690x; 1.2384x over previous
#include <cuda_runtime.h>
#include <cstdint>

#define DEVINL __device__ __forceinline__

constexpr int Bc = 4, Sc = 2048, Dc = 1024, Hc = 16;
constexpr int Mc = Bc * Sc;           // 8192
constexpr int NQKV = 3 * Dc;          // 3072

// ---------------------------------------------------------------------------
// Scratch (__device__ globals). All fp16 data stored as packed f16x2 words.
// ---------------------------------------------------------------------------
__device__ uint32_t g_xh[(size_t)Mc * 512], g_xl[(size_t)Mc * 512];      // x split [8192][512]
__device__ uint32_t g_wth[(size_t)NQKV * 512];                           // wA^T hi [3072][512]
__device__ uint32_t g_wph[(size_t)Dc * 512];                             // wP^T hi [1024][512]
__device__ uint32_t g_qh[(size_t)64 * Sc * 32];                          // q hi [64][2048][32]
__device__ uint32_t g_kh[(size_t)64 * Sc * 32];                          // k hi
__device__ uint32_t g_vh[(size_t)64 * Sc * 32];                          // v hi
__device__ uint32_t g_ah[(size_t)Mc * 512], g_al[(size_t)Mc * 512];      // attn split [8192][512]

// ---------------------------------------------------------------------------
// Helpers
// ---------------------------------------------------------------------------
DEVINL uint32_t pack_h2(float x0, float x1) {
    uint32_t h;
    asm("cvt.rn.f16x2.f32 %0, %1, %2;" : "=r"(h) : "f"(x1), "f"(x0));
    return h;
}
DEVINL void unpack_h2(uint32_t h, float& x0, float& x1) {
    asm("{\n\t.reg .f16 lo, hi;\n\tmov.b32 {lo, hi}, %2;\n\t"
        "cvt.f32.f16 %0, lo;\n\tcvt.f32.f16 %1, hi;\n\t}"
        : "=f"(x0), "=f"(x1) : "r"(h));
}
DEVINL void split_h2(float x0, float x1, uint32_t& h, uint32_t& l) {
    h = pack_h2(x0, x1);
    float b0, b1;
    unpack_h2(h, b0, b1);
    l = pack_h2(x0 - b0, x1 - b1);
}
DEVINL uint32_t ex2_h2(float d0, float d1) {
    uint32_t din = pack_h2(d0, d1);
    uint32_t r;
    asm("ex2.approx.f16x2 %0, %1;" : "=r"(r) : "r"(din));
    return r;
}
DEVINL void mma_f16(float d[4], const uint32_t a[4], const uint32_t b[2], const float c[4]) {
    asm volatile(
        "mma.sync.aligned.m16n8k16.row.col.f32.f16.f16.f32 "
        "{%0,%1,%2,%3}, {%4,%5,%6,%7}, {%8,%9}, {%10,%11,%12,%13};\n"
        : "=f"(d[0]), "=f"(d[1]), "=f"(d[2]), "=f"(d[3])
        : "r"(a[0]), "r"(a[1]), "r"(a[2]), "r"(a[3]),
          "r"(b[0]), "r"(b[1]),
          "f"(c[0]), "f"(c[1]), "f"(c[2]), "f"(c[3]));
}
DEVINL void ldsm_x4(uint32_t addr, uint32_t& r0, uint32_t& r1, uint32_t& r2, uint32_t& r3) {
    asm volatile("ldmatrix.sync.aligned.m8n8.x4.shared.b16 {%0,%1,%2,%3}, [%4];"
                 : "=r"(r0), "=r"(r1), "=r"(r2), "=r"(r3) : "r"(addr));
}
DEVINL void ldsm_x4_t(uint32_t addr, uint32_t& r0, uint32_t& r1, uint32_t& r2, uint32_t& r3) {
    asm volatile("ldmatrix.sync.aligned.m8n8.x4.trans.shared.b16 {%0,%1,%2,%3}, [%4];"
                 : "=r"(r0), "=r"(r1), "=r"(r2), "=r"(r3) : "r"(addr));
}
DEVINL void cp16(void* s, const void* g) {
    uint32_t sa = (uint32_t)__cvta_generic_to_shared(s);
    asm volatile("cp.async.cg.shared.global [%0], [%1], 16;\n" :: "r"(sa), "l"(g));
}
DEVINL void cp_commit() { asm volatile("cp.async.commit_group;\n"); }
template <int N> DEVINL void cp_wait() { asm volatile("cp.async.wait_group %0;\n" :: "n"(N)); }

// ---------------------------------------------------------------------------
// Pre-pass 1: split x (fp32 [8192][1024]) -> g_xh/g_xl (f16x2 words)
// ---------------------------------------------------------------------------
__global__ void conv_x(const float* __restrict__ x)
{
    size_t idx = (size_t)blockIdx.x * 1024 + threadIdx.x;   // 4M words
    float2 v = ((const float2*)x)[idx];
    uint32_t h, l;
    split_h2(v.x, v.y, h, l);
    g_xh[idx] = h; g_xl[idx] = l;
}

// ---------------------------------------------------------------------------
// Pre-pass 2: transpose + round W (fp32 [1024][N]) -> [N][512 words] hi only.
// ---------------------------------------------------------------------------
__global__ void conv_wT(const float* __restrict__ W, int N, int which)
{
    __shared__ float ts[64][33];
    uint32_t* Wh = which ? g_wph : g_wth;
    const int k0 = blockIdx.x * 64, n0 = blockIdx.y * 32;
    const int tx = threadIdx.x, ty = threadIdx.y;
#pragma unroll
    for (int i = 0; i < 8; i++)
        ts[ty + i * 8][tx] = W[(size_t)(k0 + ty + i * 8) * N + n0 + tx];
    __syncthreads();
#pragma unroll
    for (int i = 0; i < 4; i++) {
        int n = ty + i * 8;
        Wh[(size_t)(n0 + n) * 512 + (k0 >> 1) + tx] = pack_h2(ts[2 * tx][n], ts[2 * tx + 1][n]);
    }
}

// ---------------------------------------------------------------------------
// fp16 GEMM: C = A(Mx1024) W^T + bias.
// CTA 128x128, BK=32, 3-stage cp.async, 2 CTAs/SM.
// A-side 2-term (Ah+Al) for: proj GEMM (EPI=1) and QKV q-columns (cn<1024).
// A-side 1-term for QKV k/v columns (cn>=1024) -- skips Al cp + Al mma pass.
// ---------------------------------------------------------------------------
constexpr int P_LD = 20;                       // words/row (16 + 4 pad)
constexpr int P_ARR_W = 128 * P_LD;            // 2560 words
constexpr int P_ARR_B = P_ARR_W * 4;           // 10240 B
constexpr int P_STG_W = 3 * P_ARR_W;           // 7680 words
constexpr int P_STG_B = P_STG_W * 4;           // 30720 B
constexpr int G_SMEM = 3 * P_STG_B;            // 92160 B

template <int EPI>
__global__ void __launch_bounds__(256, 2)
h_gemm(const float* __restrict__ bias, float* __restrict__ out)
{
    extern __shared__ uint32_t sw[];
    const uint32_t* Agh = EPI ? g_ah : g_xh;
    const uint32_t* Agl = EPI ? g_al : g_xl;
    const uint32_t* Bgh = EPI ? g_wph : g_wth;

    const int tid = threadIdx.x, wid = tid >> 5, lid = tid & 31;
    const int wm = wid >> 2, wn = wid & 3;
    const int g = lid >> 2, tg = lid & 3;
    const int cm = blockIdx.y * 128, cn = blockIdx.x * 128;
    const bool two_term = (EPI == 1) || (cn < 1024);
    const uint32_t smb = (uint32_t)__cvta_generic_to_shared(sw);

    const uint32_t a_fb = smb + 4u * ((wm * 64 + (lid & 15)) * P_LD + (lid >> 4) * 4);
    const uint32_t b_fb = smb + 4u * ((wn * 32 + ((lid >> 4) & 1) * 8 + (lid & 7)) * P_LD
                                      + ((lid >> 3) & 1) * 4) + 2u * P_ARR_B;

    const int row = tid >> 1;
    const int ch0 = (tid & 1) * 2;

    auto load_stage = [&](int kt, int s) {
#pragma unroll
        for (int i = 0; i < 2; i++) {
            int c = ch0 + i;
            uint32_t dst = (uint32_t)(s * P_STG_W + row * P_LD + c * 4);
            size_t asrc = (size_t)(cm + row) * 512 + kt * 16 + c * 4;
            size_t bsrc = (size_t)(cn + row) * 512 + kt * 16 + c * 4;
            cp16(sw + dst,               Agh + asrc);
            if (two_term) cp16(sw + dst + P_ARR_W, Agl + asrc);
            cp16(sw + dst + 2 * P_ARR_W, Bgh + bsrc);
        }
    };

    float acc[4][4][4];
#pragma unroll
    for (int i = 0; i < 4; i++)
#pragma unroll
        for (int j = 0; j < 4; j++)
#pragma unroll
            for (int e = 0; e < 4; e++) acc[i][j][e] = 0.f;

    constexpr int NT = 32;                     // K=1024 / 32
    load_stage(0, 0); cp_commit();
    load_stage(1, 1); cp_commit();

    for (int kt = 0; kt < NT; kt++) {
        cp_wait<1>();
        __syncthreads();
        if (kt + 2 < NT) load_stage(kt + 2, (kt + 2) % 3);
        cp_commit();

        const uint32_t sb = (uint32_t)((kt % 3) * P_STG_B);
#pragma unroll
        for (int ks = 0; ks < 2; ks++) {
            uint32_t ah[4][4], b[4][2];
#pragma unroll
            for (int mi = 0; mi < 4; mi++) {
                uint32_t ad = a_fb + sb + 4u * (mi * 16 * P_LD + ks * 8);
                ldsm_x4(ad, ah[mi][0], ah[mi][1], ah[mi][2], ah[mi][3]);
            }
#pragma unroll
            for (int p = 0; p < 2; p++)
                ldsm_x4(b_fb + sb + 4u * (p * 16 * P_LD + ks * 8),
                        b[2 * p][0], b[2 * p][1], b[2 * p + 1][0], b[2 * p + 1][1]);
            if (two_term) {
                uint32_t al[4][4];
#pragma unroll
                for (int mi = 0; mi < 4; mi++) {
                    uint32_t ad = a_fb + sb + 4u * (mi * 16 * P_LD + ks * 8);
                    ldsm_x4(ad + P_ARR_B, al[mi][0], al[mi][1], al[mi][2], al[mi][3]);
                }
#pragma unroll
                for (int mi = 0; mi < 4; mi++)
#pragma unroll
                    for (int nj = 0; nj < 4; nj++)
                        mma_f16(acc[mi][nj], al[mi], b[nj], acc[mi][nj]);
            }
#pragma unroll
            for (int mi = 0; mi < 4; mi++)
#pragma unroll
                for (int nj = 0; nj < 4; nj++)
                    mma_f16(acc[mi][nj], ah[mi], b[nj], acc[mi][nj]);
        }
    }

    // Epilogue
#pragma unroll
    for (int mi = 0; mi < 4; mi++) {
#pragma unroll
        for (int nj = 0; nj < 4; nj++) {
            int col0 = cn + wn * 32 + nj * 8 + 2 * tg;       // even
            float2 v0 = make_float2(acc[mi][nj][0] + bias[col0],
                                    acc[mi][nj][1] + bias[col0 + 1]);
            float2 v1 = make_float2(acc[mi][nj][2] + bias[col0],
                                    acc[mi][nj][3] + bias[col0 + 1]);
            int row0 = cm + wm * 64 + mi * 16 + g;
            int row1 = row0 + 8;
            if (EPI == 1) {
                *(float2*)&out[(size_t)row0 * 1024 + col0] = v0;
                *(float2*)&out[(size_t)row1 * 1024 + col0] = v1;
            } else {
                int t = col0 >> 10;                // 0:q 1:k 2:v
                int r1 = col0 & 1023;
                int h = r1 >> 6, d = r1 & 63;      // d even
                int b0 = row0 >> 11, s0 = row0 & 2047;
                int b1 = row1 >> 11, s1 = row1 & 2047;
                size_t w0 = ((size_t)(b0 * Hc + h) * Sc + s0) * 32 + (d >> 1);
                size_t w1 = ((size_t)(b1 * Hc + h) * Sc + s1) * 32 + (d >> 1);
                uint32_t* dst = (t == 0) ? g_qh : (t == 1) ? g_kh : g_vh;
                dst[w0] = pack_h2(v0.x, v0.y);
                dst[w1] = pack_h2(v1.x, v1.y);
            }
        }
    }
}

// ---------------------------------------------------------------------------
// Flash attention: causal, hd=64, k-blocks of 64, fp16 1-term QK^T.
// Softmax: ex2.approx.f16x2 -> results are directly the packed P fragments.
// 3-stage cp.async K/V tiles. 2 CTAs/SM. Heaviest q-blocks launch first.
// ---------------------------------------------------------------------------
constexpr int F_LD = 36;                       // words per 64-half row
constexpr int F_TW = 64 * F_LD;                // 2304 words per stage
constexpr int F_VB0 = 3 * F_TW;                // V area word offset
constexpr int FLASH_SMEM = 6 * F_TW * 4;       // 55296 B

__global__ void __launch_bounds__(256, 2)
flash_kernel()
{
    extern __shared__ uint32_t smw[];
    const uint32_t smb = (uint32_t)__cvta_generic_to_shared(smw);

    const int tid = threadIdx.x, wid = tid >> 5, lid = tid & 31;
    const int g = lid >> 2, tg = lid & 3;
    const int qb = (int)gridDim.x - 1 - (int)blockIdx.x;   // heavy blocks first
    const int head = blockIdx.y;

    const uint32_t* Qh = g_qh + (size_t)head * Sc * 32 + (size_t)qb * 128 * 32;
    const uint32_t* Kh = g_kh + (size_t)head * Sc * 32;
    const uint32_t* Vh = g_vh + (size_t)head * Sc * 32;

    // Stage Q hi -> V area (128 rows x 36w stride).
#pragma unroll
    for (int i = 0; i < 4; i++) {
        int idx = tid + i * 256;
        int r = idx >> 3, c = idx & 7;
        cp16(smw + F_VB0 + r * F_LD + c * 4, Qh + (size_t)r * 32 + c * 4);
    }
    cp_commit();
    cp_wait<0>();
    __syncthreads();

    uint32_t qh[4][4];
    {
        uint32_t qo = smb + 4u * F_VB0
                    + 4u * ((wid * 16 + (lid & 15)) * F_LD + (lid >> 4) * 4);
#pragma unroll
        for (int ks = 0; ks < 4; ks++)
            ldsm_x4(qo + 4u * (ks * 8), qh[ks][0], qh[ks][1], qh[ks][2], qh[ks][3]);
    }
    __syncthreads();                           // K/V areas now reusable

    auto load_tile = [&](int kb, int s) {
        size_t kbase = (size_t)kb * 64;
#pragma unroll
        for (int i = 0; i < 2; i++) {
            int idx = tid + i * 256;
            int r = idx >> 3, c = idx & 7;
            uint32_t dk = (uint32_t)(s * F_TW + r * F_LD + c * 4);
            cp16(smw + dk,         Kh + (kbase + r) * 32 + c * 4);
            cp16(smw + F_VB0 + dk, Vh + (kbase + r) * 32 + c * 4);
        }
    };

    const int nkb = 2 * qb + 2;                // 64-wide k-blocks
    load_tile(0, 0); cp_commit();
    load_tile(1, 1); cp_commit();

    float o[8][4];
#pragma unroll
    for (int j = 0; j < 8; j++)
#pragma unroll
        for (int e = 0; e < 4; e++) o[j][e] = 0.f;
    float m0 = -1e30f, m1 = -1e30f, l0 = 0.f, l1 = 0.f;

    const float scale = 0.125f;
    const float LOG2E = 1.4426950408889634f;
    const int row0g = qb * 128 + wid * 16 + g;
    const int row1g = row0g + 8;

    const uint32_t k_fb = smb + 4u * ((((lid >> 4) & 1) * 8 + (lid & 7)) * F_LD
                                      + ((lid >> 3) & 1) * 4);
    const uint32_t v_fb = smb + 4u * F_VB0
                        + 4u * ((((lid >> 3) & 1) * 8 + (lid & 7)) * F_LD)
                        + (uint32_t)(lid >> 4) * 16;

    for (int kb = 0; kb < nkb; kb++) {
        cp_wait<1>();
        __syncthreads();
        if (kb + 2 < nkb) load_tile(kb + 2, (kb + 2) % 3);
        cp_commit();

        const uint32_t stb = (uint32_t)((kb % 3) * F_TW * 4);

        // S = Q K^T (16 q-rows x 64 k-cols per warp), fp16 1-term
        float sacc[8][4];
#pragma unroll
        for (int nj = 0; nj < 8; nj++)
#pragma unroll
            for (int e = 0; e < 4; e++) sacc[nj][e] = 0.f;
#pragma unroll
        for (int ks = 0; ks < 4; ks++) {
            uint32_t kd = k_fb + stb + 4u * (ks * 8);
#pragma unroll
            for (int p = 0; p < 2; p++) {
                uint32_t b0[2], b1[2];
                ldsm_x4(kd + 4u * (2 * p * 16 * F_LD), b0[0], b0[1], b1[0], b1[1]);
                mma_f16(sacc[4 * p],     qh[ks], b0, sacc[4 * p]);
                mma_f16(sacc[4 * p + 1], qh[ks], b1, sacc[4 * p + 1]);
                uint32_t c0[2], c1[2];
                ldsm_x4(kd + 4u * ((2 * p + 1) * 16 * F_LD), c0[0], c0[1], c1[0], c1[1]);
                mma_f16(sacc[4 * p + 2], qh[ks], c0, sacc[4 * p + 2]);
                mma_f16(sacc[4 * p + 3], qh[ks], c1, sacc[4 * p + 3]);
            }
        }

        // scale + causal mask
#pragma unroll
        for (int nj = 0; nj < 8; nj++) {
#pragma unroll
            for (int e = 0; e < 4; e++) {
                int col = kb * 64 + nj * 8 + 2 * tg + (e & 1);
                int row = (e & 2) ? row1g : row0g;
                float v = sacc[nj][e] * scale;
                sacc[nj][e] = (col > row) ? -1e30f : v;
            }
        }

        // online softmax
        float rmax0 = -1e30f, rmax1 = -1e30f;
#pragma unroll
        for (int nj = 0; nj < 8; nj++) {
            rmax0 = fmaxf(rmax0, fmaxf(sacc[nj][0], sacc[nj][1]));
            rmax1 = fmaxf(rmax1, fmaxf(sacc[nj][2], sacc[nj][3]));
        }
        rmax0 = fmaxf(rmax0, __shfl_xor_sync(0xffffffffu, rmax0, 1));
        rmax0 = fmaxf(rmax0, __shfl_xor_sync(0xffffffffu, rmax0, 2));
        rmax1 = fmaxf(rmax1, __shfl_xor_sync(0xffffffffu, rmax1, 1));
        rmax1 = fmaxf(rmax1, __shfl_xor_sync(0xffffffffu, rmax1, 2));

        float nm0 = fmaxf(m0, rmax0), nm1 = fmaxf(m1, rmax1);
        float alpha0 = exp2f((m0 - nm0) * LOG2E);
        float alpha1 = exp2f((m1 - nm1) * LOG2E);
        float c0 = nm0 * LOG2E, c1 = nm1 * LOG2E;

        // exponentials in fp16x2: result IS the packed P fragment word
        uint32_t pp[8], pq[8];
        float rs0 = 0.f, rs1 = 0.f;
#pragma unroll
        for (int nj = 0; nj < 8; nj++) {
            pp[nj] = ex2_h2(fmaf(sacc[nj][0], LOG2E, -c0), fmaf(sacc[nj][1], LOG2E, -c0));
            pq[nj] = ex2_h2(fmaf(sacc[nj][2], LOG2E, -c1), fmaf(sacc[nj][3], LOG2E, -c1));
            float u0, u1;
            unpack_h2(pp[nj], u0, u1); rs0 += u0 + u1;
            unpack_h2(pq[nj], u0, u1); rs1 += u0 + u1;
        }
        rs0 += __shfl_xor_sync(0xffffffffu, rs0, 1);
        rs0 += __shfl_xor_sync(0xffffffffu, rs0, 2);
        rs1 += __shfl_xor_sync(0xffffffffu, rs1, 1);
        rs1 += __shfl_xor_sync(0xffffffffu, rs1, 2);

        m0 = nm0; m1 = nm1;
        l0 = l0 * alpha0 + rs0;
        l1 = l1 * alpha1 + rs1;
#pragma unroll
        for (int j = 0; j < 8; j++) {
            o[j][0] *= alpha0; o[j][1] *= alpha0;
            o[j][2] *= alpha1; o[j][3] *= alpha1;
        }

        // O += P V : P already packed fp16 A-frags.
#pragma unroll
        for (int ks = 0; ks < 4; ks++) {
            uint32_t pa[4];
            pa[0] = pp[2 * ks];
            pa[1] = pq[2 * ks];
            pa[2] = pp[2 * ks + 1];
            pa[3] = pq[2 * ks + 1];
            uint32_t vd = v_fb + stb + 4u * (ks * 16 * F_LD);
#pragma unroll
            for (int p = 0; p < 4; p++) {
                uint32_t b0[2], b1[2];
                ldsm_x4_t(vd + (uint32_t)p * 32, b0[0], b0[1], b1[0], b1[1]);
                mma_f16(o[2 * p],     pa, b0, o[2 * p]);
                mma_f16(o[2 * p + 1], pa, b1, o[2 * p + 1]);
            }
        }
    }

    // Epilogue: write attn as fp16 hi/lo into g_ah/g_al [8192][512 words]
    {
        int b = head >> 4, h = head & 15;
        int s0 = qb * 128 + wid * 16 + g;
        float inv0 = 1.f / l0, inv1 = 1.f / l1;
        size_t base0 = ((size_t)b * Sc + s0) * 512 + h * 32;
        size_t base1 = ((size_t)b * Sc + s0 + 8) * 512 + h * 32;
#pragma unroll
        for (int nj = 0; nj < 8; nj++) {
            int dw = nj * 4 + tg;
            uint32_t h0, l0w, h1, l1w;
            split_h2(o[nj][0] * inv0, o[nj][1] * inv0, h0, l0w);
            split_h2(o[nj][2] * inv1, o[nj][3] * inv1, h1, l1w);
            g_ah[base0 + dw] = h0; g_al[base0 + dw] = l0w;
            g_ah[base1 + dw] = h1; g_al[base1 + dw] = l1w;
        }
    }
}

// ---------------------------------------------------------------------------
extern "C" void kernel_launch(void* const* d_in, const int* in_sizes, int n_in,
                              void* d_out, int out_size)
{
    (void)in_sizes; (void)n_in; (void)out_size;
    const float* x      = (const float*)d_in[0];
    const float* w_attn = (const float*)d_in[2];
    const float* b_attn = (const float*)d_in[3];
    const float* w_proj = (const float*)d_in[4];
    const float* b_proj = (const float*)d_in[5];
    float* out = (float*)d_out;

    cudaFuncSetAttribute(h_gemm<0>,    cudaFuncAttributeMaxDynamicSharedMemorySize, G_SMEM);
    cudaFuncSetAttribute(h_gemm<1>,    cudaFuncAttributeMaxDynamicSharedMemorySize, G_SMEM);
    cudaFuncSetAttribute(flash_kernel, cudaFuncAttributeMaxDynamicSharedMemorySize, FLASH_SMEM);

    // Pre-pass: split/transpose inputs to fp16
    conv_x<<<(Mc * 512) / 1024, 1024>>>(x);
    conv_wT<<<dim3(16, NQKV / 32), dim3(32, 8)>>>(w_attn, NQKV, 0);
    conv_wT<<<dim3(16, Dc / 32),   dim3(32, 8)>>>(w_proj, Dc, 1);

    // 1) QKV GEMM -> q/k/v hi (head-major); q columns 2-term, k/v 1-term
    h_gemm<0><<<dim3(NQKV / 128, Mc / 128), 256, G_SMEM>>>(b_attn, nullptr);
    // 2) causal flash attention -> attn split
    flash_kernel<<<dim3(Sc / 128, Bc * Hc), 256, FLASH_SMEM>>>();
    // 3) proj GEMM (2-term) -> out fp32
    h_gemm<1><<<dim3(Dc / 128, Mc / 128), 256, G_SMEM>>>(b_proj, out);
}

// round 10
// speedup vs baseline: 3.7162x; 1.1031x over previous
#include <cuda_runtime.h>
#include <cstdint>

#define DEVINL __device__ __forceinline__

constexpr int Bc = 4, Sc = 2048, Dc = 1024, Hc = 16;
constexpr int Mc = Bc * Sc;           // 8192
constexpr int NQKV = 3 * Dc;          // 3072

// ---------------------------------------------------------------------------
// Scratch (__device__ globals). All fp16 data stored as packed f16x2 words.
// ---------------------------------------------------------------------------
__device__ uint32_t g_xh[(size_t)Mc * 512], g_xl[(size_t)Mc * 512];      // x split [8192][512]
__device__ uint32_t g_wth[(size_t)NQKV * 512];                           // wA^T hi [3072][512]
__device__ uint32_t g_wph[(size_t)Dc * 512];                             // wP^T hi [1024][512]
__device__ uint32_t g_qh[(size_t)64 * Sc * 32];                          // q hi [64][2048][32]
__device__ uint32_t g_kh[(size_t)64 * Sc * 32];                          // k hi
__device__ uint32_t g_vh[(size_t)64 * Sc * 32];                          // v hi
__device__ uint32_t g_ah[(size_t)Mc * 512];                              // attn hi [8192][512]

// ---------------------------------------------------------------------------
// Helpers
// ---------------------------------------------------------------------------
DEVINL uint32_t pack_h2(float x0, float x1) {
    uint32_t h;
    asm("cvt.rn.f16x2.f32 %0, %1, %2;" : "=r"(h) : "f"(x1), "f"(x0));
    return h;
}
DEVINL void unpack_h2(uint32_t h, float& x0, float& x1) {
    asm("{\n\t.reg .f16 lo, hi;\n\tmov.b32 {lo, hi}, %2;\n\t"
        "cvt.f32.f16 %0, lo;\n\tcvt.f32.f16 %1, hi;\n\t}"
        : "=f"(x0), "=f"(x1) : "r"(h));
}
DEVINL void split_h2(float x0, float x1, uint32_t& h, uint32_t& l) {
    h = pack_h2(x0, x1);
    float b0, b1;
    unpack_h2(h, b0, b1);
    l = pack_h2(x0 - b0, x1 - b1);
}
DEVINL uint32_t ex2_h2(float d0, float d1) {
    uint32_t din = pack_h2(d0, d1);
    uint32_t r;
    asm("ex2.approx.f16x2 %0, %1;" : "=r"(r) : "r"(din));
    return r;
}
DEVINL void mma_f16(float d[4], const uint32_t a[4], const uint32_t b[2], const float c[4]) {
    asm volatile(
        "mma.sync.aligned.m16n8k16.row.col.f32.f16.f16.f32 "
        "{%0,%1,%2,%3}, {%4,%5,%6,%7}, {%8,%9}, {%10,%11,%12,%13};\n"
        : "=f"(d[0]), "=f"(d[1]), "=f"(d[2]), "=f"(d[3])
        : "r"(a[0]), "r"(a[1]), "r"(a[2]), "r"(a[3]),
          "r"(b[0]), "r"(b[1]),
          "f"(c[0]), "f"(c[1]), "f"(c[2]), "f"(c[3]));
}
DEVINL void ldsm_x4(uint32_t addr, uint32_t& r0, uint32_t& r1, uint32_t& r2, uint32_t& r3) {
    asm volatile("ldmatrix.sync.aligned.m8n8.x4.shared.b16 {%0,%1,%2,%3}, [%4];"
                 : "=r"(r0), "=r"(r1), "=r"(r2), "=r"(r3) : "r"(addr));
}
DEVINL void ldsm_x4_t(uint32_t addr, uint32_t& r0, uint32_t& r1, uint32_t& r2, uint32_t& r3) {
    asm volatile("ldmatrix.sync.aligned.m8n8.x4.trans.shared.b16 {%0,%1,%2,%3}, [%4];"
                 : "=r"(r0), "=r"(r1), "=r"(r2), "=r"(r3) : "r"(addr));
}
DEVINL void cp16(void* s, const void* g) {
    uint32_t sa = (uint32_t)__cvta_generic_to_shared(s);
    asm volatile("cp.async.cg.shared.global [%0], [%1], 16;\n" :: "r"(sa), "l"(g));
}
DEVINL void cp_commit() { asm volatile("cp.async.commit_group;\n"); }
template <int N> DEVINL void cp_wait() { asm volatile("cp.async.wait_group %0;\n" :: "n"(N)); }

// ---------------------------------------------------------------------------
// Pre-pass 1: split x (fp32 [8192][1024]) -> g_xh/g_xl (f16x2 words)
// ---------------------------------------------------------------------------
__global__ void conv_x(const float* __restrict__ x)
{
    size_t idx = (size_t)blockIdx.x * 1024 + threadIdx.x;   // 4M words
    float2 v = ((const float2*)x)[idx];
    uint32_t h, l;
    split_h2(v.x, v.y, h, l);
    g_xh[idx] = h; g_xl[idx] = l;
}

// ---------------------------------------------------------------------------
// Pre-pass 2: transpose + round W (fp32 [1024][N]) -> [N][512 words] hi only.
// ---------------------------------------------------------------------------
__global__ void conv_wT(const float* __restrict__ W, int N, int which)
{
    __shared__ float ts[64][33];
    uint32_t* Wh = which ? g_wph : g_wth;
    const int k0 = blockIdx.x * 64, n0 = blockIdx.y * 32;
    const int tx = threadIdx.x, ty = threadIdx.y;
#pragma unroll
    for (int i = 0; i < 8; i++)
        ts[ty + i * 8][tx] = W[(size_t)(k0 + ty + i * 8) * N + n0 + tx];
    __syncthreads();
#pragma unroll
    for (int i = 0; i < 4; i++) {
        int n = ty + i * 8;
        Wh[(size_t)(n0 + n) * 512 + (k0 >> 1) + tx] = pack_h2(ts[2 * tx][n], ts[2 * tx + 1][n]);
    }
}

// ---------------------------------------------------------------------------
// fp16 GEMM: C = A(Mx1024) W^T + bias.
// CTA 128x128, BK=32, 3-stage cp.async, 2 CTAs/SM.
// A-side 2-term (Ah+Al) only for QKV q-columns (EPI=0, cn<1024).
// 1-term everywhere else (k/v columns, proj GEMM).
// ---------------------------------------------------------------------------
constexpr int P_LD = 20;                       // words/row (16 + 4 pad)
constexpr int P_ARR_W = 128 * P_LD;            // 2560 words
constexpr int P_ARR_B = P_ARR_W * 4;           // 10240 B
constexpr int P_STG_W = 3 * P_ARR_W;           // 7680 words
constexpr int P_STG_B = P_STG_W * 4;           // 30720 B
constexpr int G_SMEM = 3 * P_STG_B;            // 92160 B

template <int EPI>
__global__ void __launch_bounds__(256, 2)
h_gemm(const float* __restrict__ bias, float* __restrict__ out)
{
    extern __shared__ uint32_t sw[];
    const uint32_t* Agh = EPI ? g_ah : g_xh;
    const uint32_t* Agl = g_xl;                // only read when two_term
    const uint32_t* Bgh = EPI ? g_wph : g_wth;

    const int tid = threadIdx.x, wid = tid >> 5, lid = tid & 31;
    const int wm = wid >> 2, wn = wid & 3;
    const int g = lid >> 2, tg = lid & 3;
    const int cm = blockIdx.y * 128, cn = blockIdx.x * 128;
    const bool two_term = (EPI == 0) && (cn < 1024);
    const uint32_t smb = (uint32_t)__cvta_generic_to_shared(sw);

    const uint32_t a_fb = smb + 4u * ((wm * 64 + (lid & 15)) * P_LD + (lid >> 4) * 4);
    const uint32_t b_fb = smb + 4u * ((wn * 32 + ((lid >> 4) & 1) * 8 + (lid & 7)) * P_LD
                                      + ((lid >> 3) & 1) * 4) + 2u * P_ARR_B;

    const int row = tid >> 1;
    const int ch0 = (tid & 1) * 2;

    auto load_stage = [&](int kt, int s) {
#pragma unroll
        for (int i = 0; i < 2; i++) {
            int c = ch0 + i;
            uint32_t dst = (uint32_t)(s * P_STG_W + row * P_LD + c * 4);
            size_t asrc = (size_t)(cm + row) * 512 + kt * 16 + c * 4;
            size_t bsrc = (size_t)(cn + row) * 512 + kt * 16 + c * 4;
            cp16(sw + dst,               Agh + asrc);
            if (two_term) cp16(sw + dst + P_ARR_W, Agl + asrc);
            cp16(sw + dst + 2 * P_ARR_W, Bgh + bsrc);
        }
    };

    float acc[4][4][4];
#pragma unroll
    for (int i = 0; i < 4; i++)
#pragma unroll
        for (int j = 0; j < 4; j++)
#pragma unroll
            for (int e = 0; e < 4; e++) acc[i][j][e] = 0.f;

    constexpr int NT = 32;                     // K=1024 / 32
    load_stage(0, 0); cp_commit();
    load_stage(1, 1); cp_commit();

    for (int kt = 0; kt < NT; kt++) {
        cp_wait<1>();
        __syncthreads();
        if (kt + 2 < NT) load_stage(kt + 2, (kt + 2) % 3);
        cp_commit();

        const uint32_t sb = (uint32_t)((kt % 3) * P_STG_B);
#pragma unroll
        for (int ks = 0; ks < 2; ks++) {
            uint32_t ah[4][4], b[4][2];
#pragma unroll
            for (int mi = 0; mi < 4; mi++) {
                uint32_t ad = a_fb + sb + 4u * (mi * 16 * P_LD + ks * 8);
                ldsm_x4(ad, ah[mi][0], ah[mi][1], ah[mi][2], ah[mi][3]);
            }
#pragma unroll
            for (int p = 0; p < 2; p++)
                ldsm_x4(b_fb + sb + 4u * (p * 16 * P_LD + ks * 8),
                        b[2 * p][0], b[2 * p][1], b[2 * p + 1][0], b[2 * p + 1][1]);
            if (two_term) {
                uint32_t al[4][4];
#pragma unroll
                for (int mi = 0; mi < 4; mi++) {
                    uint32_t ad = a_fb + sb + 4u * (mi * 16 * P_LD + ks * 8);
                    ldsm_x4(ad + P_ARR_B, al[mi][0], al[mi][1], al[mi][2], al[mi][3]);
                }
#pragma unroll
                for (int mi = 0; mi < 4; mi++)
#pragma unroll
                    for (int nj = 0; nj < 4; nj++)
                        mma_f16(acc[mi][nj], al[mi], b[nj], acc[mi][nj]);
            }
#pragma unroll
            for (int mi = 0; mi < 4; mi++)
#pragma unroll
                for (int nj = 0; nj < 4; nj++)
                    mma_f16(acc[mi][nj], ah[mi], b[nj], acc[mi][nj]);
        }
    }

    // Epilogue
#pragma unroll
    for (int mi = 0; mi < 4; mi++) {
#pragma unroll
        for (int nj = 0; nj < 4; nj++) {
            int col0 = cn + wn * 32 + nj * 8 + 2 * tg;       // even
            float2 v0 = make_float2(acc[mi][nj][0] + bias[col0],
                                    acc[mi][nj][1] + bias[col0 + 1]);
            float2 v1 = make_float2(acc[mi][nj][2] + bias[col0],
                                    acc[mi][nj][3] + bias[col0 + 1]);
            int row0 = cm + wm * 64 + mi * 16 + g;
            int row1 = row0 + 8;
            if (EPI == 1) {
                *(float2*)&out[(size_t)row0 * 1024 + col0] = v0;
                *(float2*)&out[(size_t)row1 * 1024 + col0] = v1;
            } else {
                int t = col0 >> 10;                // 0:q 1:k 2:v
                int r1 = col0 & 1023;
                int h = r1 >> 6, d = r1 & 63;      // d even
                int b0 = row0 >> 11, s0 = row0 & 2047;
                int b1 = row1 >> 11, s1 = row1 & 2047;
                size_t w0 = ((size_t)(b0 * Hc + h) * Sc + s0) * 32 + (d >> 1);
                size_t w1 = ((size_t)(b1 * Hc + h) * Sc + s1) * 32 + (d >> 1);
                uint32_t* dst = (t == 0) ? g_qh : (t == 1) ? g_kh : g_vh;
                dst[w0] = pack_h2(v0.x, v0.y);
                dst[w1] = pack_h2(v1.x, v1.y);
            }
        }
    }
}

// ---------------------------------------------------------------------------
// Flash attention: causal, hd=64, k-blocks of 64, fp16 1-term QK^T.
// Softmax: ex2.approx.f16x2 -> results are directly the packed P fragments.
// 3-stage cp.async K/V tiles. 2 CTAs/SM. Heaviest q-blocks launch first.
// ---------------------------------------------------------------------------
constexpr int F_LD = 36;                       // words per 64-half row
constexpr int F_TW = 64 * F_LD;                // 2304 words per stage
constexpr int F_VB0 = 3 * F_TW;                // V area word offset
constexpr int FLASH_SMEM = 6 * F_TW * 4;       // 55296 B

__global__ void __launch_bounds__(256, 2)
flash_kernel()
{
    extern __shared__ uint32_t smw[];
    const uint32_t smb = (uint32_t)__cvta_generic_to_shared(smw);

    const int tid = threadIdx.x, wid = tid >> 5, lid = tid & 31;
    const int g = lid >> 2, tg = lid & 3;
    const int qb = (int)gridDim.x - 1 - (int)blockIdx.x;   // heavy blocks first
    const int head = blockIdx.y;

    const uint32_t* Qh = g_qh + (size_t)head * Sc * 32 + (size_t)qb * 128 * 32;
    const uint32_t* Kh = g_kh + (size_t)head * Sc * 32;
    const uint32_t* Vh = g_vh + (size_t)head * Sc * 32;

    // Stage Q hi -> V area (128 rows x 36w stride).
#pragma unroll
    for (int i = 0; i < 4; i++) {
        int idx = tid + i * 256;
        int r = idx >> 3, c = idx & 7;
        cp16(smw + F_VB0 + r * F_LD + c * 4, Qh + (size_t)r * 32 + c * 4);
    }
    cp_commit();
    cp_wait<0>();
    __syncthreads();

    uint32_t qh[4][4];
    {
        uint32_t qo = smb + 4u * F_VB0
                    + 4u * ((wid * 16 + (lid & 15)) * F_LD + (lid >> 4) * 4);
#pragma unroll
        for (int ks = 0; ks < 4; ks++)
            ldsm_x4(qo + 4u * (ks * 8), qh[ks][0], qh[ks][1], qh[ks][2], qh[ks][3]);
    }
    __syncthreads();                           // K/V areas now reusable

    auto load_tile = [&](int kb, int s) {
        size_t kbase = (size_t)kb * 64;
#pragma unroll
        for (int i = 0; i < 2; i++) {
            int idx = tid + i * 256;
            int r = idx >> 3, c = idx & 7;
            uint32_t dk = (uint32_t)(s * F_TW + r * F_LD + c * 4);
            cp16(smw + dk,         Kh + (kbase + r) * 32 + c * 4);
            cp16(smw + F_VB0 + dk, Vh + (kbase + r) * 32 + c * 4);
        }
    };

    const int nkb = 2 * qb + 2;                // 64-wide k-blocks
    load_tile(0, 0); cp_commit();
    load_tile(1, 1); cp_commit();

    float o[8][4];
#pragma unroll
    for (int j = 0; j < 8; j++)
#pragma unroll
        for (int e = 0; e < 4; e++) o[j][e] = 0.f;
    float m0 = -1e30f, m1 = -1e30f, l0 = 0.f, l1 = 0.f;

    const float scale = 0.125f;
    const float LOG2E = 1.4426950408889634f;
    const int row0g = qb * 128 + wid * 16 + g;
    const int row1g = row0g + 8;

    const uint32_t k_fb = smb + 4u * ((((lid >> 4) & 1) * 8 + (lid & 7)) * F_LD
                                      + ((lid >> 3) & 1) * 4);
    const uint32_t v_fb = smb + 4u * F_VB0
                        + 4u * ((((lid >> 3) & 1) * 8 + (lid & 7)) * F_LD)
                        + (uint32_t)(lid >> 4) * 16;

    for (int kb = 0; kb < nkb; kb++) {
        cp_wait<1>();
        __syncthreads();
        if (kb + 2 < nkb) load_tile(kb + 2, (kb + 2) % 3);
        cp_commit();

        const uint32_t stb = (uint32_t)((kb % 3) * F_TW * 4);

        // S = Q K^T (16 q-rows x 64 k-cols per warp), fp16 1-term
        float sacc[8][4];
#pragma unroll
        for (int nj = 0; nj < 8; nj++)
#pragma unroll
            for (int e = 0; e < 4; e++) sacc[nj][e] = 0.f;
#pragma unroll
        for (int ks = 0; ks < 4; ks++) {
            uint32_t kd = k_fb + stb + 4u * (ks * 8);
#pragma unroll
            for (int p = 0; p < 2; p++) {
                uint32_t b0[2], b1[2];
                ldsm_x4(kd + 4u * (2 * p * 16 * F_LD), b0[0], b0[1], b1[0], b1[1]);
                mma_f16(sacc[4 * p],     qh[ks], b0, sacc[4 * p]);
                mma_f16(sacc[4 * p + 1], qh[ks], b1, sacc[4 * p + 1]);
                uint32_t c0[2], c1[2];
                ldsm_x4(kd + 4u * ((2 * p + 1) * 16 * F_LD), c0[0], c0[1], c1[0], c1[1]);
                mma_f16(sacc[4 * p + 2], qh[ks], c0, sacc[4 * p + 2]);
                mma_f16(sacc[4 * p + 3], qh[ks], c1, sacc[4 * p + 3]);
            }
        }

        // scale + causal mask
#pragma unroll
        for (int nj = 0; nj < 8; nj++) {
#pragma unroll
            for (int e = 0; e < 4; e++) {
                int col = kb * 64 + nj * 8 + 2 * tg + (e & 1);
                int row = (e & 2) ? row1g : row0g;
                float v = sacc[nj][e] * scale;
                sacc[nj][e] = (col > row) ? -1e30f : v;
            }
        }

        // online softmax
        float rmax0 = -1e30f, rmax1 = -1e30f;
#pragma unroll
        for (int nj = 0; nj < 8; nj++) {
            rmax0 = fmaxf(rmax0, fmaxf(sacc[nj][0], sacc[nj][1]));
            rmax1 = fmaxf(rmax1, fmaxf(sacc[nj][2], sacc[nj][3]));
        }
        rmax0 = fmaxf(rmax0, __shfl_xor_sync(0xffffffffu, rmax0, 1));
        rmax0 = fmaxf(rmax0, __shfl_xor_sync(0xffffffffu, rmax0, 2));
        rmax1 = fmaxf(rmax1, __shfl_xor_sync(0xffffffffu, rmax1, 1));
        rmax1 = fmaxf(rmax1, __shfl_xor_sync(0xffffffffu, rmax1, 2));

        float nm0 = fmaxf(m0, rmax0), nm1 = fmaxf(m1, rmax1);
        float alpha0 = exp2f((m0 - nm0) * LOG2E);
        float alpha1 = exp2f((m1 - nm1) * LOG2E);
        float c0 = nm0 * LOG2E, c1 = nm1 * LOG2E;

        // exponentials in fp16x2: result IS the packed P fragment word
        uint32_t pp[8], pq[8];
        float rs0 = 0.f, rs1 = 0.f;
#pragma unroll
        for (int nj = 0; nj < 8; nj++) {
            pp[nj] = ex2_h2(fmaf(sacc[nj][0], LOG2E, -c0), fmaf(sacc[nj][1], LOG2E, -c0));
            pq[nj] = ex2_h2(fmaf(sacc[nj][2], LOG2E, -c1), fmaf(sacc[nj][3], LOG2E, -c1));
            float u0, u1;
            unpack_h2(pp[nj], u0, u1); rs0 += u0 + u1;
            unpack_h2(pq[nj], u0, u1); rs1 += u0 + u1;
        }
        rs0 += __shfl_xor_sync(0xffffffffu, rs0, 1);
        rs0 += __shfl_xor_sync(0xffffffffu, rs0, 2);
        rs1 += __shfl_xor_sync(0xffffffffu, rs1, 1);
        rs1 += __shfl_xor_sync(0xffffffffu, rs1, 2);

        m0 = nm0; m1 = nm1;
        l0 = l0 * alpha0 + rs0;
        l1 = l1 * alpha1 + rs1;
#pragma unroll
        for (int j = 0; j < 8; j++) {
            o[j][0] *= alpha0; o[j][1] *= alpha0;
            o[j][2] *= alpha1; o[j][3] *= alpha1;
        }

        // O += P V : P already packed fp16 A-frags.
#pragma unroll
        for (int ks = 0; ks < 4; ks++) {
            uint32_t pa[4];
            pa[0] = pp[2 * ks];
            pa[1] = pq[2 * ks];
            pa[2] = pp[2 * ks + 1];
            pa[3] = pq[2 * ks + 1];
            uint32_t vd = v_fb + stb + 4u * (ks * 16 * F_LD);
#pragma unroll
            for (int p = 0; p < 4; p++) {
                uint32_t b0[2], b1[2];
                ldsm_x4_t(vd + (uint32_t)p * 32, b0[0], b0[1], b1[0], b1[1]);
                mma_f16(o[2 * p],     pa, b0, o[2 * p]);
                mma_f16(o[2 * p + 1], pa, b1, o[2 * p + 1]);
            }
        }
    }

    // Epilogue: write attn as fp16 hi only into g_ah [8192][512 words]
    {
        int b = head >> 4, h = head & 15;
        int s0 = qb * 128 + wid * 16 + g;
        float inv0 = 1.f / l0, inv1 = 1.f / l1;
        size_t base0 = ((size_t)b * Sc + s0) * 512 + h * 32;
        size_t base1 = ((size_t)b * Sc + s0 + 8) * 512 + h * 32;
#pragma unroll
        for (int nj = 0; nj < 8; nj++) {
            int dw = nj * 4 + tg;
            g_ah[base0 + dw] = pack_h2(o[nj][0] * inv0, o[nj][1] * inv0);
            g_ah[base1 + dw] = pack_h2(o[nj][2] * inv1, o[nj][3] * inv1);
        }
    }
}

// ---------------------------------------------------------------------------
extern "C" void kernel_launch(void* const* d_in, const int* in_sizes, int n_in,
                              void* d_out, int out_size)
{
    (void)in_sizes; (void)n_in; (void)out_size;
    const float* x      = (const float*)d_in[0];
    const float* w_attn = (const float*)d_in[2];
    const float* b_attn = (const float*)d_in[3];
    const float* w_proj = (const float*)d_in[4];
    const float* b_proj = (const float*)d_in[5];
    float* out = (float*)d_out;

    cudaFuncSetAttribute(h_gemm<0>,    cudaFuncAttributeMaxDynamicSharedMemorySize, G_SMEM);
    cudaFuncSetAttribute(h_gemm<1>,    cudaFuncAttributeMaxDynamicSharedMemorySize, G_SMEM);
    cudaFuncSetAttribute(flash_kernel, cudaFuncAttributeMaxDynamicSharedMemorySize, FLASH_SMEM);

    // Pre-pass: split/transpose inputs to fp16
    conv_x<<<(Mc * 512) / 1024, 1024>>>(x);
    conv_wT<<<dim3(16, NQKV / 32), dim3(32, 8)>>>(w_attn, NQKV, 0);
    conv_wT<<<dim3(16, Dc / 32),   dim3(32, 8)>>>(w_proj, Dc, 1);

    // 1) QKV GEMM -> q/k/v hi (head-major); q columns 2-term, k/v 1-term
    h_gemm<0><<<dim3(NQKV / 128, Mc / 128), 256, G_SMEM>>>(b_attn, nullptr);
    // 2) causal flash attention -> attn hi (1-term)
    flash_kernel<<<dim3(Sc / 128, Bc * Hc), 256, FLASH_SMEM>>>();
    // 3) proj GEMM (1-term) -> out fp32
    h_gemm<1><<<dim3(Dc / 128, Mc / 128), 256, G_SMEM>>>(b_proj, out);
}

// round 11
// speedup vs baseline: 4.3178x; 1.1619x over previous
#include <cuda_runtime.h>
#include <cstdint>

#define DEVINL __device__ __forceinline__

constexpr int Bc = 4, Sc = 2048, Dc = 1024, Hc = 16;
constexpr int Mc = Bc * Sc;           // 8192
constexpr int NQKV = 3 * Dc;          // 3072

// ---------------------------------------------------------------------------
// Scratch (__device__ globals). All fp16 data stored as packed f16x2 words.
// ---------------------------------------------------------------------------
__device__ uint32_t g_xh[(size_t)Mc * 512];                              // x hi [8192][512]
__device__ uint32_t g_wth[(size_t)NQKV * 512];                           // wA^T hi [3072][512]
__device__ uint32_t g_wph[(size_t)Dc * 512];                             // wP^T hi [1024][512]
__device__ uint32_t g_qh[(size_t)64 * Sc * 32];                          // q hi [64][2048][32]
__device__ uint32_t g_kh[(size_t)64 * Sc * 32];                          // k hi
__device__ uint32_t g_vh[(size_t)64 * Sc * 32];                          // v hi
__device__ uint32_t g_ah[(size_t)Mc * 512];                              // attn hi [8192][512]

// ---------------------------------------------------------------------------
// Helpers
// ---------------------------------------------------------------------------
DEVINL uint32_t pack_h2(float x0, float x1) {
    uint32_t h;
    asm("cvt.rn.f16x2.f32 %0, %1, %2;" : "=r"(h) : "f"(x1), "f"(x0));
    return h;
}
DEVINL uint32_t ex2_h2(float d0, float d1) {
    uint32_t din = pack_h2(d0, d1);
    uint32_t r;
    asm("ex2.approx.f16x2 %0, %1;" : "=r"(r) : "r"(din));
    return r;
}
DEVINL void mma_f16(float d[4], const uint32_t a[4], const uint32_t b[2], const float c[4]) {
    asm volatile(
        "mma.sync.aligned.m16n8k16.row.col.f32.f16.f16.f32 "
        "{%0,%1,%2,%3}, {%4,%5,%6,%7}, {%8,%9}, {%10,%11,%12,%13};\n"
        : "=f"(d[0]), "=f"(d[1]), "=f"(d[2]), "=f"(d[3])
        : "r"(a[0]), "r"(a[1]), "r"(a[2]), "r"(a[3]),
          "r"(b[0]), "r"(b[1]),
          "f"(c[0]), "f"(c[1]), "f"(c[2]), "f"(c[3]));
}
DEVINL void ldsm_x4(uint32_t addr, uint32_t& r0, uint32_t& r1, uint32_t& r2, uint32_t& r3) {
    asm volatile("ldmatrix.sync.aligned.m8n8.x4.shared.b16 {%0,%1,%2,%3}, [%4];"
                 : "=r"(r0), "=r"(r1), "=r"(r2), "=r"(r3) : "r"(addr));
}
DEVINL void ldsm_x4_t(uint32_t addr, uint32_t& r0, uint32_t& r1, uint32_t& r2, uint32_t& r3) {
    asm volatile("ldmatrix.sync.aligned.m8n8.x4.trans.shared.b16 {%0,%1,%2,%3}, [%4];"
                 : "=r"(r0), "=r"(r1), "=r"(r2), "=r"(r3) : "r"(addr));
}
DEVINL void cp16(void* s, const void* g) {
    uint32_t sa = (uint32_t)__cvta_generic_to_shared(s);
    asm volatile("cp.async.cg.shared.global [%0], [%1], 16;\n" :: "r"(sa), "l"(g));
}
DEVINL void cp_commit() { asm volatile("cp.async.commit_group;\n"); }
template <int N> DEVINL void cp_wait() { asm volatile("cp.async.wait_group %0;\n" :: "n"(N)); }

// ---------------------------------------------------------------------------
// Pre-pass 1: round x (fp32 [8192][1024]) -> g_xh (f16x2 words)
// ---------------------------------------------------------------------------
__global__ void conv_x(const float* __restrict__ x)
{
    size_t idx = (size_t)blockIdx.x * 1024 + threadIdx.x;   // 4M words
    float2 v = ((const float2*)x)[idx];
    g_xh[idx] = pack_h2(v.x, v.y);
}

// ---------------------------------------------------------------------------
// Pre-pass 2: transpose + round W (fp32 [1024][N]) -> [N][512 words] hi only.
// ---------------------------------------------------------------------------
__global__ void conv_wT(const float* __restrict__ W, int N, int which)
{
    __shared__ float ts[64][33];
    uint32_t* Wh = which ? g_wph : g_wth;
    const int k0 = blockIdx.x * 64, n0 = blockIdx.y * 32;
    const int tx = threadIdx.x, ty = threadIdx.y;
#pragma unroll
    for (int i = 0; i < 8; i++)
        ts[ty + i * 8][tx] = W[(size_t)(k0 + ty + i * 8) * N + n0 + tx];
    __syncthreads();
#pragma unroll
    for (int i = 0; i < 4; i++) {
        int n = ty + i * 8;
        Wh[(size_t)(n0 + n) * 512 + (k0 >> 1) + tx] = pack_h2(ts[2 * tx][n], ts[2 * tx + 1][n]);
    }
}

// ---------------------------------------------------------------------------
// fp16 1-term GEMM: C = A(Mx1024) W^T + bias.
// CTA 128x128, BK=32, 3-stage cp.async, 2 CTAs/SM. Warp tile 64x32.
// EPI=0: A=x -> scatter q/k/v hi (head-major). EPI=1: A=attn -> out fp32.
// ---------------------------------------------------------------------------
constexpr int P_LD = 20;                       // words/row (16 + 4 pad)
constexpr int P_ARR_W = 128 * P_LD;            // 2560 words
constexpr int P_ARR_B = P_ARR_W * 4;           // 10240 B
constexpr int P_STG_W = 2 * P_ARR_W;           // 5120 words (A | B)
constexpr int P_STG_B = P_STG_W * 4;           // 20480 B
constexpr int G_SMEM = 3 * P_STG_B;            // 61440 B

template <int EPI>
__global__ void __launch_bounds__(256, 2)
h_gemm(const float* __restrict__ bias, float* __restrict__ out)
{
    extern __shared__ uint32_t sw[];
    const uint32_t* Agh = EPI ? g_ah : g_xh;
    const uint32_t* Bgh = EPI ? g_wph : g_wth;

    const int tid = threadIdx.x, wid = tid >> 5, lid = tid & 31;
    const int wm = wid >> 2, wn = wid & 3;
    const int g = lid >> 2, tg = lid & 3;
    const int cm = blockIdx.y * 128, cn = blockIdx.x * 128;
    const uint32_t smb = (uint32_t)__cvta_generic_to_shared(sw);

    const uint32_t a_fb = smb + 4u * ((wm * 64 + (lid & 15)) * P_LD + (lid >> 4) * 4);
    const uint32_t b_fb = smb + 4u * ((wn * 32 + ((lid >> 4) & 1) * 8 + (lid & 7)) * P_LD
                                      + ((lid >> 3) & 1) * 4) + (uint32_t)P_ARR_B;

    const int row = tid >> 1;
    const int ch0 = (tid & 1) * 2;

    auto load_stage = [&](int kt, int s) {
#pragma unroll
        for (int i = 0; i < 2; i++) {
            int c = ch0 + i;
            uint32_t dst = (uint32_t)(s * P_STG_W + row * P_LD + c * 4);
            size_t asrc = (size_t)(cm + row) * 512 + kt * 16 + c * 4;
            size_t bsrc = (size_t)(cn + row) * 512 + kt * 16 + c * 4;
            cp16(sw + dst,           Agh + asrc);
            cp16(sw + dst + P_ARR_W, Bgh + bsrc);
        }
    };

    float acc[4][4][4];
#pragma unroll
    for (int i = 0; i < 4; i++)
#pragma unroll
        for (int j = 0; j < 4; j++)
#pragma unroll
            for (int e = 0; e < 4; e++) acc[i][j][e] = 0.f;

    constexpr int NT = 32;                     // K=1024 / 32
    load_stage(0, 0); cp_commit();
    load_stage(1, 1); cp_commit();

    for (int kt = 0; kt < NT; kt++) {
        cp_wait<1>();
        __syncthreads();
        if (kt + 2 < NT) load_stage(kt + 2, (kt + 2) % 3);
        cp_commit();

        const uint32_t sb = (uint32_t)((kt % 3) * P_STG_B);
#pragma unroll
        for (int ks = 0; ks < 2; ks++) {
            uint32_t ah[4][4], b[4][2];
#pragma unroll
            for (int mi = 0; mi < 4; mi++) {
                uint32_t ad = a_fb + sb + 4u * (mi * 16 * P_LD + ks * 8);
                ldsm_x4(ad, ah[mi][0], ah[mi][1], ah[mi][2], ah[mi][3]);
            }
#pragma unroll
            for (int p = 0; p < 2; p++)
                ldsm_x4(b_fb + sb + 4u * (p * 16 * P_LD + ks * 8),
                        b[2 * p][0], b[2 * p][1], b[2 * p + 1][0], b[2 * p + 1][1]);
#pragma unroll
            for (int mi = 0; mi < 4; mi++)
#pragma unroll
                for (int nj = 0; nj < 4; nj++)
                    mma_f16(acc[mi][nj], ah[mi], b[nj], acc[mi][nj]);
        }
    }

    // Epilogue
#pragma unroll
    for (int mi = 0; mi < 4; mi++) {
#pragma unroll
        for (int nj = 0; nj < 4; nj++) {
            int col0 = cn + wn * 32 + nj * 8 + 2 * tg;       // even
            float2 v0 = make_float2(acc[mi][nj][0] + bias[col0],
                                    acc[mi][nj][1] + bias[col0 + 1]);
            float2 v1 = make_float2(acc[mi][nj][2] + bias[col0],
                                    acc[mi][nj][3] + bias[col0 + 1]);
            int row0 = cm + wm * 64 + mi * 16 + g;
            int row1 = row0 + 8;
            if (EPI == 1) {
                *(float2*)&out[(size_t)row0 * 1024 + col0] = v0;
                *(float2*)&out[(size_t)row1 * 1024 + col0] = v1;
            } else {
                int t = col0 >> 10;                // 0:q 1:k 2:v
                int r1 = col0 & 1023;
                int h = r1 >> 6, d = r1 & 63;      // d even
                int b0 = row0 >> 11, s0 = row0 & 2047;
                int b1 = row1 >> 11, s1 = row1 & 2047;
                size_t w0 = ((size_t)(b0 * Hc + h) * Sc + s0) * 32 + (d >> 1);
                size_t w1 = ((size_t)(b1 * Hc + h) * Sc + s1) * 32 + (d >> 1);
                uint32_t* dst = (t == 0) ? g_qh : (t == 1) ? g_kh : g_vh;
                dst[w0] = pack_h2(v0.x, v0.y);
                dst[w1] = pack_h2(v1.x, v1.y);
            }
        }
    }
}

// ---------------------------------------------------------------------------
// Flash attention: causal, hd=64, k-blocks of 64, fp16 1-term QK^T.
// Softmax: ex2.approx.f16x2 -> packed P fragments. Row-sum l accumulated by
// a ones-vector mma (no unpack/adds/shfl). 3-stage cp.async. 2 CTAs/SM.
// ---------------------------------------------------------------------------
constexpr int F_LD = 36;                       // words per 64-half row
constexpr int F_TW = 64 * F_LD;                // 2304 words per stage
constexpr int F_VB0 = 3 * F_TW;                // V area word offset
constexpr int FLASH_SMEM = 6 * F_TW * 4;       // 55296 B

__global__ void __launch_bounds__(256, 2)
flash_kernel()
{
    extern __shared__ uint32_t smw[];
    const uint32_t smb = (uint32_t)__cvta_generic_to_shared(smw);

    const int tid = threadIdx.x, wid = tid >> 5, lid = tid & 31;
    const int g = lid >> 2, tg = lid & 3;
    const int qb = (int)gridDim.x - 1 - (int)blockIdx.x;   // heavy blocks first
    const int head = blockIdx.y;

    const uint32_t* Qh = g_qh + (size_t)head * Sc * 32 + (size_t)qb * 128 * 32;
    const uint32_t* Kh = g_kh + (size_t)head * Sc * 32;
    const uint32_t* Vh = g_vh + (size_t)head * Sc * 32;

    // Stage Q hi -> V area (128 rows x 36w stride).
#pragma unroll
    for (int i = 0; i < 4; i++) {
        int idx = tid + i * 256;
        int r = idx >> 3, c = idx & 7;
        cp16(smw + F_VB0 + r * F_LD + c * 4, Qh + (size_t)r * 32 + c * 4);
    }
    cp_commit();
    cp_wait<0>();
    __syncthreads();

    uint32_t qh[4][4];
    {
        uint32_t qo = smb + 4u * F_VB0
                    + 4u * ((wid * 16 + (lid & 15)) * F_LD + (lid >> 4) * 4);
#pragma unroll
        for (int ks = 0; ks < 4; ks++)
            ldsm_x4(qo + 4u * (ks * 8), qh[ks][0], qh[ks][1], qh[ks][2], qh[ks][3]);
    }
    __syncthreads();                           // K/V areas now reusable

    auto load_tile = [&](int kb, int s) {
        size_t kbase = (size_t)kb * 64;
#pragma unroll
        for (int i = 0; i < 2; i++) {
            int idx = tid + i * 256;
            int r = idx >> 3, c = idx & 7;
            uint32_t dk = (uint32_t)(s * F_TW + r * F_LD + c * 4);
            cp16(smw + dk,         Kh + (kbase + r) * 32 + c * 4);
            cp16(smw + F_VB0 + dk, Vh + (kbase + r) * 32 + c * 4);
        }
    };

    const int nkb = 2 * qb + 2;                // 64-wide k-blocks
    load_tile(0, 0); cp_commit();
    load_tile(1, 1); cp_commit();

    float o[8][4];
#pragma unroll
    for (int j = 0; j < 8; j++)
#pragma unroll
        for (int e = 0; e < 4; e++) o[j][e] = 0.f;
    float lacc[4] = {0.f, 0.f, 0.f, 0.f};      // row-sum accumulator (ones-mma)
    float m0 = -1e30f, m1 = -1e30f;

    const float scale = 0.125f;
    const float LOG2E = 1.4426950408889634f;
    const int row0g = qb * 128 + wid * 16 + g;
    const int row1g = row0g + 8;
    const uint32_t b_ones[2] = {0x3C003C00u, 0x3C003C00u};   // f16 1.0 x2

    const uint32_t k_fb = smb + 4u * ((((lid >> 4) & 1) * 8 + (lid & 7)) * F_LD
                                      + ((lid >> 3) & 1) * 4);
    const uint32_t v_fb = smb + 4u * F_VB0
                        + 4u * ((((lid >> 3) & 1) * 8 + (lid & 7)) * F_LD)
                        + (uint32_t)(lid >> 4) * 16;

    for (int kb = 0; kb < nkb; kb++) {
        cp_wait<1>();
        __syncthreads();
        if (kb + 2 < nkb) load_tile(kb + 2, (kb + 2) % 3);
        cp_commit();

        const uint32_t stb = (uint32_t)((kb % 3) * F_TW * 4);

        // S = Q K^T (16 q-rows x 64 k-cols per warp), fp16 1-term
        float sacc[8][4];
#pragma unroll
        for (int nj = 0; nj < 8; nj++)
#pragma unroll
            for (int e = 0; e < 4; e++) sacc[nj][e] = 0.f;
#pragma unroll
        for (int ks = 0; ks < 4; ks++) {
            uint32_t kd = k_fb + stb + 4u * (ks * 8);
#pragma unroll
            for (int p = 0; p < 2; p++) {
                uint32_t b0[2], b1[2];
                ldsm_x4(kd + 4u * (2 * p * 16 * F_LD), b0[0], b0[1], b1[0], b1[1]);
                mma_f16(sacc[4 * p],     qh[ks], b0, sacc[4 * p]);
                mma_f16(sacc[4 * p + 1], qh[ks], b1, sacc[4 * p + 1]);
                uint32_t c0[2], c1[2];
                ldsm_x4(kd + 4u * ((2 * p + 1) * 16 * F_LD), c0[0], c0[1], c1[0], c1[1]);
                mma_f16(sacc[4 * p + 2], qh[ks], c0, sacc[4 * p + 2]);
                mma_f16(sacc[4 * p + 3], qh[ks], c1, sacc[4 * p + 3]);
            }
        }

        // scale + causal mask
#pragma unroll
        for (int nj = 0; nj < 8; nj++) {
#pragma unroll
            for (int e = 0; e < 4; e++) {
                int col = kb * 64 + nj * 8 + 2 * tg + (e & 1);
                int row = (e & 2) ? row1g : row0g;
                float v = sacc[nj][e] * scale;
                sacc[nj][e] = (col > row) ? -1e30f : v;
            }
        }

        // online softmax: row max
        float rmax0 = -1e30f, rmax1 = -1e30f;
#pragma unroll
        for (int nj = 0; nj < 8; nj++) {
            rmax0 = fmaxf(rmax0, fmaxf(sacc[nj][0], sacc[nj][1]));
            rmax1 = fmaxf(rmax1, fmaxf(sacc[nj][2], sacc[nj][3]));
        }
        rmax0 = fmaxf(rmax0, __shfl_xor_sync(0xffffffffu, rmax0, 1));
        rmax0 = fmaxf(rmax0, __shfl_xor_sync(0xffffffffu, rmax0, 2));
        rmax1 = fmaxf(rmax1, __shfl_xor_sync(0xffffffffu, rmax1, 1));
        rmax1 = fmaxf(rmax1, __shfl_xor_sync(0xffffffffu, rmax1, 2));

        float nm0 = fmaxf(m0, rmax0), nm1 = fmaxf(m1, rmax1);
        float alpha0 = exp2f((m0 - nm0) * LOG2E);
        float alpha1 = exp2f((m1 - nm1) * LOG2E);
        float c0 = nm0 * LOG2E, c1 = nm1 * LOG2E;

        // exponentials in fp16x2: result IS the packed P fragment word
        uint32_t pp[8], pq[8];
#pragma unroll
        for (int nj = 0; nj < 8; nj++) {
            pp[nj] = ex2_h2(fmaf(sacc[nj][0], LOG2E, -c0), fmaf(sacc[nj][1], LOG2E, -c0));
            pq[nj] = ex2_h2(fmaf(sacc[nj][2], LOG2E, -c1), fmaf(sacc[nj][3], LOG2E, -c1));
        }

        m0 = nm0; m1 = nm1;
        lacc[0] *= alpha0; lacc[1] *= alpha0;
        lacc[2] *= alpha1; lacc[3] *= alpha1;
#pragma unroll
        for (int j = 0; j < 8; j++) {
            o[j][0] *= alpha0; o[j][1] *= alpha0;
            o[j][2] *= alpha1; o[j][3] *= alpha1;
        }

        // O += P V, and lacc += P * ones (row sums via tensor core)
#pragma unroll
        for (int ks = 0; ks < 4; ks++) {
            uint32_t pa[4];
            pa[0] = pp[2 * ks];
            pa[1] = pq[2 * ks];
            pa[2] = pp[2 * ks + 1];
            pa[3] = pq[2 * ks + 1];
            mma_f16(lacc, pa, b_ones, lacc);
            uint32_t vd = v_fb + stb + 4u * (ks * 16 * F_LD);
#pragma unroll
            for (int p = 0; p < 4; p++) {
                uint32_t b0[2], b1[2];
                ldsm_x4_t(vd + (uint32_t)p * 32, b0[0], b0[1], b1[0], b1[1]);
                mma_f16(o[2 * p],     pa, b0, o[2 * p]);
                mma_f16(o[2 * p + 1], pa, b1, o[2 * p + 1]);
            }
        }
    }

    // Epilogue: write attn as fp16 hi into g_ah [8192][512 words]
    {
        int b = head >> 4, h = head & 15;
        int s0 = qb * 128 + wid * 16 + g;
        float inv0 = 1.f / lacc[0], inv1 = 1.f / lacc[2];
        size_t base0 = ((size_t)b * Sc + s0) * 512 + h * 32;
        size_t base1 = ((size_t)b * Sc + s0 + 8) * 512 + h * 32;
#pragma unroll
        for (int nj = 0; nj < 8; nj++) {
            int dw = nj * 4 + tg;
            g_ah[base0 + dw] = pack_h2(o[nj][0] * inv0, o[nj][1] * inv0);
            g_ah[base1 + dw] = pack_h2(o[nj][2] * inv1, o[nj][3] * inv1);
        }
    }
}

// ---------------------------------------------------------------------------
extern "C" void kernel_launch(void* const* d_in, const int* in_sizes, int n_in,
                              void* d_out, int out_size)
{
    (void)in_sizes; (void)n_in; (void)out_size;
    const float* x      = (const float*)d_in[0];
    const float* w_attn = (const float*)d_in[2];
    const float* b_attn = (const float*)d_in[3];
    const float* w_proj = (const float*)d_in[4];
    const float* b_proj = (const float*)d_in[5];
    float* out = (float*)d_out;

    cudaFuncSetAttribute(h_gemm<0>,    cudaFuncAttributeMaxDynamicSharedMemorySize, G_SMEM);
    cudaFuncSetAttribute(h_gemm<1>,    cudaFuncAttributeMaxDynamicSharedMemorySize, G_SMEM);
    cudaFuncSetAttribute(flash_kernel, cudaFuncAttributeMaxDynamicSharedMemorySize, FLASH_SMEM);

    // Pre-pass: round/transpose inputs to fp16
    conv_x<<<(Mc * 512) / 1024, 1024>>>(x);
    conv_wT<<<dim3(16, NQKV / 32), dim3(32, 8)>>>(w_attn, NQKV, 0);
    conv_wT<<<dim3(16, Dc / 32),   dim3(32, 8)>>>(w_proj, Dc, 1);

    // 1) QKV GEMM (1-term) -> q/k/v hi (head-major)
    h_gemm<0><<<dim3(NQKV / 128, Mc / 128), 256, G_SMEM>>>(b_attn, nullptr);
    // 2) causal flash attention -> attn hi
    flash_kernel<<<dim3(Sc / 128, Bc * Hc), 256, FLASH_SMEM>>>();
    // 3) proj GEMM (1-term) -> out fp32
    h_gemm<1><<<dim3(Dc / 128, Mc / 128), 256, G_SMEM>>>(b_proj, out);
}